// round 1
// baseline (speedup 1.0000x reference)
#include <cuda_runtime.h>
#include <math.h>

#define NN 50000
#define EE 600000
#define DDIM 128

// ---------------- scratch (static device globals; no allocation) ----------------
__device__ float  g_xa[(size_t)NN * DDIM];
__device__ float  g_xb[(size_t)NN * DDIM];
__device__ float  g_agg[(size_t)2 * NN * DDIM];
__device__ int    g_deg[NN];
__device__ int    g_rowptr[NN + 1];
__device__ int    g_cur[NN];
__device__ int    g_ebuf[EE];
__device__ double g_sums[4];

__device__ __forceinline__ float lrelu(float x) { return x > 0.f ? x : 0.01f * x; }

__device__ __forceinline__ void fma4(float acc[4], float4 a,
                                     float4 w0, float4 w1, float4 w2, float4 w3) {
    acc[0] = fmaf(a.x, w0.x, acc[0]); acc[0] = fmaf(a.y, w1.x, acc[0]);
    acc[0] = fmaf(a.z, w2.x, acc[0]); acc[0] = fmaf(a.w, w3.x, acc[0]);
    acc[1] = fmaf(a.x, w0.y, acc[1]); acc[1] = fmaf(a.y, w1.y, acc[1]);
    acc[1] = fmaf(a.z, w2.y, acc[1]); acc[1] = fmaf(a.w, w3.y, acc[1]);
    acc[2] = fmaf(a.x, w0.z, acc[2]); acc[2] = fmaf(a.y, w1.z, acc[2]);
    acc[2] = fmaf(a.z, w2.z, acc[2]); acc[2] = fmaf(a.w, w3.z, acc[2]);
    acc[3] = fmaf(a.x, w0.w, acc[3]); acc[3] = fmaf(a.y, w1.w, acc[3]);
    acc[3] = fmaf(a.z, w2.w, acc[3]); acc[3] = fmaf(a.w, w3.w, acc[3]);
}

// ---------------- tiny setup kernels ----------------
__global__ void init_kernel() {
    int i = blockIdx.x * blockDim.x + threadIdx.x;
    if (i < NN) g_deg[i] = 0;
    if (i < 4) g_sums[i] = 0.0;
}

__global__ void hist_kernel(const int* __restrict__ ei) {
    int e = blockIdx.x * blockDim.x + threadIdx.x;
    if (e < EE) atomicAdd(&g_deg[ei[EE + e]], 1);
}

// single-block exclusive scan of g_deg -> g_rowptr (+ cursor copy)
__global__ void scan_kernel() {
    __shared__ int warp_sums[32];
    __shared__ int s_running;
    const int tid = threadIdx.x;
    const int lane = tid & 31, wid = tid >> 5;
    if (tid == 0) { s_running = 0; g_rowptr[0] = 0; }
    __syncthreads();
    for (int base = 0; base < NN; base += 1024) {
        int i = base + tid;
        int v = (i < NN) ? g_deg[i] : 0;
        int xs = v;
        #pragma unroll
        for (int o = 1; o < 32; o <<= 1) {
            int y = __shfl_up_sync(0xFFFFFFFFu, xs, o);
            if (lane >= o) xs += y;
        }
        if (lane == 31) warp_sums[wid] = xs;
        __syncthreads();
        if (wid == 0) {
            int s = warp_sums[lane];
            #pragma unroll
            for (int o = 1; o < 32; o <<= 1) {
                int y = __shfl_up_sync(0xFFFFFFFFu, s, o);
                if (lane >= o) s += y;
            }
            warp_sums[lane] = s;
        }
        __syncthreads();
        int offset = s_running + (wid > 0 ? warp_sums[wid - 1] : 0);
        int incl = offset + xs;
        if (i < NN) { g_rowptr[i + 1] = incl; g_cur[i] = incl - v; }
        __syncthreads();
        if (tid == 1023) s_running = incl;
        __syncthreads();
    }
}

__global__ void fill_kernel(const int* __restrict__ ei, const int* __restrict__ et) {
    int e = blockIdx.x * blockDim.x + threadIdx.x;
    if (e >= EE) return;
    int src = ei[e];
    int dst = ei[EE + e];
    int pos = atomicAdd(&g_cur[dst], 1);
    g_ebuf[pos] = src | (et[e] << 30);
}

// ---------------- encode: x = leaky( concat(proj4) @ W1 + b1 ) ----------------
// 512 threads, 128 nodes per block.
// smem: sW 24576 floats | sX0 128*128 | sIn 128*68
__global__ void encode_kernel(
    const float* __restrict__ desc, const float* __restrict__ tweet,
    const float* __restrict__ numf, const float* __restrict__ catf,
    const float* __restrict__ Wd, const float* __restrict__ bd,
    const float* __restrict__ Wt, const float* __restrict__ bt,
    const float* __restrict__ Wn, const float* __restrict__ bn,
    const float* __restrict__ Wc, const float* __restrict__ bc,
    const float* __restrict__ W1, const float* __restrict__ b1,
    float* __restrict__ out)
{
    extern __shared__ float sm[];
    float* sW  = sm;                  // up to 24576 floats
    float* sX0 = sm + 24576;          // 16384 floats
    float* sIn = sm + 24576 + 16384;  // 128*68 floats
    const int tid = threadIdx.x;
    const int node0 = blockIdx.x * 128;

    // ---- desc / tweet projections (cols 0-31, 32-63) ----
    for (int ph = 0; ph < 2; ph++) {
        const float* In = ph ? tweet : desc;
        const float* W  = ph ? Wt : Wd;
        const float* B  = ph ? bt : bd;
        const int colbase = ph * 32;
        __syncthreads();  // protect sW overwrite
        for (int i = tid; i < 6144; i += 512)
            ((float4*)sW)[i] = ((const float4*)W)[i];

        const int ct = tid & 7, rt = tid >> 3;   // 8 col-threads * 4 cols, 64 row-threads * 2 rows
        float4 bv = __ldg((const float4*)B + ct);
        float acc[2][4];
        #pragma unroll
        for (int i = 0; i < 2; i++) {
            acc[i][0] = bv.x; acc[i][1] = bv.y; acc[i][2] = bv.z; acc[i][3] = bv.w;
        }
        for (int k0 = 0; k0 < 768; k0 += 64) {
            __syncthreads();
            #pragma unroll
            for (int j = 0; j < 4; j++) {
                int idx = tid + j * 512;          // 0..2047 float4 slots
                int row = idx >> 4, c4 = idx & 15;
                int g = node0 + row;
                float4 v = make_float4(0.f, 0.f, 0.f, 0.f);
                if (g < NN) v = __ldg((const float4*)(In + (size_t)g * 768 + k0) + c4);
                *(float4*)(sIn + row * 68 + c4 * 4) = v;
            }
            __syncthreads();
            #pragma unroll 4
            for (int kk = 0; kk < 64; kk += 4) {
                float4 w0 = ((float4*)(sW + (k0 + kk + 0) * 32))[ct];
                float4 w1 = ((float4*)(sW + (k0 + kk + 1) * 32))[ct];
                float4 w2 = ((float4*)(sW + (k0 + kk + 2) * 32))[ct];
                float4 w3 = ((float4*)(sW + (k0 + kk + 3) * 32))[ct];
                #pragma unroll
                for (int i = 0; i < 2; i++) {
                    float4 a = *(float4*)(sIn + (rt * 2 + i) * 68 + kk);
                    fma4(acc[i], a, w0, w1, w2, w3);
                }
            }
        }
        #pragma unroll
        for (int i = 0; i < 2; i++) {
            int row = rt * 2 + i;
            float4 o;
            o.x = lrelu(acc[i][0]); o.y = lrelu(acc[i][1]);
            o.z = lrelu(acc[i][2]); o.w = lrelu(acc[i][3]);
            *(float4*)(sX0 + row * 128 + colbase + ct * 4) = o;
        }
    }

    // ---- num / cat projections (cols 64-127) ----
    __syncthreads();
    if (tid < 160) sW[tid] = Wn[tid];
    if (tid < 96)  sW[160 + tid] = Wc[tid];
    if (tid < 32)  { sW[256 + tid] = bn[tid]; sW[288 + tid] = bc[tid]; }
    __syncthreads();
    #pragma unroll
    for (int j = 0; j < 16; j++) {
        int o = tid + j * 512;            // 0..8191
        int row = o >> 6, c = o & 63;
        int g = node0 + row;
        float v = 0.f;
        if (g < NN) {
            if (c < 32) {
                float a = sW[256 + c];
                #pragma unroll
                for (int k = 0; k < 5; k++)
                    a = fmaf(__ldg(numf + (size_t)g * 5 + k), sW[k * 32 + c], a);
                v = lrelu(a);
            } else {
                int cc = c - 32;
                float a = sW[288 + cc];
                #pragma unroll
                for (int k = 0; k < 3; k++)
                    a = fmaf(__ldg(catf + (size_t)g * 3 + k), sW[160 + k * 32 + cc], a);
                v = lrelu(a);
            }
        }
        sX0[row * 128 + 64 + c] = v;
    }

    // ---- W1: out = leaky( x0 @ W1 + b1 ) ----
    __syncthreads();
    for (int i = tid; i < 4096; i += 512)
        ((float4*)sW)[i] = ((const float4*)W1)[i];
    __syncthreads();
    {
        const int ct = tid & 31, rt = tid >> 5;  // 32 col-threads * 4 cols, 16 row-threads * 8 rows
        float4 bv = __ldg((const float4*)b1 + ct);
        float acc[8][4];
        #pragma unroll
        for (int i = 0; i < 8; i++) {
            acc[i][0] = bv.x; acc[i][1] = bv.y; acc[i][2] = bv.z; acc[i][3] = bv.w;
        }
        for (int k = 0; k < 128; k += 4) {
            float4 w0 = ((float4*)(sW + (k + 0) * 128))[ct];
            float4 w1 = ((float4*)(sW + (k + 1) * 128))[ct];
            float4 w2 = ((float4*)(sW + (k + 2) * 128))[ct];
            float4 w3 = ((float4*)(sW + (k + 3) * 128))[ct];
            #pragma unroll
            for (int i = 0; i < 8; i++) {
                float4 a = *(float4*)(sX0 + (rt * 8 + i) * 128 + k);
                fma4(acc[i], a, w0, w1, w2, w3);
            }
        }
        #pragma unroll
        for (int i = 0; i < 8; i++) {
            int g = node0 + rt * 8 + i;
            if (g < NN) {
                float4 o;
                o.x = lrelu(acc[i][0]); o.y = lrelu(acc[i][1]);
                o.z = lrelu(acc[i][2]); o.w = lrelu(acc[i][3]);
                *(float4*)(out + (size_t)g * 128 + ct * 4) = o;
            }
        }
    }
}

// ---------------- pull: per-relation segment-max into g_agg (warp per node) ----------------
__global__ void pull_kernel(const float* __restrict__ x) {
    const int w = (blockIdx.x * blockDim.x + threadIdx.x) >> 5;
    const int lane = threadIdx.x & 31;
    if (w >= NN) return;
    const int beg = g_rowptr[w], end = g_rowptr[w + 1];
    const float NEG = -3.0e38f;
    float4 a0 = make_float4(NEG, NEG, NEG, NEG);
    float4 a1 = a0;
    for (int e = beg; e < end; e++) {
        int v = g_ebuf[e];
        float4 f = __ldg((const float4*)(x + (size_t)(v & 0x3FFFFFFF) * 128) + lane);
        if (v >> 30) {
            a1.x = fmaxf(a1.x, f.x); a1.y = fmaxf(a1.y, f.y);
            a1.z = fmaxf(a1.z, f.z); a1.w = fmaxf(a1.w, f.w);
        } else {
            a0.x = fmaxf(a0.x, f.x); a0.y = fmaxf(a0.y, f.y);
            a0.z = fmaxf(a0.z, f.z); a0.w = fmaxf(a0.w, f.w);
        }
    }
    float4 o0, o1;
    o0.x = (a0.x == NEG) ? 0.f : a0.x; o0.y = (a0.y == NEG) ? 0.f : a0.y;
    o0.z = (a0.z == NEG) ? 0.f : a0.z; o0.w = (a0.w == NEG) ? 0.f : a0.w;
    o1.x = (a1.x == NEG) ? 0.f : a1.x; o1.y = (a1.y == NEG) ? 0.f : a1.y;
    o1.z = (a1.z == NEG) ? 0.f : a1.z; o1.w = (a1.w == NEG) ? 0.f : a1.w;
    ((float4*)(g_agg + (size_t)w * 128))[lane] = o0;
    ((float4*)(g_agg + (size_t)(NN + w) * 128))[lane] = o1;
}

// ---------------- RGCN GEMM: out = [x|agg0|agg1] @ [root;W0;W1] + bias, fused LN stats ----------------
__global__ void rgcn_kernel(const float* __restrict__ x,
                            const float* __restrict__ root,
                            const float* __restrict__ relw,
                            const float* __restrict__ bias,
                            float* __restrict__ out,
                            double* __restrict__ sums)
{
    extern __shared__ float sm[];
    float* sW  = sm;           // 384*128 = 49152 floats
    float* sIn = sm + 49152;   // 128*36 floats
    __shared__ double sred[2];
    const int tid = threadIdx.x;
    const int node0 = blockIdx.x * 128;
    if (tid == 0) { sred[0] = 0.0; sred[1] = 0.0; }

    for (int i = tid; i < 4096; i += 512)
        ((float4*)sW)[i] = ((const float4*)root)[i];
    for (int i = tid; i < 8192; i += 512)
        ((float4*)(sW + 16384))[i] = ((const float4*)relw)[i];
    __syncthreads();

    const int ct = tid & 31, rt = tid >> 5;
    float4 bv = __ldg((const float4*)bias + ct);
    float acc[8][4];
    #pragma unroll
    for (int i = 0; i < 8; i++) {
        acc[i][0] = bv.x; acc[i][1] = bv.y; acc[i][2] = bv.z; acc[i][3] = bv.w;
    }

    for (int k0 = 0; k0 < 384; k0 += 32) {
        const float* ptr;
        if (k0 < 128) ptr = x;
        else if (k0 < 256) ptr = g_agg;
        else ptr = g_agg + (size_t)NN * DDIM;
        const int colofs = k0 & 127;
        __syncthreads();
        #pragma unroll
        for (int j = 0; j < 2; j++) {
            int idx = tid + j * 512;      // 0..1023 float4 slots
            int row = idx >> 3, c4 = idx & 7;
            int g = node0 + row;
            float4 v = make_float4(0.f, 0.f, 0.f, 0.f);
            if (g < NN) v = __ldg((const float4*)(ptr + (size_t)g * 128 + colofs) + c4);
            *(float4*)(sIn + row * 36 + c4 * 4) = v;
        }
        __syncthreads();
        #pragma unroll
        for (int kk = 0; kk < 32; kk += 4) {
            float4 w0 = ((float4*)(sW + (k0 + kk + 0) * 128))[ct];
            float4 w1 = ((float4*)(sW + (k0 + kk + 1) * 128))[ct];
            float4 w2 = ((float4*)(sW + (k0 + kk + 2) * 128))[ct];
            float4 w3 = ((float4*)(sW + (k0 + kk + 3) * 128))[ct];
            #pragma unroll
            for (int i = 0; i < 8; i++) {
                float4 a = *(float4*)(sIn + (rt * 8 + i) * 36 + kk);
                fma4(acc[i], a, w0, w1, w2, w3);
            }
        }
    }

    float ls = 0.f, lq = 0.f;
    #pragma unroll
    for (int i = 0; i < 8; i++) {
        int g = node0 + rt * 8 + i;
        if (g < NN) {
            float4 o = make_float4(acc[i][0], acc[i][1], acc[i][2], acc[i][3]);
            *(float4*)(out + (size_t)g * 128 + ct * 4) = o;
            ls += o.x + o.y + o.z + o.w;
            lq += o.x * o.x + o.y * o.y + o.z * o.z + o.w * o.w;
        }
    }
    #pragma unroll
    for (int off = 16; off; off >>= 1) {
        ls += __shfl_down_sync(0xFFFFFFFFu, ls, off);
        lq += __shfl_down_sync(0xFFFFFFFFu, lq, off);
    }
    if ((tid & 31) == 0) {
        atomicAdd(&sred[0], (double)ls);
        atomicAdd(&sred[1], (double)lq);
    }
    __syncthreads();
    if (tid == 0) {
        atomicAdd(&sums[0], sred[0]);
        atomicAdd(&sums[1], sred[1]);
    }
}

// ---------------- graph LayerNorm normalize (in place) ----------------
__global__ void ln_kernel(float* __restrict__ x,
                          const float* __restrict__ g,
                          const float* __restrict__ b,
                          const double* __restrict__ s)
{
    const double cnt = (double)NN * DDIM;
    const double mu = s[0] / cnt;
    const double var = s[1] / cnt - mu * mu;
    const float rstd = (float)(1.0 / sqrt(var + 1e-5));
    const float muf = (float)mu;
    const int total = NN * 32;
    for (int i = blockIdx.x * blockDim.x + threadIdx.x; i < total;
         i += gridDim.x * blockDim.x) {
        float4 v = ((float4*)x)[i];
        int c = i & 31;
        float4 gg = __ldg((const float4*)g + c);
        float4 bb = __ldg((const float4*)b + c);
        v.x = (v.x - muf) * rstd * gg.x + bb.x;
        v.y = (v.y - muf) * rstd * gg.y + bb.y;
        v.z = (v.z - muf) * rstd * gg.z + bb.z;
        v.w = (v.w - muf) * rstd * gg.w + bb.w;
        ((float4*)x)[i] = v;
    }
}

// ---------------- head: out = sigmoid( leaky(x@W2+b2) @ W3 + b3 ) ----------------
__global__ void head_kernel(const float* __restrict__ x,
                            const float* __restrict__ W2,
                            const float* __restrict__ b2,
                            const float* __restrict__ W3,
                            const float* __restrict__ b3,
                            float* __restrict__ out)
{
    extern __shared__ float sm[];
    float* sW  = sm;            // 16384 floats
    float* sIn = sm + 16384;    // 128*132 floats
    const int tid = threadIdx.x;
    const int node0 = blockIdx.x * 128;

    for (int i = tid; i < 4096; i += 512)
        ((float4*)sW)[i] = ((const float4*)W2)[i];
    #pragma unroll
    for (int j = 0; j < 8; j++) {
        int idx = tid + j * 512;        // 0..4095 float4 slots
        int row = idx >> 5, c4 = idx & 31;
        int g = node0 + row;
        float4 v = make_float4(0.f, 0.f, 0.f, 0.f);
        if (g < NN) v = __ldg((const float4*)(x + (size_t)g * 128) + c4);
        *(float4*)(sIn + row * 132 + c4 * 4) = v;
    }
    __syncthreads();

    const int ct = tid & 31, rt = tid >> 5;
    float4 bv = __ldg((const float4*)b2 + ct);
    float acc[8][4];
    #pragma unroll
    for (int i = 0; i < 8; i++) {
        acc[i][0] = bv.x; acc[i][1] = bv.y; acc[i][2] = bv.z; acc[i][3] = bv.w;
    }
    for (int k = 0; k < 128; k += 4) {
        float4 w0 = ((float4*)(sW + (k + 0) * 128))[ct];
        float4 w1 = ((float4*)(sW + (k + 1) * 128))[ct];
        float4 w2 = ((float4*)(sW + (k + 2) * 128))[ct];
        float4 w3 = ((float4*)(sW + (k + 3) * 128))[ct];
        #pragma unroll
        for (int i = 0; i < 8; i++) {
            float4 a = *(float4*)(sIn + (rt * 8 + i) * 132 + k);
            fma4(acc[i], a, w0, w1, w2, w3);
        }
    }
    float4 w3v = __ldg((const float4*)W3 + ct);
    float b3v = __ldg(b3);
    #pragma unroll
    for (int i = 0; i < 8; i++) {
        float p = lrelu(acc[i][0]) * w3v.x + lrelu(acc[i][1]) * w3v.y +
                  lrelu(acc[i][2]) * w3v.z + lrelu(acc[i][3]) * w3v.w;
        #pragma unroll
        for (int off = 16; off; off >>= 1)
            p += __shfl_down_sync(0xFFFFFFFFu, p, off);
        if (ct == 0) {
            int g = node0 + rt * 8 + i;
            if (g < NN) out[g] = 1.f / (1.f + expf(-(p + b3v)));
        }
    }
}

// ---------------- launch ----------------
extern "C" void kernel_launch(void* const* d_in, const int* in_sizes, int n_in,
                              void* d_out, int out_size)
{
    const float* desc  = (const float*)d_in[0];
    const float* tweet = (const float*)d_in[1];
    const float* numf  = (const float*)d_in[2];
    const float* catf  = (const float*)d_in[3];
    const int*   ei    = (const int*)d_in[4];
    const int*   et    = (const int*)d_in[5];
    const float* Wd = (const float*)d_in[6];  const float* bd = (const float*)d_in[7];
    const float* Wt = (const float*)d_in[8];  const float* bt = (const float*)d_in[9];
    const float* Wn = (const float*)d_in[10]; const float* bn = (const float*)d_in[11];
    const float* Wc = (const float*)d_in[12]; const float* bc = (const float*)d_in[13];
    const float* W1 = (const float*)d_in[14]; const float* b1 = (const float*)d_in[15];
    const float* rg1_w    = (const float*)d_in[16];
    const float* rg1_root = (const float*)d_in[17];
    const float* rg1_bias = (const float*)d_in[18];
    const float* ln1_g = (const float*)d_in[19]; const float* ln1_b = (const float*)d_in[20];
    const float* rg2_w    = (const float*)d_in[21];
    const float* rg2_root = (const float*)d_in[22];
    const float* rg2_bias = (const float*)d_in[23];
    const float* ln2_g = (const float*)d_in[24]; const float* ln2_b = (const float*)d_in[25];
    const float* W2 = (const float*)d_in[26]; const float* b2 = (const float*)d_in[27];
    const float* W3 = (const float*)d_in[28]; const float* b3 = (const float*)d_in[29];

    float* xa; float* xb; double* sums;
    cudaGetSymbolAddress((void**)&xa, g_xa);
    cudaGetSymbolAddress((void**)&xb, g_xb);
    cudaGetSymbolAddress((void**)&sums, g_sums);

    const int SM_ENC  = (24576 + 16384 + 128 * 68) * 4;   // 198656
    const int SM_RGCN = (49152 + 128 * 36) * 4;            // 215040
    const int SM_HEAD = (16384 + 128 * 132) * 4;           // 133120
    cudaFuncSetAttribute(encode_kernel, cudaFuncAttributeMaxDynamicSharedMemorySize, SM_ENC);
    cudaFuncSetAttribute(rgcn_kernel,   cudaFuncAttributeMaxDynamicSharedMemorySize, SM_RGCN);
    cudaFuncSetAttribute(head_kernel,   cudaFuncAttributeMaxDynamicSharedMemorySize, SM_HEAD);

    const int GEMM_BLOCKS = (NN + 127) / 128;  // 391

    init_kernel<<<(NN + 255) / 256, 256>>>();
    hist_kernel<<<(EE + 255) / 256, 256>>>(ei);
    scan_kernel<<<1, 1024>>>();
    fill_kernel<<<(EE + 255) / 256, 256>>>(ei, et);

    encode_kernel<<<GEMM_BLOCKS, 512, SM_ENC>>>(desc, tweet, numf, catf,
                                                Wd, bd, Wt, bt, Wn, bn, Wc, bc,
                                                W1, b1, xa);

    pull_kernel<<<(NN + 7) / 8, 256>>>(xa);
    rgcn_kernel<<<GEMM_BLOCKS, 512, SM_RGCN>>>(xa, rg1_root, rg1_w, rg1_bias, xb, sums + 0);
    ln_kernel<<<1024, 256>>>(xb, ln1_g, ln1_b, sums + 0);

    pull_kernel<<<(NN + 7) / 8, 256>>>(xb);
    rgcn_kernel<<<GEMM_BLOCKS, 512, SM_RGCN>>>(xb, rg2_root, rg2_w, rg2_bias, xa, sums + 2);
    ln_kernel<<<1024, 256>>>(xa, ln2_g, ln2_b, sums + 2);

    head_kernel<<<GEMM_BLOCKS, 512, SM_HEAD>>>(xa, W2, b2, W3, b3, (float*)d_out);
}

// round 3
// speedup vs baseline: 1.4071x; 1.4071x over previous
#include <cuda_runtime.h>
#include <math.h>
#include <stdint.h>

#define NN 50000
#define EE 600000
#define DDIM 128

// ---------------- scratch (static device globals; no allocation) ----------------
__device__ float  g_xa[(size_t)NN * DDIM];
__device__ float  g_xb[(size_t)NN * DDIM];
__device__ float  g_agg[(size_t)2 * NN * DDIM];
__device__ int    g_deg[NN];
__device__ int    g_rowptr[NN + 1];
__device__ int    g_cur[NN];
__device__ int    g_ebuf[EE];
__device__ double g_sums[4];

__device__ __forceinline__ float lrelu(float x) { return x > 0.f ? x : 0.01f * x; }

__device__ __forceinline__ uint32_t f2tf(float x) {
    uint32_t u; asm("cvt.rna.tf32.f32 %0, %1;" : "=r"(u) : "f"(x)); return u;
}
__device__ __forceinline__ float f2tff(float x) { return __uint_as_float(f2tf(x)); }

__device__ __forceinline__ void mma_tf32(float c[4], uint32_t a0, uint32_t a1,
                                         uint32_t a2, uint32_t a3,
                                         uint32_t b0, uint32_t b1) {
    asm volatile(
        "mma.sync.aligned.m16n8k8.row.col.f32.tf32.tf32.f32 "
        "{%0,%1,%2,%3},{%4,%5,%6,%7},{%8,%9},{%0,%1,%2,%3};"
        : "+f"(c[0]), "+f"(c[1]), "+f"(c[2]), "+f"(c[3])
        : "r"(a0), "r"(a1), "r"(a2), "r"(a3), "r"(b0), "r"(b1));
}

// A fragment: sA row-major, pitch P (P % 32 == 4 -> conflict free)
__device__ __forceinline__ void lda_frag(const float* sA, int P, int r0, int k0,
                                         int u, int v, uint32_t& a0, uint32_t& a1,
                                         uint32_t& a2, uint32_t& a3) {
    const float* p = sA + (r0 + u) * P + k0 + v;
    a0 = __float_as_uint(p[0]);
    a1 = __float_as_uint(p[8 * P]);
    a2 = __float_as_uint(p[4]);
    a3 = __float_as_uint(p[8 * P + 4]);
}

// B fragment: sW swizzled [k][n ^ ((k&3)<<3)], row width Nw (mult of 32); k0 % 8 == 0
__device__ __forceinline__ void ldb_frag(const float* sW, int Nw, int k0, int n0,
                                         int u, int v, uint32_t& b0, uint32_t& b1) {
    int col = (n0 + u) ^ (v << 3);
    b0 = __float_as_uint(sW[(k0 + v) * Nw + col]);
    b1 = __float_as_uint(sW[(k0 + 4 + v) * Nw + col]);
}

// ---------------- tiny setup kernels ----------------
__global__ void init_kernel() {
    int i = blockIdx.x * blockDim.x + threadIdx.x;
    if (i < NN) g_deg[i] = 0;
    if (i < 4) g_sums[i] = 0.0;
}

__global__ void hist_kernel(const int* __restrict__ ei) {
    int e = blockIdx.x * blockDim.x + threadIdx.x;
    if (e < EE) atomicAdd(&g_deg[ei[EE + e]], 1);
}

__global__ void scan_kernel() {
    __shared__ int warp_sums[32];
    __shared__ int s_running;
    const int tid = threadIdx.x;
    const int lane = tid & 31, wid = tid >> 5;
    if (tid == 0) { s_running = 0; g_rowptr[0] = 0; }
    __syncthreads();
    for (int base = 0; base < NN; base += 1024) {
        int i = base + tid;
        int v = (i < NN) ? g_deg[i] : 0;
        int xs = v;
        #pragma unroll
        for (int o = 1; o < 32; o <<= 1) {
            int y = __shfl_up_sync(0xFFFFFFFFu, xs, o);
            if (lane >= o) xs += y;
        }
        if (lane == 31) warp_sums[wid] = xs;
        __syncthreads();
        if (wid == 0) {
            int s = warp_sums[lane];
            #pragma unroll
            for (int o = 1; o < 32; o <<= 1) {
                int y = __shfl_up_sync(0xFFFFFFFFu, s, o);
                if (lane >= o) s += y;
            }
            warp_sums[lane] = s;
        }
        __syncthreads();
        int offset = s_running + (wid > 0 ? warp_sums[wid - 1] : 0);
        int incl = offset + xs;
        if (i < NN) { g_rowptr[i + 1] = incl; g_cur[i] = incl - v; }
        __syncthreads();
        if (tid == 1023) s_running = incl;
        __syncthreads();
    }
}

__global__ void fill_kernel(const int* __restrict__ ei, const int* __restrict__ et) {
    int e = blockIdx.x * blockDim.x + threadIdx.x;
    if (e >= EE) return;
    int src = ei[e];
    int dst = ei[EE + e];
    int pos = atomicAdd(&g_cur[dst], 1);
    g_ebuf[pos] = src | (et[e] << 30);
}

// ---------------- encode: x = leaky( concat(proj4) @ W1 + b1 ) ----------------
// 256 threads (8 warps), 128 nodes per block, tensor-core tf32.
// smem: sW 24576 | sX0 128*132 | sA 128*36   (46080 floats)
__global__ void __launch_bounds__(256, 1) encode_kernel(
    const float* __restrict__ desc, const float* __restrict__ tweet,
    const float* __restrict__ numf, const float* __restrict__ catf,
    const float* __restrict__ Wd, const float* __restrict__ bd,
    const float* __restrict__ Wt, const float* __restrict__ bt,
    const float* __restrict__ Wn, const float* __restrict__ bn,
    const float* __restrict__ Wc, const float* __restrict__ bc,
    const float* __restrict__ W1, const float* __restrict__ b1,
    float* __restrict__ out)
{
    extern __shared__ float sm[];
    float* sW  = sm;                    // proj: 768*32 = 24576; W1: 128*128 = 16384
    float* sX0 = sm + 24576;            // 128*132
    float* sA  = sm + 24576 + 16896;    // 128*36
    const int tid = threadIdx.x;
    const int node0 = blockIdx.x * 128;
    const int lane = tid & 31, warp = tid >> 5;
    const int u = lane >> 2, v = lane & 3;
    const int r0 = warp * 16;

    // ---- desc / tweet projections (cols 0-31, 32-63) ----
    for (int ph = 0; ph < 2; ph++) {
        const float* In = ph ? tweet : desc;
        const float* W  = ph ? Wt : Wd;
        const float* B  = ph ? bt : bd;
        __syncthreads();
        for (int i = tid; i < 6144; i += 256) {
            float4 w = ((const float4*)W)[i];
            int k = i >> 3, n = (i & 7) * 4;
            float* d = sW + k * 32 + (n ^ ((k & 3) << 3));
            *(float4*)d = make_float4(f2tff(w.x), f2tff(w.y), f2tff(w.z), f2tff(w.w));
        }
        float acc[4][4];
        #pragma unroll
        for (int nt = 0; nt < 4; nt++) {
            float2 bv = *(const float2*)(B + nt * 8 + 2 * v);
            acc[nt][0] = bv.x; acc[nt][1] = bv.y; acc[nt][2] = bv.x; acc[nt][3] = bv.y;
        }
        for (int c0 = 0; c0 < 768; c0 += 32) {
            __syncthreads();
            #pragma unroll
            for (int j = 0; j < 4; j++) {
                int idx = tid + j * 256;
                int row = idx >> 3, c4 = (idx & 7) * 4;
                int g = node0 + row;
                float4 val = make_float4(0.f, 0.f, 0.f, 0.f);
                if (g < NN) val = __ldg((const float4*)(In + (size_t)g * 768 + c0 + c4));
                *(float4*)(sA + row * 36 + c4) =
                    make_float4(f2tff(val.x), f2tff(val.y), f2tff(val.z), f2tff(val.w));
            }
            __syncthreads();
            #pragma unroll
            for (int ks = 0; ks < 4; ks++) {
                int k0 = ks * 8;
                uint32_t a0, a1, a2, a3;
                lda_frag(sA, 36, r0, k0, u, v, a0, a1, a2, a3);
                int kw = c0 + k0;   // global K row in sW (FIX: was k0)
                #pragma unroll
                for (int nt = 0; nt < 4; nt++) {
                    uint32_t b0, b1;
                    ldb_frag(sW, 32, kw, nt * 8, u, v, b0, b1);
                    mma_tf32(acc[nt], a0, a1, a2, a3, b0, b1);
                }
            }
        }
        const int cb = ph * 32;
        #pragma unroll
        for (int nt = 0; nt < 4; nt++) {
            int col = cb + nt * 8 + 2 * v;
            float2 o;
            o.x = f2tff(lrelu(acc[nt][0])); o.y = f2tff(lrelu(acc[nt][1]));
            *(float2*)(sX0 + (r0 + u) * 132 + col) = o;
            o.x = f2tff(lrelu(acc[nt][2])); o.y = f2tff(lrelu(acc[nt][3]));
            *(float2*)(sX0 + (r0 + u + 8) * 132 + col) = o;
        }
    }

    // ---- num / cat projections (cols 64-127) ----
    __syncthreads();
    if (tid < 160) sW[tid] = Wn[tid];
    if (tid < 96)  sW[160 + tid] = Wc[tid];
    if (tid < 32)  { sW[256 + tid] = bn[tid]; sW[288 + tid] = bc[tid]; }
    __syncthreads();
    for (int o = tid; o < 8192; o += 256) {
        int row = o >> 6, c = o & 63;
        int g = node0 + row;
        float vv = 0.f;
        if (g < NN) {
            if (c < 32) {
                float a = sW[256 + c];
                #pragma unroll
                for (int k = 0; k < 5; k++)
                    a = fmaf(__ldg(numf + (size_t)g * 5 + k), sW[k * 32 + c], a);
                vv = lrelu(a);
            } else {
                int cc = c - 32;
                float a = sW[288 + cc];
                #pragma unroll
                for (int k = 0; k < 3; k++)
                    a = fmaf(__ldg(catf + (size_t)g * 3 + k), sW[160 + k * 32 + cc], a);
                vv = lrelu(a);
            }
        }
        sX0[row * 132 + 64 + c] = f2tff(vv);
    }

    // ---- W1: out = leaky( x0 @ W1 + b1 ) ----
    __syncthreads();
    for (int i = tid; i < 4096; i += 256) {
        float4 w = ((const float4*)W1)[i];
        int k = i >> 5, n = (i & 31) * 4;
        float* d = sW + k * 128 + (n ^ ((k & 3) << 3));
        *(float4*)d = make_float4(f2tff(w.x), f2tff(w.y), f2tff(w.z), f2tff(w.w));
    }
    __syncthreads();
    {
        float acc[16][4];
        #pragma unroll
        for (int nt = 0; nt < 16; nt++) {
            float2 bv = *(const float2*)(b1 + nt * 8 + 2 * v);
            acc[nt][0] = bv.x; acc[nt][1] = bv.y; acc[nt][2] = bv.x; acc[nt][3] = bv.y;
        }
        for (int ks = 0; ks < 16; ks++) {
            int k0 = ks * 8;
            uint32_t a0, a1, a2, a3;
            lda_frag(sX0, 132, r0, k0, u, v, a0, a1, a2, a3);
            #pragma unroll
            for (int nt = 0; nt < 16; nt++) {
                uint32_t b0, b1;
                ldb_frag(sW, 128, k0, nt * 8, u, v, b0, b1);
                mma_tf32(acc[nt], a0, a1, a2, a3, b0, b1);
            }
        }
        int gA = node0 + r0 + u, gB = gA + 8;
        #pragma unroll
        for (int nt = 0; nt < 16; nt++) {
            int col = nt * 8 + 2 * v;
            if (gA < NN) {
                float2 o; o.x = lrelu(acc[nt][0]); o.y = lrelu(acc[nt][1]);
                *(float2*)(out + (size_t)gA * 128 + col) = o;
            }
            if (gB < NN) {
                float2 o; o.x = lrelu(acc[nt][2]); o.y = lrelu(acc[nt][3]);
                *(float2*)(out + (size_t)gB * 128 + col) = o;
            }
        }
    }
}

// ---------------- pull: per-relation segment-max into g_agg (warp per node) ----------------
__global__ void pull_kernel(const float* __restrict__ x) {
    const int w = (blockIdx.x * blockDim.x + threadIdx.x) >> 5;
    const int lane = threadIdx.x & 31;
    if (w >= NN) return;
    const int beg = g_rowptr[w], end = g_rowptr[w + 1];
    const float NEG = -3.0e38f;
    float4 a0 = make_float4(NEG, NEG, NEG, NEG);
    float4 a1 = a0;
    for (int e = beg; e < end; e++) {
        int v = g_ebuf[e];
        float4 f = __ldg((const float4*)(x + (size_t)(v & 0x3FFFFFFF) * 128) + lane);
        if (v >> 30) {
            a1.x = fmaxf(a1.x, f.x); a1.y = fmaxf(a1.y, f.y);
            a1.z = fmaxf(a1.z, f.z); a1.w = fmaxf(a1.w, f.w);
        } else {
            a0.x = fmaxf(a0.x, f.x); a0.y = fmaxf(a0.y, f.y);
            a0.z = fmaxf(a0.z, f.z); a0.w = fmaxf(a0.w, f.w);
        }
    }
    float4 o0, o1;
    o0.x = (a0.x == NEG) ? 0.f : a0.x; o0.y = (a0.y == NEG) ? 0.f : a0.y;
    o0.z = (a0.z == NEG) ? 0.f : a0.z; o0.w = (a0.w == NEG) ? 0.f : a0.w;
    o1.x = (a1.x == NEG) ? 0.f : a1.x; o1.y = (a1.y == NEG) ? 0.f : a1.y;
    o1.z = (a1.z == NEG) ? 0.f : a1.z; o1.w = (a1.w == NEG) ? 0.f : a1.w;
    ((float4*)(g_agg + (size_t)w * 128))[lane] = o0;
    ((float4*)(g_agg + (size_t)(NN + w) * 128))[lane] = o1;
}

// ---------------- RGCN GEMM (tf32 tensor): out = [x|agg0|agg1]@[root;W0;W1]+bias, fused LN stats
// 256 threads, 128 nodes/block. smem: sW 384*128 | sA 128*36  (53760 floats = 215040 B)
__global__ void __launch_bounds__(256, 1) rgcn_kernel(
    const float* __restrict__ x,
    const float* __restrict__ root,
    const float* __restrict__ relw,
    const float* __restrict__ bias,
    float* __restrict__ out,
    double* __restrict__ sums)
{
    extern __shared__ float sm[];
    float* sW = sm;            // 49152 floats, swizzled [k][n^((k&3)<<3)]
    float* sA = sm + 49152;    // 128*36
    __shared__ double sred[2];
    const int tid = threadIdx.x;
    const int node0 = blockIdx.x * 128;
    const int lane = tid & 31, warp = tid >> 5;
    const int u = lane >> 2, v = lane & 3;
    const int r0 = warp * 16;
    if (tid < 2) sred[tid] = 0.0;

    for (int i = tid; i < 4096; i += 256) {
        float4 w = ((const float4*)root)[i];
        int k = i >> 5, n = (i & 31) * 4;
        float* d = sW + k * 128 + (n ^ ((k & 3) << 3));
        *(float4*)d = make_float4(f2tff(w.x), f2tff(w.y), f2tff(w.z), f2tff(w.w));
    }
    for (int i = tid; i < 8192; i += 256) {
        float4 w = ((const float4*)relw)[i];
        int k = 128 + (i >> 5), n = (i & 31) * 4;
        float* d = sW + k * 128 + (n ^ ((k & 3) << 3));
        *(float4*)d = make_float4(f2tff(w.x), f2tff(w.y), f2tff(w.z), f2tff(w.w));
    }

    float acc[16][4];
    #pragma unroll
    for (int nt = 0; nt < 16; nt++) {
        float2 bv = *(const float2*)(bias + nt * 8 + 2 * v);
        acc[nt][0] = bv.x; acc[nt][1] = bv.y; acc[nt][2] = bv.x; acc[nt][3] = bv.y;
    }

    for (int c0 = 0; c0 < 384; c0 += 32) {
        const float* ptr;
        if (c0 < 128) ptr = x;
        else if (c0 < 256) ptr = g_agg;
        else ptr = g_agg + (size_t)NN * DDIM;
        const int colofs = c0 & 127;
        __syncthreads();
        #pragma unroll
        for (int j = 0; j < 4; j++) {
            int idx = tid + j * 256;
            int row = idx >> 3, c4 = (idx & 7) * 4;
            int g = node0 + row;
            float4 val = make_float4(0.f, 0.f, 0.f, 0.f);
            if (g < NN) val = __ldg((const float4*)(ptr + (size_t)g * 128 + colofs + c4));
            *(float4*)(sA + row * 36 + c4) =
                make_float4(f2tff(val.x), f2tff(val.y), f2tff(val.z), f2tff(val.w));
        }
        __syncthreads();
        #pragma unroll
        for (int ks = 0; ks < 4; ks++) {
            int k0 = ks * 8;
            uint32_t a0, a1, a2, a3;
            lda_frag(sA, 36, r0, k0, u, v, a0, a1, a2, a3);
            int kw = c0 + k0;   // row in sW
            #pragma unroll
            for (int nt = 0; nt < 16; nt++) {
                uint32_t b0, b1;
                ldb_frag(sW, 128, kw, nt * 8, u, v, b0, b1);
                mma_tf32(acc[nt], a0, a1, a2, a3, b0, b1);
            }
        }
    }

    int gA = node0 + r0 + u, gB = gA + 8;
    float ls = 0.f, lq = 0.f;
    #pragma unroll
    for (int nt = 0; nt < 16; nt++) {
        int col = nt * 8 + 2 * v;
        if (gA < NN) {
            float x0 = acc[nt][0], x1 = acc[nt][1];
            float2 o; o.x = x0; o.y = x1;
            *(float2*)(out + (size_t)gA * 128 + col) = o;
            ls += x0 + x1; lq += x0 * x0 + x1 * x1;
        }
        if (gB < NN) {
            float x0 = acc[nt][2], x1 = acc[nt][3];
            float2 o; o.x = x0; o.y = x1;
            *(float2*)(out + (size_t)gB * 128 + col) = o;
            ls += x0 + x1; lq += x0 * x0 + x1 * x1;
        }
    }
    #pragma unroll
    for (int off = 16; off; off >>= 1) {
        ls += __shfl_down_sync(0xFFFFFFFFu, ls, off);
        lq += __shfl_down_sync(0xFFFFFFFFu, lq, off);
    }
    if (lane == 0) {
        atomicAdd(&sred[0], (double)ls);
        atomicAdd(&sred[1], (double)lq);
    }
    __syncthreads();
    if (tid == 0) {
        atomicAdd(&sums[0], sred[0]);
        atomicAdd(&sums[1], sred[1]);
    }
}

// ---------------- graph LayerNorm normalize (in place) ----------------
__global__ void ln_kernel(float* __restrict__ x,
                          const float* __restrict__ g,
                          const float* __restrict__ b,
                          const double* __restrict__ s)
{
    const double cnt = (double)NN * DDIM;
    const double mu = s[0] / cnt;
    const double var = s[1] / cnt - mu * mu;
    const float rstd = (float)(1.0 / sqrt(var + 1e-5));
    const float muf = (float)mu;
    const int total = NN * 32;
    for (int i = blockIdx.x * blockDim.x + threadIdx.x; i < total;
         i += gridDim.x * blockDim.x) {
        float4 vv = ((float4*)x)[i];
        int c = i & 31;
        float4 gg = __ldg((const float4*)g + c);
        float4 bb = __ldg((const float4*)b + c);
        vv.x = (vv.x - muf) * rstd * gg.x + bb.x;
        vv.y = (vv.y - muf) * rstd * gg.y + bb.y;
        vv.z = (vv.z - muf) * rstd * gg.z + bb.z;
        vv.w = (vv.w - muf) * rstd * gg.w + bb.w;
        ((float4*)x)[i] = vv;
    }
}

// ---------------- head: out = sigmoid( leaky(x@W2+b2) @ W3 + b3 ) ----------------
// 256 threads. smem: sW 16384 | sX 128*132 | w3 128
__global__ void __launch_bounds__(256, 1) head_kernel(
    const float* __restrict__ x,
    const float* __restrict__ W2,
    const float* __restrict__ b2,
    const float* __restrict__ W3,
    const float* __restrict__ b3,
    float* __restrict__ out)
{
    extern __shared__ float sm[];
    float* sW  = sm;                 // 16384, swizzled
    float* sX  = sm + 16384;         // 128*132
    float* sw3 = sm + 16384 + 16896; // 128
    const int tid = threadIdx.x;
    const int node0 = blockIdx.x * 128;
    const int lane = tid & 31, warp = tid >> 5;
    const int u = lane >> 2, v = lane & 3;
    const int r0 = warp * 16;

    for (int i = tid; i < 4096; i += 256) {
        float4 w = ((const float4*)W2)[i];
        int k = i >> 5, n = (i & 31) * 4;
        float* d = sW + k * 128 + (n ^ ((k & 3) << 3));
        *(float4*)d = make_float4(f2tff(w.x), f2tff(w.y), f2tff(w.z), f2tff(w.w));
    }
    for (int i = tid; i < 4096; i += 256) {
        int row = i >> 5, c4 = (i & 31) * 4;
        int g = node0 + row;
        float4 val = make_float4(0.f, 0.f, 0.f, 0.f);
        if (g < NN) val = __ldg((const float4*)(x + (size_t)g * 128 + c4));
        *(float4*)(sX + row * 132 + c4) =
            make_float4(f2tff(val.x), f2tff(val.y), f2tff(val.z), f2tff(val.w));
    }
    if (tid < 128) sw3[tid] = W3[tid];
    __syncthreads();

    float acc[16][4];
    #pragma unroll
    for (int nt = 0; nt < 16; nt++) {
        float2 bv = *(const float2*)(b2 + nt * 8 + 2 * v);
        acc[nt][0] = bv.x; acc[nt][1] = bv.y; acc[nt][2] = bv.x; acc[nt][3] = bv.y;
    }
    for (int ks = 0; ks < 16; ks++) {
        int k0 = ks * 8;
        uint32_t a0, a1, a2, a3;
        lda_frag(sX, 132, r0, k0, u, v, a0, a1, a2, a3);
        #pragma unroll
        for (int nt = 0; nt < 16; nt++) {
            uint32_t b0, b1;
            ldb_frag(sW, 128, k0, nt * 8, u, v, b0, b1);
            mma_tf32(acc[nt], a0, a1, a2, a3, b0, b1);
        }
    }

    float pA = 0.f, pB = 0.f;
    #pragma unroll
    for (int nt = 0; nt < 16; nt++) {
        int col = nt * 8 + 2 * v;
        float w0 = sw3[col], w1 = sw3[col + 1];
        pA += lrelu(acc[nt][0]) * w0 + lrelu(acc[nt][1]) * w1;
        pB += lrelu(acc[nt][2]) * w0 + lrelu(acc[nt][3]) * w1;
    }
    pA += __shfl_xor_sync(0xFFFFFFFFu, pA, 1);
    pA += __shfl_xor_sync(0xFFFFFFFFu, pA, 2);
    pB += __shfl_xor_sync(0xFFFFFFFFu, pB, 1);
    pB += __shfl_xor_sync(0xFFFFFFFFu, pB, 2);
    if (v == 0) {
        float b3v = __ldg(b3);
        int gA = node0 + r0 + u;
        if (gA < NN) out[gA] = 1.f / (1.f + expf(-(pA + b3v)));
        int gB = gA + 8;
        if (gB < NN) out[gB] = 1.f / (1.f + expf(-(pB + b3v)));
    }
}

// ---------------- launch ----------------
extern "C" void kernel_launch(void* const* d_in, const int* in_sizes, int n_in,
                              void* d_out, int out_size)
{
    const float* desc  = (const float*)d_in[0];
    const float* tweet = (const float*)d_in[1];
    const float* numf  = (const float*)d_in[2];
    const float* catf  = (const float*)d_in[3];
    const int*   ei    = (const int*)d_in[4];
    const int*   et    = (const int*)d_in[5];
    const float* Wd = (const float*)d_in[6];  const float* bd = (const float*)d_in[7];
    const float* Wt = (const float*)d_in[8];  const float* bt = (const float*)d_in[9];
    const float* Wn = (const float*)d_in[10]; const float* bn = (const float*)d_in[11];
    const float* Wc = (const float*)d_in[12]; const float* bc = (const float*)d_in[13];
    const float* W1 = (const float*)d_in[14]; const float* b1 = (const float*)d_in[15];
    const float* rg1_w    = (const float*)d_in[16];
    const float* rg1_root = (const float*)d_in[17];
    const float* rg1_bias = (const float*)d_in[18];
    const float* ln1_g = (const float*)d_in[19]; const float* ln1_b = (const float*)d_in[20];
    const float* rg2_w    = (const float*)d_in[21];
    const float* rg2_root = (const float*)d_in[22];
    const float* rg2_bias = (const float*)d_in[23];
    const float* ln2_g = (const float*)d_in[24]; const float* ln2_b = (const float*)d_in[25];
    const float* W2 = (const float*)d_in[26]; const float* b2 = (const float*)d_in[27];
    const float* W3 = (const float*)d_in[28]; const float* b3 = (const float*)d_in[29];

    float* xa; float* xb; double* sums;
    cudaGetSymbolAddress((void**)&xa, g_xa);
    cudaGetSymbolAddress((void**)&xb, g_xb);
    cudaGetSymbolAddress((void**)&sums, g_sums);

    const int SM_ENC  = 46080 * 4;   // 184320
    const int SM_RGCN = 53760 * 4;   // 215040
    const int SM_HEAD = (16384 + 16896 + 128) * 4;  // 133632
    cudaFuncSetAttribute(encode_kernel, cudaFuncAttributeMaxDynamicSharedMemorySize, SM_ENC);
    cudaFuncSetAttribute(rgcn_kernel,   cudaFuncAttributeMaxDynamicSharedMemorySize, SM_RGCN);
    cudaFuncSetAttribute(head_kernel,   cudaFuncAttributeMaxDynamicSharedMemorySize, SM_HEAD);

    const int GEMM_BLOCKS = (NN + 127) / 128;  // 391

    init_kernel<<<(NN + 255) / 256, 256>>>();
    hist_kernel<<<(EE + 255) / 256, 256>>>(ei);
    scan_kernel<<<1, 1024>>>();
    fill_kernel<<<(EE + 255) / 256, 256>>>(ei, et);

    encode_kernel<<<GEMM_BLOCKS, 256, SM_ENC>>>(desc, tweet, numf, catf,
                                                Wd, bd, Wt, bt, Wn, bn, Wc, bc,
                                                W1, b1, xa);

    pull_kernel<<<(NN + 7) / 8, 256>>>(xa);
    rgcn_kernel<<<GEMM_BLOCKS, 256, SM_RGCN>>>(xa, rg1_root, rg1_w, rg1_bias, xb, sums + 0);
    ln_kernel<<<1024, 256>>>(xb, ln1_g, ln1_b, sums + 0);

    pull_kernel<<<(NN + 7) / 8, 256>>>(xb);
    rgcn_kernel<<<GEMM_BLOCKS, 256, SM_RGCN>>>(xb, rg2_root, rg2_w, rg2_bias, xa, sums + 2);
    ln_kernel<<<1024, 256>>>(xa, ln2_g, ln2_b, sums + 2);

    head_kernel<<<GEMM_BLOCKS, 256, SM_HEAD>>>(xa, W2, b2, W3, b3, (float*)d_out);
}

// round 4
// speedup vs baseline: 1.5350x; 1.0910x over previous
#include <cuda_runtime.h>
#include <math.h>
#include <stdint.h>

#define NN 50000
#define EE 600000
#define DDIM 128
#define NTILES ((NN + 127) / 128)   // 391
#define PGRID 148

// ---------------- scratch (static device globals; no allocation) ----------------
__device__ float  g_xa[(size_t)NN * DDIM];
__device__ float  g_xb[(size_t)NN * DDIM];
__device__ float  g_agg[(size_t)2 * NN * DDIM];
__device__ int    g_deg[NN];
__device__ int    g_rowptr[NN + 1];
__device__ int    g_cur[NN];
__device__ int    g_ebuf[EE];
__device__ double g_sums[4];
__device__ float  g_sc1[DDIM], g_sh1[DDIM];   // LN1 affine
__device__ float  g_sc2[DDIM], g_sh2[DDIM];   // LN2 affine

__device__ __forceinline__ float lrelu(float x) { return x > 0.f ? x : 0.01f * x; }

__device__ __forceinline__ uint32_t f2tf(float x) {
    uint32_t u; asm("cvt.rna.tf32.f32 %0, %1;" : "=r"(u) : "f"(x)); return u;
}
__device__ __forceinline__ float f2tff(float x) { return __uint_as_float(f2tf(x)); }

__device__ __forceinline__ void mma_tf32(float c[4], uint32_t a0, uint32_t a1,
                                         uint32_t a2, uint32_t a3,
                                         uint32_t b0, uint32_t b1) {
    asm volatile(
        "mma.sync.aligned.m16n8k8.row.col.f32.tf32.tf32.f32 "
        "{%0,%1,%2,%3},{%4,%5,%6,%7},{%8,%9},{%0,%1,%2,%3};"
        : "+f"(c[0]), "+f"(c[1]), "+f"(c[2]), "+f"(c[3])
        : "r"(a0), "r"(a1), "r"(a2), "r"(a3), "r"(b0), "r"(b1));
}

// A fragment: sA row-major, pitch P (P % 32 == 4 -> conflict free)
__device__ __forceinline__ void lda_frag(const float* sA, int P, int r0, int k0,
                                         int u, int v, uint32_t& a0, uint32_t& a1,
                                         uint32_t& a2, uint32_t& a3) {
    const float* p = sA + (r0 + u) * P + k0 + v;
    a0 = __float_as_uint(p[0]);
    a1 = __float_as_uint(p[8 * P]);
    a2 = __float_as_uint(p[4]);
    a3 = __float_as_uint(p[8 * P + 4]);
}

// B fragment: sW swizzled [k][n ^ ((k&3)<<3)], row width Nw; k0 % 8 == 0
__device__ __forceinline__ void ldb_frag(const float* sW, int Nw, int k0, int n0,
                                         int u, int v, uint32_t& b0, uint32_t& b1) {
    int col = (n0 + u) ^ (v << 3);
    b0 = __float_as_uint(sW[(k0 + v) * Nw + col]);
    b1 = __float_as_uint(sW[(k0 + 4 + v) * Nw + col]);
}

// ---------------- tiny setup kernels ----------------
__global__ void init_kernel() {
    int i = blockIdx.x * blockDim.x + threadIdx.x;
    if (i < NN) g_deg[i] = 0;
    if (i < 4) g_sums[i] = 0.0;
}

__global__ void hist_kernel(const int* __restrict__ ei) {
    int e = blockIdx.x * blockDim.x + threadIdx.x;
    if (e < EE) atomicAdd(&g_deg[ei[EE + e]], 1);
}

__global__ void scan_kernel() {
    __shared__ int warp_sums[32];
    __shared__ int s_running;
    const int tid = threadIdx.x;
    const int lane = tid & 31, wid = tid >> 5;
    if (tid == 0) { s_running = 0; g_rowptr[0] = 0; }
    __syncthreads();
    for (int base = 0; base < NN; base += 1024) {
        int i = base + tid;
        int v = (i < NN) ? g_deg[i] : 0;
        int xs = v;
        #pragma unroll
        for (int o = 1; o < 32; o <<= 1) {
            int y = __shfl_up_sync(0xFFFFFFFFu, xs, o);
            if (lane >= o) xs += y;
        }
        if (lane == 31) warp_sums[wid] = xs;
        __syncthreads();
        if (wid == 0) {
            int s = warp_sums[lane];
            #pragma unroll
            for (int o = 1; o < 32; o <<= 1) {
                int y = __shfl_up_sync(0xFFFFFFFFu, s, o);
                if (lane >= o) s += y;
            }
            warp_sums[lane] = s;
        }
        __syncthreads();
        int offset = s_running + (wid > 0 ? warp_sums[wid - 1] : 0);
        int incl = offset + xs;
        if (i < NN) { g_rowptr[i + 1] = incl; g_cur[i] = incl - v; }
        __syncthreads();
        if (tid == 1023) s_running = incl;
        __syncthreads();
    }
}

__global__ void fill_kernel(const int* __restrict__ ei, const int* __restrict__ et) {
    int e = blockIdx.x * blockDim.x + threadIdx.x;
    if (e >= EE) return;
    int src = ei[e];
    int dst = ei[EE + e];
    int pos = atomicAdd(&g_cur[dst], 1);
    g_ebuf[pos] = src | (et[e] << 30);
}

// LN finalize: scale/shift from fused stats
__global__ void fin_kernel(const double* __restrict__ s,
                           const float* __restrict__ g,
                           const float* __restrict__ b,
                           float* __restrict__ scale,
                           float* __restrict__ shift) {
    int c = threadIdx.x;
    const double cnt = (double)NN * DDIM;
    double mu = s[0] / cnt;
    double var = s[1] / cnt - mu * mu;
    float rstd = (float)(1.0 / sqrt(var + 1e-5));
    float sc = rstd * g[c];
    scale[c] = sc;
    shift[c] = b[c] - (float)mu * sc;
}

// ---------------- encode: x = leaky( concat(proj4) @ W1 + b1 ) ----------------
// 256 threads (8 warps), 128 nodes per block, tf32 mma, reg-prefetch pipelining.
// smem: sW 24576 | sX0 128*132 | sA 128*36  (46080 floats = 184320 B)
__global__ void __launch_bounds__(256, 1) encode_kernel(
    const float* __restrict__ desc, const float* __restrict__ tweet,
    const float* __restrict__ numf, const float* __restrict__ catf,
    const float* __restrict__ Wd, const float* __restrict__ bd,
    const float* __restrict__ Wt, const float* __restrict__ bt,
    const float* __restrict__ Wn, const float* __restrict__ bn,
    const float* __restrict__ Wc, const float* __restrict__ bc,
    const float* __restrict__ W1, const float* __restrict__ b1,
    float* __restrict__ out)
{
    extern __shared__ float sm[];
    float* sW  = sm;                    // proj: 768*32 = 24576; W1: 128*128 = 16384
    float* sX0 = sm + 24576;            // 128*132
    float* sA  = sm + 24576 + 16896;    // 128*36
    const int tid = threadIdx.x;
    const int node0 = blockIdx.x * 128;
    const int lane = tid & 31, warp = tid >> 5;
    const int u = lane >> 2, v = lane & 3;
    const int r0 = warp * 16;
    const int srow = tid >> 3, sc4 = (tid & 7) * 4;   // staging coords (j stride 32 rows)

    // ---- desc / tweet projections (cols 0-31, 32-63) ----
    for (int ph = 0; ph < 2; ph++) {
        const float* In = ph ? tweet : desc;
        const float* W  = ph ? Wt : Wd;
        const float* B  = ph ? bt : bd;
        __syncthreads();  // prior compute done before sW overwrite
        for (int i = tid; i < 6144; i += 256) {
            float4 w = ((const float4*)W)[i];
            int k = i >> 3, n = (i & 7) * 4;
            float* d = sW + k * 32 + (n ^ ((k & 3) << 3));
            *(float4*)d = make_float4(f2tff(w.x), f2tff(w.y), f2tff(w.z), f2tff(w.w));
        }
        float acc[4][4];
        #pragma unroll
        for (int nt = 0; nt < 4; nt++) {
            float2 bv = *(const float2*)(B + nt * 8 + 2 * v);
            acc[nt][0] = bv.x; acc[nt][1] = bv.y; acc[nt][2] = bv.x; acc[nt][3] = bv.y;
        }
        // prefetch chunk 0
        float4 pv[4];
        #pragma unroll
        for (int j = 0; j < 4; j++) {
            int g = node0 + srow + j * 32;
            pv[j] = make_float4(0.f, 0.f, 0.f, 0.f);
            if (g < NN) pv[j] = __ldg((const float4*)(In + (size_t)g * 768 + sc4));
        }
        for (int c0 = 0; c0 < 768; c0 += 32) {
            __syncthreads();   // sA consumers (prev chunk) done; also fences sW load
            #pragma unroll
            for (int j = 0; j < 4; j++)
                *(float4*)(sA + (srow + j * 32) * 36 + sc4) =
                    make_float4(f2tff(pv[j].x), f2tff(pv[j].y), f2tff(pv[j].z), f2tff(pv[j].w));
            __syncthreads();
            if (c0 + 32 < 768) {
                #pragma unroll
                for (int j = 0; j < 4; j++) {
                    int g = node0 + srow + j * 32;
                    pv[j] = make_float4(0.f, 0.f, 0.f, 0.f);
                    if (g < NN) pv[j] = __ldg((const float4*)(In + (size_t)g * 768 + c0 + 32 + sc4));
                }
            }
            #pragma unroll
            for (int ks = 0; ks < 4; ks++) {
                int k0 = ks * 8;
                uint32_t a0, a1, a2, a3;
                lda_frag(sA, 36, r0, k0, u, v, a0, a1, a2, a3);
                int kw = c0 + k0;
                #pragma unroll
                for (int nt = 0; nt < 4; nt++) {
                    uint32_t b0, b1;
                    ldb_frag(sW, 32, kw, nt * 8, u, v, b0, b1);
                    mma_tf32(acc[nt], a0, a1, a2, a3, b0, b1);
                }
            }
        }
        const int cb = ph * 32;
        #pragma unroll
        for (int nt = 0; nt < 4; nt++) {
            int col = cb + nt * 8 + 2 * v;
            float2 o;
            o.x = f2tff(lrelu(acc[nt][0])); o.y = f2tff(lrelu(acc[nt][1]));
            *(float2*)(sX0 + (r0 + u) * 132 + col) = o;
            o.x = f2tff(lrelu(acc[nt][2])); o.y = f2tff(lrelu(acc[nt][3]));
            *(float2*)(sX0 + (r0 + u + 8) * 132 + col) = o;
        }
    }

    // ---- num / cat projections (cols 64-127) ----
    __syncthreads();
    if (tid < 160) sW[tid] = Wn[tid];
    if (tid < 96)  sW[160 + tid] = Wc[tid];
    if (tid < 32)  { sW[256 + tid] = bn[tid]; sW[288 + tid] = bc[tid]; }
    __syncthreads();
    for (int o = tid; o < 8192; o += 256) {
        int row = o >> 6, c = o & 63;
        int g = node0 + row;
        float vv = 0.f;
        if (g < NN) {
            if (c < 32) {
                float a = sW[256 + c];
                #pragma unroll
                for (int k = 0; k < 5; k++)
                    a = fmaf(__ldg(numf + (size_t)g * 5 + k), sW[k * 32 + c], a);
                vv = lrelu(a);
            } else {
                int cc = c - 32;
                float a = sW[288 + cc];
                #pragma unroll
                for (int k = 0; k < 3; k++)
                    a = fmaf(__ldg(catf + (size_t)g * 3 + k), sW[160 + k * 32 + cc], a);
                vv = lrelu(a);
            }
        }
        sX0[row * 132 + 64 + c] = f2tff(vv);
    }

    // ---- W1: out = leaky( x0 @ W1 + b1 ) ----
    __syncthreads();
    for (int i = tid; i < 4096; i += 256) {
        float4 w = ((const float4*)W1)[i];
        int k = i >> 5, n = (i & 31) * 4;
        float* d = sW + k * 128 + (n ^ ((k & 3) << 3));
        *(float4*)d = make_float4(f2tff(w.x), f2tff(w.y), f2tff(w.z), f2tff(w.w));
    }
    __syncthreads();
    {
        float acc[16][4];
        #pragma unroll
        for (int nt = 0; nt < 16; nt++) {
            float2 bv = *(const float2*)(b1 + nt * 8 + 2 * v);
            acc[nt][0] = bv.x; acc[nt][1] = bv.y; acc[nt][2] = bv.x; acc[nt][3] = bv.y;
        }
        #pragma unroll 4
        for (int ks = 0; ks < 16; ks++) {
            int k0 = ks * 8;
            uint32_t a0, a1, a2, a3;
            lda_frag(sX0, 132, r0, k0, u, v, a0, a1, a2, a3);
            #pragma unroll
            for (int nt = 0; nt < 16; nt++) {
                uint32_t b0, b1;
                ldb_frag(sW, 128, k0, nt * 8, u, v, b0, b1);
                mma_tf32(acc[nt], a0, a1, a2, a3, b0, b1);
            }
        }
        int gA = node0 + r0 + u, gB = gA + 8;
        #pragma unroll
        for (int nt = 0; nt < 16; nt++) {
            int col = nt * 8 + 2 * v;
            if (gA < NN) {
                float2 o; o.x = lrelu(acc[nt][0]); o.y = lrelu(acc[nt][1]);
                *(float2*)(out + (size_t)gA * 128 + col) = o;
            }
            if (gB < NN) {
                float2 o; o.x = lrelu(acc[nt][2]); o.y = lrelu(acc[nt][3]);
                *(float2*)(out + (size_t)gB * 128 + col) = o;
            }
        }
    }
}

// ---------------- pull: per-relation segment-max into g_agg (warp per node) ----------------
// Optionally applies the LN affine (x*sc+sh) to gathered values (max of empty stays 0).
__global__ void pull_kernel(const float* __restrict__ x,
                            const float* __restrict__ scale,
                            const float* __restrict__ shift,
                            int apply) {
    const int w = (blockIdx.x * blockDim.x + threadIdx.x) >> 5;
    const int lane = threadIdx.x & 31;
    if (w >= NN) return;
    float4 sc = make_float4(1.f, 1.f, 1.f, 1.f);
    float4 sh = make_float4(0.f, 0.f, 0.f, 0.f);
    if (apply) {
        sc = __ldg((const float4*)scale + lane);
        sh = __ldg((const float4*)shift + lane);
    }
    const int beg = g_rowptr[w], end = g_rowptr[w + 1];
    const float NEG = -3.0e38f;
    float4 a0 = make_float4(NEG, NEG, NEG, NEG);
    float4 a1 = a0;
    int e = beg;
    for (; e + 2 <= end; e += 2) {
        int v0 = g_ebuf[e], v1 = g_ebuf[e + 1];
        float4 f0 = __ldg((const float4*)(x + (size_t)(v0 & 0x3FFFFFFF) * 128) + lane);
        float4 f1 = __ldg((const float4*)(x + (size_t)(v1 & 0x3FFFFFFF) * 128) + lane);
        f0.x = fmaf(f0.x, sc.x, sh.x); f0.y = fmaf(f0.y, sc.y, sh.y);
        f0.z = fmaf(f0.z, sc.z, sh.z); f0.w = fmaf(f0.w, sc.w, sh.w);
        f1.x = fmaf(f1.x, sc.x, sh.x); f1.y = fmaf(f1.y, sc.y, sh.y);
        f1.z = fmaf(f1.z, sc.z, sh.z); f1.w = fmaf(f1.w, sc.w, sh.w);
        if (v0 >> 30) {
            a1.x = fmaxf(a1.x, f0.x); a1.y = fmaxf(a1.y, f0.y);
            a1.z = fmaxf(a1.z, f0.z); a1.w = fmaxf(a1.w, f0.w);
        } else {
            a0.x = fmaxf(a0.x, f0.x); a0.y = fmaxf(a0.y, f0.y);
            a0.z = fmaxf(a0.z, f0.z); a0.w = fmaxf(a0.w, f0.w);
        }
        if (v1 >> 30) {
            a1.x = fmaxf(a1.x, f1.x); a1.y = fmaxf(a1.y, f1.y);
            a1.z = fmaxf(a1.z, f1.z); a1.w = fmaxf(a1.w, f1.w);
        } else {
            a0.x = fmaxf(a0.x, f1.x); a0.y = fmaxf(a0.y, f1.y);
            a0.z = fmaxf(a0.z, f1.z); a0.w = fmaxf(a0.w, f1.w);
        }
    }
    if (e < end) {
        int v0 = g_ebuf[e];
        float4 f0 = __ldg((const float4*)(x + (size_t)(v0 & 0x3FFFFFFF) * 128) + lane);
        f0.x = fmaf(f0.x, sc.x, sh.x); f0.y = fmaf(f0.y, sc.y, sh.y);
        f0.z = fmaf(f0.z, sc.z, sh.z); f0.w = fmaf(f0.w, sc.w, sh.w);
        if (v0 >> 30) {
            a1.x = fmaxf(a1.x, f0.x); a1.y = fmaxf(a1.y, f0.y);
            a1.z = fmaxf(a1.z, f0.z); a1.w = fmaxf(a1.w, f0.w);
        } else {
            a0.x = fmaxf(a0.x, f0.x); a0.y = fmaxf(a0.y, f0.y);
            a0.z = fmaxf(a0.z, f0.z); a0.w = fmaxf(a0.w, f0.w);
        }
    }
    float4 o0, o1;
    o0.x = (a0.x == NEG) ? 0.f : a0.x; o0.y = (a0.y == NEG) ? 0.f : a0.y;
    o0.z = (a0.z == NEG) ? 0.f : a0.z; o0.w = (a0.w == NEG) ? 0.f : a0.w;
    o1.x = (a1.x == NEG) ? 0.f : a1.x; o1.y = (a1.y == NEG) ? 0.f : a1.y;
    o1.z = (a1.z == NEG) ? 0.f : a1.z; o1.w = (a1.w == NEG) ? 0.f : a1.w;
    ((float4*)(g_agg + (size_t)w * 128))[lane] = o0;
    ((float4*)(g_agg + (size_t)(NN + w) * 128))[lane] = o1;
}

// ---------------- RGCN GEMM (tf32, persistent): out = [x'|agg0|agg1]@[root;W0;W1]+bias
// x' = optionally LN-transformed x (apply=1 -> x*scale+shift during staging).
// Fused LN stats. grid=PGRID, 256 threads. smem: sW 49152 | sA 128*36 (215040 B)
__global__ void __launch_bounds__(256, 1) rgcn_kernel(
    const float* __restrict__ x,
    const float* __restrict__ root,
    const float* __restrict__ relw,
    const float* __restrict__ bias,
    const float* __restrict__ scale,
    const float* __restrict__ shift,
    int apply,
    float* __restrict__ out,
    double* __restrict__ sums)
{
    extern __shared__ float sm[];
    float* sW = sm;            // 49152 floats, swizzled [k][n^((k&3)<<3)]
    float* sA = sm + 49152;    // 128*36
    __shared__ double sred[2];
    const int tid = threadIdx.x;
    const int lane = tid & 31, warp = tid >> 5;
    const int u = lane >> 2, v = lane & 3;
    const int r0 = warp * 16;
    const int srow = tid >> 3, sc4 = (tid & 7) * 4;
    if (tid < 2) sred[tid] = 0.0;

    // weights once per block (persistent)
    for (int i = tid; i < 4096; i += 256) {
        float4 w = ((const float4*)root)[i];
        int k = i >> 5, n = (i & 31) * 4;
        float* d = sW + k * 128 + (n ^ ((k & 3) << 3));
        *(float4*)d = make_float4(f2tff(w.x), f2tff(w.y), f2tff(w.z), f2tff(w.w));
    }
    for (int i = tid; i < 8192; i += 256) {
        float4 w = ((const float4*)relw)[i];
        int k = 128 + (i >> 5), n = (i & 31) * 4;
        float* d = sW + k * 128 + (n ^ ((k & 3) << 3));
        *(float4*)d = make_float4(f2tff(w.x), f2tff(w.y), f2tff(w.z), f2tff(w.w));
    }

    float2 bias_r[16];
    #pragma unroll
    for (int nt = 0; nt < 16; nt++)
        bias_r[nt] = *(const float2*)(bias + nt * 8 + 2 * v);

    for (int tile = blockIdx.x; tile < NTILES; tile += PGRID) {
        const int node0 = tile * 128;
        float acc[16][4];
        #pragma unroll
        for (int nt = 0; nt < 16; nt++) {
            acc[nt][0] = bias_r[nt].x; acc[nt][1] = bias_r[nt].y;
            acc[nt][2] = bias_r[nt].x; acc[nt][3] = bias_r[nt].y;
        }

        float4 pv[4];
        // prefetch chunk 0 (x-part, colofs 0)
        {
            const bool tx = (apply != 0);
            #pragma unroll
            for (int j = 0; j < 4; j++) {
                int g = node0 + srow + j * 32;
                float4 val = make_float4(0.f, 0.f, 0.f, 0.f);
                if (g < NN) val = __ldg((const float4*)(x + (size_t)g * 128 + sc4));
                if (tx) {
                    float4 s4 = __ldg((const float4*)scale + (sc4 >> 2));
                    float4 h4 = __ldg((const float4*)shift + (sc4 >> 2));
                    val.x = fmaf(val.x, s4.x, h4.x); val.y = fmaf(val.y, s4.y, h4.y);
                    val.z = fmaf(val.z, s4.z, h4.z); val.w = fmaf(val.w, s4.w, h4.w);
                }
                pv[j] = val;
            }
        }

        for (int ci = 0; ci < 12; ci++) {
            __syncthreads();   // sA consumers done (also fences weight load on first pass)
            #pragma unroll
            for (int j = 0; j < 4; j++)
                *(float4*)(sA + (srow + j * 32) * 36 + sc4) =
                    make_float4(f2tff(pv[j].x), f2tff(pv[j].y), f2tff(pv[j].z), f2tff(pv[j].w));
            __syncthreads();
            if (ci + 1 < 12) {
                const int cn = ci + 1;
                const float* ptr = (cn < 4) ? x : ((cn < 8) ? g_agg : g_agg + (size_t)NN * DDIM);
                const int colofs = (cn & 3) * 32;
                const bool tx = (apply != 0) && (cn < 4);
                #pragma unroll
                for (int j = 0; j < 4; j++) {
                    int g = node0 + srow + j * 32;
                    float4 val = make_float4(0.f, 0.f, 0.f, 0.f);
                    if (g < NN) val = __ldg((const float4*)(ptr + (size_t)g * 128 + colofs + sc4));
                    if (tx) {
                        float4 s4 = __ldg((const float4*)scale + ((colofs + sc4) >> 2));
                        float4 h4 = __ldg((const float4*)shift + ((colofs + sc4) >> 2));
                        val.x = fmaf(val.x, s4.x, h4.x); val.y = fmaf(val.y, s4.y, h4.y);
                        val.z = fmaf(val.z, s4.z, h4.z); val.w = fmaf(val.w, s4.w, h4.w);
                    }
                    pv[j] = val;
                }
            }
            const int c0 = ci * 32;
            #pragma unroll
            for (int ks = 0; ks < 4; ks++) {
                int k0 = ks * 8;
                uint32_t a0, a1, a2, a3;
                lda_frag(sA, 36, r0, k0, u, v, a0, a1, a2, a3);
                int kw = c0 + k0;
                #pragma unroll
                for (int nt = 0; nt < 16; nt++) {
                    uint32_t b0, b1;
                    ldb_frag(sW, 128, kw, nt * 8, u, v, b0, b1);
                    mma_tf32(acc[nt], a0, a1, a2, a3, b0, b1);
                }
            }
        }

        int gA = node0 + r0 + u, gB = gA + 8;
        float ls = 0.f, lq = 0.f;
        #pragma unroll
        for (int nt = 0; nt < 16; nt++) {
            int col = nt * 8 + 2 * v;
            if (gA < NN) {
                float x0 = acc[nt][0], x1 = acc[nt][1];
                float2 o; o.x = x0; o.y = x1;
                *(float2*)(out + (size_t)gA * 128 + col) = o;
                ls += x0 + x1; lq += x0 * x0 + x1 * x1;
            }
            if (gB < NN) {
                float x0 = acc[nt][2], x1 = acc[nt][3];
                float2 o; o.x = x0; o.y = x1;
                *(float2*)(out + (size_t)gB * 128 + col) = o;
                ls += x0 + x1; lq += x0 * x0 + x1 * x1;
            }
        }
        #pragma unroll
        for (int off = 16; off; off >>= 1) {
            ls += __shfl_down_sync(0xFFFFFFFFu, ls, off);
            lq += __shfl_down_sync(0xFFFFFFFFu, lq, off);
        }
        if (lane == 0) {
            atomicAdd(&sred[0], (double)ls);
            atomicAdd(&sred[1], (double)lq);
        }
    }

    __syncthreads();
    if (tid == 0) {
        atomicAdd(&sums[0], sred[0]);
        atomicAdd(&sums[1], sred[1]);
    }
}

// ---------------- head: out = sigmoid( leaky(LN2(x)@W2+b2) @ W3 + b3 ) ----------------
// LN2 affine applied during staging. 256 threads. smem: sW 16384 | sX 128*132 | w3 128
__global__ void __launch_bounds__(256, 1) head_kernel(
    const float* __restrict__ x,
    const float* __restrict__ W2,
    const float* __restrict__ b2,
    const float* __restrict__ W3,
    const float* __restrict__ b3,
    const float* __restrict__ scale,
    const float* __restrict__ shift,
    float* __restrict__ out)
{
    extern __shared__ float sm[];
    float* sW  = sm;                 // 16384, swizzled
    float* sX  = sm + 16384;         // 128*132
    float* sw3 = sm + 16384 + 16896; // 128
    const int tid = threadIdx.x;
    const int node0 = blockIdx.x * 128;
    const int lane = tid & 31, warp = tid >> 5;
    const int u = lane >> 2, v = lane & 3;
    const int r0 = warp * 16;

    for (int i = tid; i < 4096; i += 256) {
        float4 w = ((const float4*)W2)[i];
        int k = i >> 5, n = (i & 31) * 4;
        float* d = sW + k * 128 + (n ^ ((k & 3) << 3));
        *(float4*)d = make_float4(f2tff(w.x), f2tff(w.y), f2tff(w.z), f2tff(w.w));
    }
    for (int i = tid; i < 4096; i += 256) {
        int row = i >> 5, c4 = (i & 31) * 4;
        int g = node0 + row;
        float4 val = make_float4(0.f, 0.f, 0.f, 0.f);
        if (g < NN) {
            val = __ldg((const float4*)(x + (size_t)g * 128 + c4));
            float4 s4 = __ldg((const float4*)scale + (c4 >> 2));
            float4 h4 = __ldg((const float4*)shift + (c4 >> 2));
            val.x = fmaf(val.x, s4.x, h4.x); val.y = fmaf(val.y, s4.y, h4.y);
            val.z = fmaf(val.z, s4.z, h4.z); val.w = fmaf(val.w, s4.w, h4.w);
        }
        *(float4*)(sX + row * 132 + c4) =
            make_float4(f2tff(val.x), f2tff(val.y), f2tff(val.z), f2tff(val.w));
    }
    if (tid < 128) sw3[tid] = W3[tid];
    __syncthreads();

    float acc[16][4];
    #pragma unroll
    for (int nt = 0; nt < 16; nt++) {
        float2 bv = *(const float2*)(b2 + nt * 8 + 2 * v);
        acc[nt][0] = bv.x; acc[nt][1] = bv.y; acc[nt][2] = bv.x; acc[nt][3] = bv.y;
    }
    #pragma unroll 4
    for (int ks = 0; ks < 16; ks++) {
        int k0 = ks * 8;
        uint32_t a0, a1, a2, a3;
        lda_frag(sX, 132, r0, k0, u, v, a0, a1, a2, a3);
        #pragma unroll
        for (int nt = 0; nt < 16; nt++) {
            uint32_t b0, b1;
            ldb_frag(sW, 128, k0, nt * 8, u, v, b0, b1);
            mma_tf32(acc[nt], a0, a1, a2, a3, b0, b1);
        }
    }

    float pA = 0.f, pB = 0.f;
    #pragma unroll
    for (int nt = 0; nt < 16; nt++) {
        int col = nt * 8 + 2 * v;
        float w0 = sw3[col], w1 = sw3[col + 1];
        pA += lrelu(acc[nt][0]) * w0 + lrelu(acc[nt][1]) * w1;
        pB += lrelu(acc[nt][2]) * w0 + lrelu(acc[nt][3]) * w1;
    }
    pA += __shfl_xor_sync(0xFFFFFFFFu, pA, 1);
    pA += __shfl_xor_sync(0xFFFFFFFFu, pA, 2);
    pB += __shfl_xor_sync(0xFFFFFFFFu, pB, 1);
    pB += __shfl_xor_sync(0xFFFFFFFFu, pB, 2);
    if (v == 0) {
        float b3v = __ldg(b3);
        int gA = node0 + r0 + u;
        if (gA < NN) out[gA] = 1.f / (1.f + expf(-(pA + b3v)));
        int gB = gA + 8;
        if (gB < NN) out[gB] = 1.f / (1.f + expf(-(pB + b3v)));
    }
}

// ---------------- launch ----------------
extern "C" void kernel_launch(void* const* d_in, const int* in_sizes, int n_in,
                              void* d_out, int out_size)
{
    const float* desc  = (const float*)d_in[0];
    const float* tweet = (const float*)d_in[1];
    const float* numf  = (const float*)d_in[2];
    const float* catf  = (const float*)d_in[3];
    const int*   ei    = (const int*)d_in[4];
    const int*   et    = (const int*)d_in[5];
    const float* Wd = (const float*)d_in[6];  const float* bd = (const float*)d_in[7];
    const float* Wt = (const float*)d_in[8];  const float* bt = (const float*)d_in[9];
    const float* Wn = (const float*)d_in[10]; const float* bn = (const float*)d_in[11];
    const float* Wc = (const float*)d_in[12]; const float* bc = (const float*)d_in[13];
    const float* W1 = (const float*)d_in[14]; const float* b1 = (const float*)d_in[15];
    const float* rg1_w    = (const float*)d_in[16];
    const float* rg1_root = (const float*)d_in[17];
    const float* rg1_bias = (const float*)d_in[18];
    const float* ln1_g = (const float*)d_in[19]; const float* ln1_b = (const float*)d_in[20];
    const float* rg2_w    = (const float*)d_in[21];
    const float* rg2_root = (const float*)d_in[22];
    const float* rg2_bias = (const float*)d_in[23];
    const float* ln2_g = (const float*)d_in[24]; const float* ln2_b = (const float*)d_in[25];
    const float* W2 = (const float*)d_in[26]; const float* b2 = (const float*)d_in[27];
    const float* W3 = (const float*)d_in[28]; const float* b3 = (const float*)d_in[29];

    float *xa, *xb, *sc1, *sh1, *sc2, *sh2;
    double* sums;
    cudaGetSymbolAddress((void**)&xa, g_xa);
    cudaGetSymbolAddress((void**)&xb, g_xb);
    cudaGetSymbolAddress((void**)&sums, g_sums);
    cudaGetSymbolAddress((void**)&sc1, g_sc1);
    cudaGetSymbolAddress((void**)&sh1, g_sh1);
    cudaGetSymbolAddress((void**)&sc2, g_sc2);
    cudaGetSymbolAddress((void**)&sh2, g_sh2);

    const int SM_ENC  = 46080 * 4;   // 184320
    const int SM_RGCN = 53760 * 4;   // 215040
    const int SM_HEAD = (16384 + 16896 + 128) * 4;  // 133632
    cudaFuncSetAttribute(encode_kernel, cudaFuncAttributeMaxDynamicSharedMemorySize, SM_ENC);
    cudaFuncSetAttribute(rgcn_kernel,   cudaFuncAttributeMaxDynamicSharedMemorySize, SM_RGCN);
    cudaFuncSetAttribute(head_kernel,   cudaFuncAttributeMaxDynamicSharedMemorySize, SM_HEAD);

    init_kernel<<<(NN + 255) / 256, 256>>>();
    hist_kernel<<<(EE + 255) / 256, 256>>>(ei);
    scan_kernel<<<1, 1024>>>();
    fill_kernel<<<(EE + 255) / 256, 256>>>(ei, et);

    encode_kernel<<<NTILES, 256, SM_ENC>>>(desc, tweet, numf, catf,
                                           Wd, bd, Wt, bt, Wn, bn, Wc, bc,
                                           W1, b1, xa);

    pull_kernel<<<(NN + 7) / 8, 256>>>(xa, sc1, sh1, 0);
    rgcn_kernel<<<PGRID, 256, SM_RGCN>>>(xa, rg1_root, rg1_w, rg1_bias,
                                         sc1, sh1, 0, xb, sums + 0);
    fin_kernel<<<1, 128>>>(sums + 0, ln1_g, ln1_b, sc1, sh1);

    pull_kernel<<<(NN + 7) / 8, 256>>>(xb, sc1, sh1, 1);
    rgcn_kernel<<<PGRID, 256, SM_RGCN>>>(xb, rg2_root, rg2_w, rg2_bias,
                                         sc1, sh1, 1, xa, sums + 2);
    fin_kernel<<<1, 128>>>(sums + 2, ln2_g, ln2_b, sc2, sh2);

    head_kernel<<<NTILES, 256, SM_HEAD>>>(xa, W2, b2, W3, b3, sc2, sh2, (float*)d_out);
}

// round 5
// speedup vs baseline: 1.8375x; 1.1970x over previous
#include <cuda_runtime.h>
#include <cuda_fp16.h>
#include <math.h>
#include <stdint.h>

#define NN 50000
#define EE 600000
#define DDIM 128
#define NTILES ((NN + 127) / 128)   // 391
#define PGRID 148

// ---------------- scratch ----------------
__device__ float  g_xa[(size_t)NN * DDIM];
__device__ float  g_xb[(size_t)NN * DDIM];
__device__ float  g_agg[(size_t)2 * NN * DDIM];
__device__ int    g_deg[NN];
__device__ int    g_rowptr[NN + 1];
__device__ int    g_cur[NN];
__device__ int    g_ebuf[EE];
__device__ double g_sums[4];
__device__ float  g_sc1[DDIM], g_sh1[DDIM];
__device__ float  g_sc2[DDIM], g_sh2[DDIM];

__device__ __forceinline__ float lrelu(float x) { return x > 0.f ? x : 0.01f * x; }

__device__ __forceinline__ uint32_t pk(float a, float b) {
    __half2 h = __floats2half2_rn(a, b);
    return *reinterpret_cast<uint32_t*>(&h);
}

// fp16 mma m16n8k16, fp32 accum
__device__ __forceinline__ void mma_f16(float c[4], uint32_t a0, uint32_t a1,
                                        uint32_t a2, uint32_t a3,
                                        uint32_t b0, uint32_t b1) {
    asm volatile(
        "mma.sync.aligned.m16n8k16.row.col.f32.f16.f16.f32 "
        "{%0,%1,%2,%3},{%4,%5,%6,%7},{%8,%9},{%0,%1,%2,%3};"
        : "+f"(c[0]), "+f"(c[1]), "+f"(c[2]), "+f"(c[3])
        : "r"(a0), "r"(a1), "r"(a2), "r"(a3), "r"(b0), "r"(b1));
}

// A fragment from half2-word smem [row][kp], pitch P words. kp0 % 8 == 0.
__device__ __forceinline__ void lda16(const uint32_t* sA, int P, int row, int kp0, int v,
                                      uint32_t& a0, uint32_t& a1, uint32_t& a2, uint32_t& a3) {
    const uint32_t* p = sA + row * P + kp0 + v;
    a0 = p[0]; a1 = p[8 * P]; a2 = p[4]; a3 = p[8 * P + 4];
}

// B fragment from half2-word smem [kp][n ^ ((kp&3)<<3)], pitch P words. kp0 % 8 == 0.
__device__ __forceinline__ void ldb16(const uint32_t* sW, int P, int kp0, int n0, int u, int v,
                                      uint32_t& b0, uint32_t& b1) {
    int col = (n0 + u) ^ (v << 3);
    b0 = sW[(kp0 + v) * P + col];
    b1 = sW[(kp0 + v + 4) * P + col];
}

// convert weight rows 2kp,2kp+1 cols n4..n4+3 into 4 half2 words, swizzled store
__device__ __forceinline__ void cvtw(uint32_t* sW, int P, const float* W, int N, int kp, int n4) {
    float4 f0 = __ldg((const float4*)(W + (size_t)(2 * kp) * N + n4));
    float4 f1 = __ldg((const float4*)(W + (size_t)(2 * kp + 1) * N + n4));
    uint4 w;
    w.x = pk(f0.x, f1.x); w.y = pk(f0.y, f1.y);
    w.z = pk(f0.z, f1.z); w.w = pk(f0.w, f1.w);
    *(uint4*)(sW + kp * P + (n4 ^ ((kp & 3) << 3))) = w;
}

// ---------------- tiny setup kernels ----------------
__global__ void init_kernel() {
    int i = blockIdx.x * blockDim.x + threadIdx.x;
    if (i < NN) g_deg[i] = 0;
    if (i < 4) g_sums[i] = 0.0;
}

__global__ void hist_kernel(const int* __restrict__ ei) {
    int e = blockIdx.x * blockDim.x + threadIdx.x;
    if (e < EE) atomicAdd(&g_deg[ei[EE + e]], 1);
}

__global__ void scan_kernel() {
    __shared__ int warp_sums[32];
    __shared__ int s_running;
    const int tid = threadIdx.x;
    const int lane = tid & 31, wid = tid >> 5;
    if (tid == 0) { s_running = 0; g_rowptr[0] = 0; }
    __syncthreads();
    for (int base = 0; base < NN; base += 1024) {
        int i = base + tid;
        int v = (i < NN) ? g_deg[i] : 0;
        int xs = v;
        #pragma unroll
        for (int o = 1; o < 32; o <<= 1) {
            int y = __shfl_up_sync(0xFFFFFFFFu, xs, o);
            if (lane >= o) xs += y;
        }
        if (lane == 31) warp_sums[wid] = xs;
        __syncthreads();
        if (wid == 0) {
            int s = warp_sums[lane];
            #pragma unroll
            for (int o = 1; o < 32; o <<= 1) {
                int y = __shfl_up_sync(0xFFFFFFFFu, s, o);
                if (lane >= o) s += y;
            }
            warp_sums[lane] = s;
        }
        __syncthreads();
        int offset = s_running + (wid > 0 ? warp_sums[wid - 1] : 0);
        int incl = offset + xs;
        if (i < NN) { g_rowptr[i + 1] = incl; g_cur[i] = incl - v; }
        __syncthreads();
        if (tid == 1023) s_running = incl;
        __syncthreads();
    }
}

__global__ void fill_kernel(const int* __restrict__ ei, const int* __restrict__ et) {
    int e = blockIdx.x * blockDim.x + threadIdx.x;
    if (e >= EE) return;
    int src = ei[e];
    int dst = ei[EE + e];
    int pos = atomicAdd(&g_cur[dst], 1);
    g_ebuf[pos] = src | (et[e] << 30);
}

__global__ void fin_kernel(const double* __restrict__ s,
                           const float* __restrict__ g,
                           const float* __restrict__ b,
                           float* __restrict__ scale,
                           float* __restrict__ shift) {
    int c = threadIdx.x;
    const double cnt = (double)NN * DDIM;
    double mu = s[0] / cnt;
    double var = s[1] / cnt - mu * mu;
    float rstd = (float)(1.0 / sqrt(var + 1e-5));
    float sc = rstd * g[c];
    scale[c] = sc;
    shift[c] = b[c] - (float)mu * sc;
}

// ---------------- encode ----------------
// smem (uint32 words): sWd 12288 | sWt 12288 | sW1 8192 | sX0 128*68 | sA0 2560 | sA1 2560 | sNC 320
__global__ void __launch_bounds__(256, 1) encode_kernel(
    const float* __restrict__ desc, const float* __restrict__ tweet,
    const float* __restrict__ numf, const float* __restrict__ catf,
    const float* __restrict__ Wd, const float* __restrict__ bd,
    const float* __restrict__ Wt, const float* __restrict__ bt,
    const float* __restrict__ Wn, const float* __restrict__ bn,
    const float* __restrict__ Wc, const float* __restrict__ bc,
    const float* __restrict__ W1, const float* __restrict__ b1,
    float* __restrict__ out)
{
    extern __shared__ uint32_t S[];
    uint32_t* sWd = S;
    uint32_t* sWt = S + 12288;
    uint32_t* sW1 = S + 24576;
    uint32_t* sX0 = S + 32768;     // pitch 68 words (half2 pairs), 128 rows
    uint32_t* sA0 = S + 41472;     // pitch 20 words, 128 rows
    uint32_t* sA1 = S + 44032;
    float*    sNC = (float*)(S + 46592);

    const int tid = threadIdx.x;
    const int node0 = blockIdx.x * 128;
    const int lane = tid & 31, warp = tid >> 5;
    const int u = lane >> 2, v = lane & 3;
    const int r0 = warp * 16;
    const int srow = tid >> 3, sc4 = (tid & 7) * 4;

    // ---- convert weights (once) ----
    for (int i = tid; i < 3072; i += 256) cvtw(sWd, 32, Wd, 32, i >> 3, (i & 7) * 4);
    for (int i = tid; i < 3072; i += 256) cvtw(sWt, 32, Wt, 32, i >> 3, (i & 7) * 4);
    for (int i = tid; i < 2048; i += 256) cvtw(sW1, 128, W1, 128, i >> 5, (i & 31) * 4);
    if (tid < 160) sNC[tid] = Wn[tid];
    if (tid < 96)  sNC[160 + tid] = Wc[tid];
    if (tid < 32)  { sNC[256 + tid] = bn[tid]; sNC[288 + tid] = bc[tid]; }

    // ---- desc / tweet projections (K=768, N=32) ----
    for (int ph = 0; ph < 2; ph++) {
        const float* In = ph ? tweet : desc;
        const float* B  = ph ? bt : bd;
        const uint32_t* sWp = ph ? sWt : sWd;

        float acc[4][4];
        #pragma unroll
        for (int nt = 0; nt < 4; nt++) {
            float2 bv = *(const float2*)(B + nt * 8 + 2 * v);
            acc[nt][0] = bv.x; acc[nt][1] = bv.y; acc[nt][2] = bv.x; acc[nt][3] = bv.y;
        }

        float4 pvA[4], pvB[4];
        // prologue: LDG c0 -> pvA, c1 -> pvB; stage c0
        #pragma unroll
        for (int j = 0; j < 4; j++) {
            int g = node0 + srow + j * 32;
            pvA[j] = make_float4(0.f, 0.f, 0.f, 0.f);
            pvB[j] = make_float4(0.f, 0.f, 0.f, 0.f);
            if (g < NN) {
                pvA[j] = __ldg((const float4*)(In + (size_t)g * 768 + sc4));
                pvB[j] = __ldg((const float4*)(In + (size_t)g * 768 + 32 + sc4));
            }
        }
        #pragma unroll
        for (int j = 0; j < 4; j++) {
            uint2 w; w.x = pk(pvA[j].x, pvA[j].y); w.y = pk(pvA[j].z, pvA[j].w);
            *(uint2*)(sA0 + (srow + j * 32) * 20 + (sc4 >> 1)) = w;
        }
        __syncthreads();

        // iter(ci): LDG ci+2 -> pvl; STS ci+1 from pvs -> dst; mma ci from src; sync
        #define ENC_ITER(CI, PVL, PVS, SRC, DST)                                        \
        {                                                                                \
            if ((CI) + 2 < 24) {                                                         \
                _Pragma("unroll")                                                        \
                for (int j = 0; j < 4; j++) {                                            \
                    int g = node0 + srow + j * 32;                                       \
                    PVL[j] = make_float4(0.f, 0.f, 0.f, 0.f);                            \
                    if (g < NN)                                                          \
                        PVL[j] = __ldg((const float4*)(In + (size_t)g * 768              \
                                                       + ((CI) + 2) * 32 + sc4));        \
                }                                                                        \
            }                                                                            \
            if ((CI) + 1 < 24) {                                                         \
                _Pragma("unroll")                                                        \
                for (int j = 0; j < 4; j++) {                                            \
                    uint2 w; w.x = pk(PVS[j].x, PVS[j].y); w.y = pk(PVS[j].z, PVS[j].w); \
                    *(uint2*)((DST) + (srow + j * 32) * 20 + (sc4 >> 1)) = w;            \
                }                                                                        \
            }                                                                            \
            _Pragma("unroll")                                                            \
            for (int ks = 0; ks < 2; ks++) {                                             \
                uint32_t a0, a1, a2, a3;                                                 \
                lda16((SRC), 20, r0 + u, ks * 8, v, a0, a1, a2, a3);                     \
                int kp0 = (CI) * 16 + ks * 8;                                            \
                _Pragma("unroll")                                                        \
                for (int nt = 0; nt < 4; nt++) {                                         \
                    uint32_t b0, b1;                                                     \
                    ldb16(sWp, 32, kp0, nt * 8, u, v, b0, b1);                           \
                    mma_f16(acc[nt], a0, a1, a2, a3, b0, b1);                            \
                }                                                                        \
            }                                                                            \
            __syncthreads();                                                             \
        }

        for (int cc = 0; cc < 24; cc += 2) {
            ENC_ITER(cc,     pvA, pvB, sA0, sA1);
            ENC_ITER(cc + 1, pvB, pvA, sA1, sA0);
        }
        #undef ENC_ITER

        // epilogue -> sX0 (half2 words, cols cb..cb+31)
        const int cb2 = ph * 16;   // word offset (32 cols / 2)
        #pragma unroll
        for (int nt = 0; nt < 4; nt++) {
            int kp = cb2 + nt * 4 + v;
            sX0[(r0 + u) * 68 + kp]     = pk(lrelu(acc[nt][0]), lrelu(acc[nt][1]));
            sX0[(r0 + u + 8) * 68 + kp] = pk(lrelu(acc[nt][2]), lrelu(acc[nt][3]));
        }
    }

    // ---- num / cat projections (cols 64-127) ----
    __syncthreads();
    {
        __half* sX0h = (__half*)sX0;
        for (int o = tid; o < 8192; o += 256) {
            int row = o >> 6, c = o & 63;
            int g = node0 + row;
            float vv = 0.f;
            if (g < NN) {
                if (c < 32) {
                    float a = sNC[256 + c];
                    #pragma unroll
                    for (int k = 0; k < 5; k++)
                        a = fmaf(__ldg(numf + (size_t)g * 5 + k), sNC[k * 32 + c], a);
                    vv = lrelu(a);
                } else {
                    int cc = c - 32;
                    float a = sNC[288 + cc];
                    #pragma unroll
                    for (int k = 0; k < 3; k++)
                        a = fmaf(__ldg(catf + (size_t)g * 3 + k), sNC[160 + k * 32 + cc], a);
                    vv = lrelu(a);
                }
            }
            sX0h[row * 136 + 64 + c] = __float2half(vv);
        }
    }
    __syncthreads();

    // ---- W1: out = leaky( x0 @ W1 + b1 ) ----
    {
        float acc[16][4];
        #pragma unroll
        for (int nt = 0; nt < 16; nt++) {
            float2 bv = *(const float2*)(b1 + nt * 8 + 2 * v);
            acc[nt][0] = bv.x; acc[nt][1] = bv.y; acc[nt][2] = bv.x; acc[nt][3] = bv.y;
        }
        #pragma unroll
        for (int ks = 0; ks < 8; ks++) {
            uint32_t a0, a1, a2, a3;
            lda16(sX0, 68, r0 + u, ks * 8, v, a0, a1, a2, a3);
            #pragma unroll
            for (int nt = 0; nt < 16; nt++) {
                uint32_t b0, b1;
                ldb16(sW1, 128, ks * 8, nt * 8, u, v, b0, b1);
                mma_f16(acc[nt], a0, a1, a2, a3, b0, b1);
            }
        }
        int gA = node0 + r0 + u, gB = gA + 8;
        #pragma unroll
        for (int nt = 0; nt < 16; nt++) {
            int col = nt * 8 + 2 * v;
            if (gA < NN) {
                float2 o; o.x = lrelu(acc[nt][0]); o.y = lrelu(acc[nt][1]);
                *(float2*)(out + (size_t)gA * 128 + col) = o;
            }
            if (gB < NN) {
                float2 o; o.x = lrelu(acc[nt][2]); o.y = lrelu(acc[nt][3]);
                *(float2*)(out + (size_t)gB * 128 + col) = o;
            }
        }
    }
}

// ---------------- pull (warp/node, optional LN affine, unroll 4) ----------------
__global__ void pull_kernel(const float* __restrict__ x,
                            const float* __restrict__ scale,
                            const float* __restrict__ shift,
                            int apply) {
    const int w = (blockIdx.x * blockDim.x + threadIdx.x) >> 5;
    const int lane = threadIdx.x & 31;
    if (w >= NN) return;
    float4 sc = make_float4(1.f, 1.f, 1.f, 1.f);
    float4 sh = make_float4(0.f, 0.f, 0.f, 0.f);
    if (apply) {
        sc = __ldg((const float4*)scale + lane);
        sh = __ldg((const float4*)shift + lane);
    }
    const int beg = g_rowptr[w], end = g_rowptr[w + 1];
    const float NEG = -3.0e38f;
    float4 a0 = make_float4(NEG, NEG, NEG, NEG);
    float4 a1 = a0;

    #define PULL_ONE(VE)                                                            \
    {                                                                                \
        float4 f = __ldg((const float4*)(x + (size_t)((VE) & 0x3FFFFFFF) * 128) + lane); \
        f.x = fmaf(f.x, sc.x, sh.x); f.y = fmaf(f.y, sc.y, sh.y);                    \
        f.z = fmaf(f.z, sc.z, sh.z); f.w = fmaf(f.w, sc.w, sh.w);                    \
        if ((VE) >> 30) {                                                            \
            a1.x = fmaxf(a1.x, f.x); a1.y = fmaxf(a1.y, f.y);                        \
            a1.z = fmaxf(a1.z, f.z); a1.w = fmaxf(a1.w, f.w);                        \
        } else {                                                                     \
            a0.x = fmaxf(a0.x, f.x); a0.y = fmaxf(a0.y, f.y);                        \
            a0.z = fmaxf(a0.z, f.z); a0.w = fmaxf(a0.w, f.w);                        \
        }                                                                            \
    }

    int e = beg;
    for (; e + 4 <= end; e += 4) {
        int v0 = g_ebuf[e], v1 = g_ebuf[e + 1], v2 = g_ebuf[e + 2], v3 = g_ebuf[e + 3];
        PULL_ONE(v0); PULL_ONE(v1); PULL_ONE(v2); PULL_ONE(v3);
    }
    for (; e < end; e++) {
        int v0 = g_ebuf[e];
        PULL_ONE(v0);
    }
    #undef PULL_ONE

    float4 o0, o1;
    o0.x = (a0.x == NEG) ? 0.f : a0.x; o0.y = (a0.y == NEG) ? 0.f : a0.y;
    o0.z = (a0.z == NEG) ? 0.f : a0.z; o0.w = (a0.w == NEG) ? 0.f : a0.w;
    o1.x = (a1.x == NEG) ? 0.f : a1.x; o1.y = (a1.y == NEG) ? 0.f : a1.y;
    o1.z = (a1.z == NEG) ? 0.f : a1.z; o1.w = (a1.w == NEG) ? 0.f : a1.w;
    ((float4*)(g_agg + (size_t)w * 128))[lane] = o0;
    ((float4*)(g_agg + (size_t)(NN + w) * 128))[lane] = o1;
}

// ---------------- RGCN GEMM (fp16 mma, persistent, 1 barrier/chunk) ----------------
// smem words: sW 192*128 = 24576 | sA 2*2560
__global__ void __launch_bounds__(256, 1) rgcn_kernel(
    const float* __restrict__ x,
    const float* __restrict__ root,
    const float* __restrict__ relw,
    const float* __restrict__ bias,
    const float* __restrict__ scale,
    const float* __restrict__ shift,
    int apply,
    float* __restrict__ out,
    double* __restrict__ sums)
{
    extern __shared__ uint32_t S[];
    uint32_t* sW = S;             // kp 0..191, pitch 128, swizzled
    uint32_t* sA0 = S + 24576;    // pitch 20, 128 rows
    uint32_t* sA1 = S + 27136;
    __shared__ double sred[2];
    const int tid = threadIdx.x;
    const int lane = tid & 31, warp = tid >> 5;
    const int u = lane >> 2, v = lane & 3;
    const int r0 = warp * 16;
    const int srow = tid >> 3, sc4 = (tid & 7) * 4;
    if (tid < 2) sred[tid] = 0.0;

    // weights once per block: root kp 0..63, relw kp 64..191
    for (int i = tid; i < 2048; i += 256) cvtw(sW, 128, root, 128, i >> 5, (i & 31) * 4);
    for (int i = tid; i < 4096; i += 256)
        cvtw(sW + 64 * 128, 128, relw, 128, i >> 5, (i & 31) * 4);

    for (int tile = blockIdx.x; tile < NTILES; tile += PGRID) {
        const int node0 = tile * 128;
        float acc[16][4];
        #pragma unroll
        for (int nt = 0; nt < 16; nt++) {
            float2 bv = *(const float2*)(bias + nt * 8 + 2 * v);
            acc[nt][0] = bv.x; acc[nt][1] = bv.y; acc[nt][2] = bv.x; acc[nt][3] = bv.y;
        }

        float4 pv[4];
        // prefetch chunk 0
        #pragma unroll
        for (int j = 0; j < 4; j++) {
            int g = node0 + srow + j * 32;
            float4 val = make_float4(0.f, 0.f, 0.f, 0.f);
            if (g < NN) val = __ldg((const float4*)(x + (size_t)g * 128 + sc4));
            if (apply) {
                float4 s4 = __ldg((const float4*)scale + (sc4 >> 2));
                float4 h4 = __ldg((const float4*)shift + (sc4 >> 2));
                val.x = fmaf(val.x, s4.x, h4.x); val.y = fmaf(val.y, s4.y, h4.y);
                val.z = fmaf(val.z, s4.z, h4.z); val.w = fmaf(val.w, s4.w, h4.w);
            }
            pv[j] = val;
        }

        for (int ci = 0; ci < 12; ci++) {
            uint32_t* buf = (ci & 1) ? sA1 : sA0;
            #pragma unroll
            for (int j = 0; j < 4; j++) {
                uint2 w; w.x = pk(pv[j].x, pv[j].y); w.y = pk(pv[j].z, pv[j].w);
                *(uint2*)(buf + (srow + j * 32) * 20 + (sc4 >> 1)) = w;
            }
            if (ci < 11) {
                const int cn = ci + 1;
                const float* ptr = (cn < 4) ? x : ((cn < 8) ? g_agg : g_agg + (size_t)NN * DDIM);
                const int colofs = (cn & 3) * 32;
                const bool tx = (apply != 0) && (cn < 4);
                #pragma unroll
                for (int j = 0; j < 4; j++) {
                    int g = node0 + srow + j * 32;
                    float4 val = make_float4(0.f, 0.f, 0.f, 0.f);
                    if (g < NN) val = __ldg((const float4*)(ptr + (size_t)g * 128 + colofs + sc4));
                    if (tx) {
                        float4 s4 = __ldg((const float4*)scale + ((colofs + sc4) >> 2));
                        float4 h4 = __ldg((const float4*)shift + ((colofs + sc4) >> 2));
                        val.x = fmaf(val.x, s4.x, h4.x); val.y = fmaf(val.y, s4.y, h4.y);
                        val.z = fmaf(val.z, s4.z, h4.z); val.w = fmaf(val.w, s4.w, h4.w);
                    }
                    pv[j] = val;
                }
            }
            __syncthreads();
            #pragma unroll
            for (int ks = 0; ks < 2; ks++) {
                uint32_t a0, a1, a2, a3;
                lda16(buf, 20, r0 + u, ks * 8, v, a0, a1, a2, a3);
                int kp0 = ci * 16 + ks * 8;
                #pragma unroll
                for (int nt = 0; nt < 16; nt++) {
                    uint32_t b0, b1;
                    ldb16(sW, 128, kp0, nt * 8, u, v, b0, b1);
                    mma_f16(acc[nt], a0, a1, a2, a3, b0, b1);
                }
            }
        }

        int gA = node0 + r0 + u, gB = gA + 8;
        float ls = 0.f, lq = 0.f;
        #pragma unroll
        for (int nt = 0; nt < 16; nt++) {
            int col = nt * 8 + 2 * v;
            if (gA < NN) {
                float x0 = acc[nt][0], x1 = acc[nt][1];
                float2 o; o.x = x0; o.y = x1;
                *(float2*)(out + (size_t)gA * 128 + col) = o;
                ls += x0 + x1; lq += x0 * x0 + x1 * x1;
            }
            if (gB < NN) {
                float x0 = acc[nt][2], x1 = acc[nt][3];
                float2 o; o.x = x0; o.y = x1;
                *(float2*)(out + (size_t)gB * 128 + col) = o;
                ls += x0 + x1; lq += x0 * x0 + x1 * x1;
            }
        }
        #pragma unroll
        for (int off = 16; off; off >>= 1) {
            ls += __shfl_down_sync(0xFFFFFFFFu, ls, off);
            lq += __shfl_down_sync(0xFFFFFFFFu, lq, off);
        }
        if (lane == 0) {
            atomicAdd(&sred[0], (double)ls);
            atomicAdd(&sred[1], (double)lq);
        }
        __syncthreads();   // sred writes done; also isolates next tile's staging
    }

    if (tid == 0) {
        atomicAdd(&sums[0], sred[0]);
        atomicAdd(&sums[1], sred[1]);
    }
}

// ---------------- head ----------------
// smem words: sW2 8192 | sX 8704 | sw3 128 floats
__global__ void __launch_bounds__(256, 1) head_kernel(
    const float* __restrict__ x,
    const float* __restrict__ W2,
    const float* __restrict__ b2,
    const float* __restrict__ W3,
    const float* __restrict__ b3,
    const float* __restrict__ scale,
    const float* __restrict__ shift,
    float* __restrict__ out)
{
    extern __shared__ uint32_t S[];
    uint32_t* sW2 = S;
    uint32_t* sX  = S + 8192;     // pitch 68
    float*    sw3 = (float*)(S + 16896);
    const int tid = threadIdx.x;
    const int node0 = blockIdx.x * 128;
    const int lane = tid & 31, warp = tid >> 5;
    const int u = lane >> 2, v = lane & 3;
    const int r0 = warp * 16;

    for (int i = tid; i < 2048; i += 256) cvtw(sW2, 128, W2, 128, i >> 5, (i & 31) * 4);
    for (int i = tid; i < 4096; i += 256) {
        int row = i >> 5, c4 = (i & 31) * 4;
        int g = node0 + row;
        float4 val = make_float4(0.f, 0.f, 0.f, 0.f);
        if (g < NN) {
            val = __ldg((const float4*)(x + (size_t)g * 128 + c4));
            float4 s4 = __ldg((const float4*)scale + (c4 >> 2));
            float4 h4 = __ldg((const float4*)shift + (c4 >> 2));
            val.x = fmaf(val.x, s4.x, h4.x); val.y = fmaf(val.y, s4.y, h4.y);
            val.z = fmaf(val.z, s4.z, h4.z); val.w = fmaf(val.w, s4.w, h4.w);
        }
        uint2 w; w.x = pk(val.x, val.y); w.y = pk(val.z, val.w);
        *(uint2*)(sX + row * 68 + (c4 >> 1)) = w;
    }
    if (tid < 128) sw3[tid] = W3[tid];
    __syncthreads();

    float acc[16][4];
    #pragma unroll
    for (int nt = 0; nt < 16; nt++) {
        float2 bv = *(const float2*)(b2 + nt * 8 + 2 * v);
        acc[nt][0] = bv.x; acc[nt][1] = bv.y; acc[nt][2] = bv.x; acc[nt][3] = bv.y;
    }
    #pragma unroll
    for (int ks = 0; ks < 8; ks++) {
        uint32_t a0, a1, a2, a3;
        lda16(sX, 68, r0 + u, ks * 8, v, a0, a1, a2, a3);
        #pragma unroll
        for (int nt = 0; nt < 16; nt++) {
            uint32_t b0, b1;
            ldb16(sW2, 128, ks * 8, nt * 8, u, v, b0, b1);
            mma_f16(acc[nt], a0, a1, a2, a3, b0, b1);
        }
    }

    float pA = 0.f, pB = 0.f;
    #pragma unroll
    for (int nt = 0; nt < 16; nt++) {
        int col = nt * 8 + 2 * v;
        float w0 = sw3[col], w1 = sw3[col + 1];
        pA += lrelu(acc[nt][0]) * w0 + lrelu(acc[nt][1]) * w1;
        pB += lrelu(acc[nt][2]) * w0 + lrelu(acc[nt][3]) * w1;
    }
    pA += __shfl_xor_sync(0xFFFFFFFFu, pA, 1);
    pA += __shfl_xor_sync(0xFFFFFFFFu, pA, 2);
    pB += __shfl_xor_sync(0xFFFFFFFFu, pB, 1);
    pB += __shfl_xor_sync(0xFFFFFFFFu, pB, 2);
    if (v == 0) {
        float b3v = __ldg(b3);
        int gA = node0 + r0 + u;
        if (gA < NN) out[gA] = 1.f / (1.f + expf(-(pA + b3v)));
        int gB = gA + 8;
        if (gB < NN) out[gB] = 1.f / (1.f + expf(-(pB + b3v)));
    }
}

// ---------------- launch ----------------
extern "C" void kernel_launch(void* const* d_in, const int* in_sizes, int n_in,
                              void* d_out, int out_size)
{
    const float* desc  = (const float*)d_in[0];
    const float* tweet = (const float*)d_in[1];
    const float* numf  = (const float*)d_in[2];
    const float* catf  = (const float*)d_in[3];
    const int*   ei    = (const int*)d_in[4];
    const int*   et    = (const int*)d_in[5];
    const float* Wd = (const float*)d_in[6];  const float* bd = (const float*)d_in[7];
    const float* Wt = (const float*)d_in[8];  const float* bt = (const float*)d_in[9];
    const float* Wn = (const float*)d_in[10]; const float* bn = (const float*)d_in[11];
    const float* Wc = (const float*)d_in[12]; const float* bc = (const float*)d_in[13];
    const float* W1 = (const float*)d_in[14]; const float* b1 = (const float*)d_in[15];
    const float* rg1_w    = (const float*)d_in[16];
    const float* rg1_root = (const float*)d_in[17];
    const float* rg1_bias = (const float*)d_in[18];
    const float* ln1_g = (const float*)d_in[19]; const float* ln1_b = (const float*)d_in[20];
    const float* rg2_w    = (const float*)d_in[21];
    const float* rg2_root = (const float*)d_in[22];
    const float* rg2_bias = (const float*)d_in[23];
    const float* ln2_g = (const float*)d_in[24]; const float* ln2_b = (const float*)d_in[25];
    const float* W2 = (const float*)d_in[26]; const float* b2 = (const float*)d_in[27];
    const float* W3 = (const float*)d_in[28]; const float* b3 = (const float*)d_in[29];

    float *xa, *xb, *sc1, *sh1, *sc2, *sh2;
    double* sums;
    cudaGetSymbolAddress((void**)&xa, g_xa);
    cudaGetSymbolAddress((void**)&xb, g_xb);
    cudaGetSymbolAddress((void**)&sums, g_sums);
    cudaGetSymbolAddress((void**)&sc1, g_sc1);
    cudaGetSymbolAddress((void**)&sh1, g_sh1);
    cudaGetSymbolAddress((void**)&sc2, g_sc2);
    cudaGetSymbolAddress((void**)&sh2, g_sh2);

    const int SM_ENC  = 46912 * 4;            // 187648
    const int SM_RGCN = (24576 + 5120) * 4;   // 118784
    const int SM_HEAD = 17024 * 4;            // 68096
    cudaFuncSetAttribute(encode_kernel, cudaFuncAttributeMaxDynamicSharedMemorySize, SM_ENC);
    cudaFuncSetAttribute(rgcn_kernel,   cudaFuncAttributeMaxDynamicSharedMemorySize, SM_RGCN);
    cudaFuncSetAttribute(head_kernel,   cudaFuncAttributeMaxDynamicSharedMemorySize, SM_HEAD);

    init_kernel<<<(NN + 255) / 256, 256>>>();
    hist_kernel<<<(EE + 255) / 256, 256>>>(ei);
    scan_kernel<<<1, 1024>>>();
    fill_kernel<<<(EE + 255) / 256, 256>>>(ei, et);

    encode_kernel<<<NTILES, 256, SM_ENC>>>(desc, tweet, numf, catf,
                                           Wd, bd, Wt, bt, Wn, bn, Wc, bc,
                                           W1, b1, xa);

    pull_kernel<<<(NN + 7) / 8, 256>>>(xa, sc1, sh1, 0);
    rgcn_kernel<<<PGRID, 256, SM_RGCN>>>(xa, rg1_root, rg1_w, rg1_bias,
                                         sc1, sh1, 0, xb, sums + 0);
    fin_kernel<<<1, 128>>>(sums + 0, ln1_g, ln1_b, sc1, sh1);

    pull_kernel<<<(NN + 7) / 8, 256>>>(xb, sc1, sh1, 1);
    rgcn_kernel<<<PGRID, 256, SM_RGCN>>>(xb, rg2_root, rg2_w, rg2_bias,
                                         sc1, sh1, 1, xa, sums + 2);
    fin_kernel<<<1, 128>>>(sums + 2, ln2_g, ln2_b, sc2, sh2);

    head_kernel<<<NTILES, 256, SM_HEAD>>>(xa, W2, b2, W3, b3, sc2, sh2, (float*)d_out);
}

// round 6
// speedup vs baseline: 2.2029x; 1.1989x over previous
#include <cuda_runtime.h>
#include <cuda_fp16.h>
#include <math.h>
#include <stdint.h>

#define NN 50000
#define EE 600000
#define DDIM 128
#define NTILES ((NN + 127) / 128)   // 391
#define PGRID 148
#define NSB ((NN + 255) / 256)      // 196

// ---------------- scratch ----------------
__device__ uint32_t g_xah[(size_t)NN * 64];    // fp16 x (encode out / rgcn2 out)
__device__ uint32_t g_xbh[(size_t)NN * 64];    // fp16 rgcn1 out
__device__ uint32_t g_aggh[(size_t)2 * NN * 64];
__device__ int    g_deg[NN];
__device__ int    g_tmp[NN];
__device__ int    g_bsum[NSB];
__device__ int    g_rowptr[NN + 1];
__device__ int    g_cur[NN];
__device__ int    g_ebuf[EE];
__device__ double g_sums[4];
__device__ float  g_sc1[DDIM], g_sh1[DDIM];
__device__ float  g_sc2[DDIM], g_sh2[DDIM];

__device__ __forceinline__ float lrelu(float x) { return x > 0.f ? x : 0.01f * x; }

__device__ __forceinline__ uint32_t pk(float a, float b) {
    __half2 h = __floats2half2_rn(a, b);
    return *reinterpret_cast<uint32_t*>(&h);
}
__device__ __forceinline__ float2 upk(uint32_t w) {
    __half2 h = *reinterpret_cast<__half2*>(&w);
    return __half22float2(h);
}
__device__ __forceinline__ uint32_t aff(uint32_t w, float2 s, float2 h) {
    float2 f = upk(w);
    return pk(fmaf(f.x, s.x, h.x), fmaf(f.y, s.y, h.y));
}

// fp16 mma m16n8k16, fp32 accum
__device__ __forceinline__ void mma_f16(float c[4], uint32_t a0, uint32_t a1,
                                        uint32_t a2, uint32_t a3,
                                        uint32_t b0, uint32_t b1) {
    asm volatile(
        "mma.sync.aligned.m16n8k16.row.col.f32.f16.f16.f32 "
        "{%0,%1,%2,%3},{%4,%5,%6,%7},{%8,%9},{%0,%1,%2,%3};"
        : "+f"(c[0]), "+f"(c[1]), "+f"(c[2]), "+f"(c[3])
        : "r"(a0), "r"(a1), "r"(a2), "r"(a3), "r"(b0), "r"(b1));
}

// A fragment from half2-word smem [row][kp], pitch P words. kp0 % 8 == 0.
__device__ __forceinline__ void lda16(const uint32_t* sA, int P, int row, int kp0, int v,
                                      uint32_t& a0, uint32_t& a1, uint32_t& a2, uint32_t& a3) {
    const uint32_t* p = sA + row * P + kp0 + v;
    a0 = p[0]; a1 = p[8 * P]; a2 = p[4]; a3 = p[8 * P + 4];
}

// B fragment from half2-word smem [kp][n ^ ((kp&3)<<3)], pitch P words. kp0 % 8 == 0.
__device__ __forceinline__ void ldb16(const uint32_t* sW, int P, int kp0, int n0, int u, int v,
                                      uint32_t& b0, uint32_t& b1) {
    int col = (n0 + u) ^ (v << 3);
    b0 = sW[(kp0 + v) * P + col];
    b1 = sW[(kp0 + v + 4) * P + col];
}

// convert weight rows 2kp,2kp+1 cols n4..n4+3 into 4 half2 words, swizzled store
__device__ __forceinline__ void cvtw(uint32_t* sW, int P, const float* W, int N, int kp, int n4) {
    float4 f0 = __ldg((const float4*)(W + (size_t)(2 * kp) * N + n4));
    float4 f1 = __ldg((const float4*)(W + (size_t)(2 * kp + 1) * N + n4));
    uint4 w;
    w.x = pk(f0.x, f1.x); w.y = pk(f0.y, f1.y);
    w.z = pk(f0.z, f1.z); w.w = pk(f0.w, f1.w);
    *(uint4*)(sW + kp * P + (n4 ^ ((kp & 3) << 3))) = w;
}

// ---------------- setup kernels ----------------
__global__ void init_kernel() {
    int i = blockIdx.x * blockDim.x + threadIdx.x;
    if (i < NN) g_deg[i] = 0;
    if (i < 4) g_sums[i] = 0.0;
}

__global__ void hist_kernel(const int* __restrict__ ei) {
    int e = blockIdx.x * blockDim.x + threadIdx.x;
    if (e < EE) atomicAdd(&g_deg[ei[EE + e]], 1);
}

// parallel scan: s1 local inclusive scan + block sums
__global__ void s1_kernel() {
    __shared__ int ws[8];
    const int tid = threadIdx.x, b = blockIdx.x;
    const int lane = tid & 31, wid = tid >> 5;
    int i = b * 256 + tid;
    int v = (i < NN) ? g_deg[i] : 0;
    int x = v;
    #pragma unroll
    for (int o = 1; o < 32; o <<= 1) {
        int y = __shfl_up_sync(0xFFFFFFFFu, x, o);
        if (lane >= o) x += y;
    }
    if (lane == 31) ws[wid] = x;
    __syncthreads();
    if (wid == 0) {
        int s = (lane < 8) ? ws[lane] : 0;
        #pragma unroll
        for (int o = 1; o < 8; o <<= 1) {
            int y = __shfl_up_sync(0xFFFFFFFFu, s, o);
            if (lane >= o) s += y;
        }
        if (lane < 8) ws[lane] = s;
    }
    __syncthreads();
    int incl = x + (wid > 0 ? ws[wid - 1] : 0);
    if (i < NN) g_tmp[i] = incl;
    if (tid == 255) g_bsum[b] = incl;
}

// s2: exclusive scan of block sums (single block)
__global__ void s2_kernel() {
    __shared__ int ws[8];
    const int tid = threadIdx.x;
    const int lane = tid & 31, wid = tid >> 5;
    int v = (tid < NSB) ? g_bsum[tid] : 0;
    int x = v;
    #pragma unroll
    for (int o = 1; o < 32; o <<= 1) {
        int y = __shfl_up_sync(0xFFFFFFFFu, x, o);
        if (lane >= o) x += y;
    }
    if (lane == 31) ws[wid] = x;
    __syncthreads();
    if (wid == 0) {
        int s = (lane < 8) ? ws[lane] : 0;
        #pragma unroll
        for (int o = 1; o < 8; o <<= 1) {
            int y = __shfl_up_sync(0xFFFFFFFFu, s, o);
            if (lane >= o) s += y;
        }
        if (lane < 8) ws[lane] = s;
    }
    __syncthreads();
    int incl = x + (wid > 0 ? ws[wid - 1] : 0);
    if (tid < NSB) g_bsum[tid] = incl - v;   // exclusive
}

// s3: apply offsets -> rowptr, cur
__global__ void s3_kernel() {
    const int b = blockIdx.x, tid = threadIdx.x;
    int i = b * 256 + tid;
    if (i < NN) {
        int r = g_tmp[i] + g_bsum[b];
        g_rowptr[i + 1] = r;
        g_cur[i] = r - g_deg[i];
    }
    if (i == 0) g_rowptr[0] = 0;
}

__global__ void fill_kernel(const int* __restrict__ ei, const int* __restrict__ et) {
    int e = blockIdx.x * blockDim.x + threadIdx.x;
    if (e >= EE) return;
    int src = ei[e];
    int dst = ei[EE + e];
    int pos = atomicAdd(&g_cur[dst], 1);
    g_ebuf[pos] = src | (et[e] << 30);
}

__global__ void fin_kernel(const double* __restrict__ s,
                           const float* __restrict__ g,
                           const float* __restrict__ b,
                           float* __restrict__ scale,
                           float* __restrict__ shift) {
    int c = threadIdx.x;
    const double cnt = (double)NN * DDIM;
    double mu = s[0] / cnt;
    double var = s[1] / cnt - mu * mu;
    float rstd = (float)(1.0 / sqrt(var + 1e-5));
    float sc = rstd * g[c];
    scale[c] = sc;
    shift[c] = b[c] - (float)mu * sc;
}

// ---------------- encode ----------------
// smem (uint32 words): sWd 12288 | sWt 12288 | sW1 8192 | sX0 128*68 | sA0 2560 | sA1 2560 | sNC 320
__global__ void __launch_bounds__(256, 1) encode_kernel(
    const float* __restrict__ desc, const float* __restrict__ tweet,
    const float* __restrict__ numf, const float* __restrict__ catf,
    const float* __restrict__ Wd, const float* __restrict__ bd,
    const float* __restrict__ Wt, const float* __restrict__ bt,
    const float* __restrict__ Wn, const float* __restrict__ bn,
    const float* __restrict__ Wc, const float* __restrict__ bc,
    const float* __restrict__ W1, const float* __restrict__ b1,
    uint32_t* __restrict__ outh)
{
    extern __shared__ uint32_t S[];
    uint32_t* sWd = S;
    uint32_t* sWt = S + 12288;
    uint32_t* sW1 = S + 24576;
    uint32_t* sX0 = S + 32768;     // pitch 68 words, 128 rows
    uint32_t* sA0 = S + 41472;     // pitch 20 words, 128 rows
    uint32_t* sA1 = S + 44032;
    float*    sNC = (float*)(S + 46592);

    const int tid = threadIdx.x;
    const int node0 = blockIdx.x * 128;
    const int lane = tid & 31, warp = tid >> 5;
    const int u = lane >> 2, v = lane & 3;
    const int r0 = warp * 16;
    const int srow = tid >> 3, sc4 = (tid & 7) * 4;

    for (int i = tid; i < 3072; i += 256) cvtw(sWd, 32, Wd, 32, i >> 3, (i & 7) * 4);
    for (int i = tid; i < 3072; i += 256) cvtw(sWt, 32, Wt, 32, i >> 3, (i & 7) * 4);
    for (int i = tid; i < 2048; i += 256) cvtw(sW1, 128, W1, 128, i >> 5, (i & 31) * 4);
    if (tid < 160) sNC[tid] = Wn[tid];
    if (tid < 96)  sNC[160 + tid] = Wc[tid];
    if (tid < 32)  { sNC[256 + tid] = bn[tid]; sNC[288 + tid] = bc[tid]; }

    for (int ph = 0; ph < 2; ph++) {
        const float* In = ph ? tweet : desc;
        const float* B  = ph ? bt : bd;
        const uint32_t* sWp = ph ? sWt : sWd;

        float acc[4][4];
        #pragma unroll
        for (int nt = 0; nt < 4; nt++) {
            float2 bv = *(const float2*)(B + nt * 8 + 2 * v);
            acc[nt][0] = bv.x; acc[nt][1] = bv.y; acc[nt][2] = bv.x; acc[nt][3] = bv.y;
        }

        float4 pvA[4], pvB[4];
        #pragma unroll
        for (int j = 0; j < 4; j++) {
            int g = node0 + srow + j * 32;
            pvA[j] = make_float4(0.f, 0.f, 0.f, 0.f);
            pvB[j] = make_float4(0.f, 0.f, 0.f, 0.f);
            if (g < NN) {
                pvA[j] = __ldg((const float4*)(In + (size_t)g * 768 + sc4));
                pvB[j] = __ldg((const float4*)(In + (size_t)g * 768 + 32 + sc4));
            }
        }
        #pragma unroll
        for (int j = 0; j < 4; j++) {
            uint2 w; w.x = pk(pvA[j].x, pvA[j].y); w.y = pk(pvA[j].z, pvA[j].w);
            *(uint2*)(sA0 + (srow + j * 32) * 20 + (sc4 >> 1)) = w;
        }
        __syncthreads();

        #define ENC_ITER(CI, PVL, PVS, SRC, DST)                                        \
        {                                                                                \
            if ((CI) + 2 < 24) {                                                         \
                _Pragma("unroll")                                                        \
                for (int j = 0; j < 4; j++) {                                            \
                    int g = node0 + srow + j * 32;                                       \
                    PVL[j] = make_float4(0.f, 0.f, 0.f, 0.f);                            \
                    if (g < NN)                                                          \
                        PVL[j] = __ldg((const float4*)(In + (size_t)g * 768              \
                                                       + ((CI) + 2) * 32 + sc4));        \
                }                                                                        \
            }                                                                            \
            if ((CI) + 1 < 24) {                                                         \
                _Pragma("unroll")                                                        \
                for (int j = 0; j < 4; j++) {                                            \
                    uint2 w; w.x = pk(PVS[j].x, PVS[j].y); w.y = pk(PVS[j].z, PVS[j].w); \
                    *(uint2*)((DST) + (srow + j * 32) * 20 + (sc4 >> 1)) = w;            \
                }                                                                        \
            }                                                                            \
            _Pragma("unroll")                                                            \
            for (int ks = 0; ks < 2; ks++) {                                             \
                uint32_t a0, a1, a2, a3;                                                 \
                lda16((SRC), 20, r0 + u, ks * 8, v, a0, a1, a2, a3);                     \
                int kp0 = (CI) * 16 + ks * 8;                                            \
                _Pragma("unroll")                                                        \
                for (int nt = 0; nt < 4; nt++) {                                         \
                    uint32_t b0, b1;                                                     \
                    ldb16(sWp, 32, kp0, nt * 8, u, v, b0, b1);                           \
                    mma_f16(acc[nt], a0, a1, a2, a3, b0, b1);                            \
                }                                                                        \
            }                                                                            \
            __syncthreads();                                                             \
        }

        for (int cc = 0; cc < 24; cc += 2) {
            ENC_ITER(cc,     pvA, pvB, sA0, sA1);
            ENC_ITER(cc + 1, pvB, pvA, sA1, sA0);
        }
        #undef ENC_ITER

        const int cb2 = ph * 16;
        #pragma unroll
        for (int nt = 0; nt < 4; nt++) {
            int kp = cb2 + nt * 4 + v;
            sX0[(r0 + u) * 68 + kp]     = pk(lrelu(acc[nt][0]), lrelu(acc[nt][1]));
            sX0[(r0 + u + 8) * 68 + kp] = pk(lrelu(acc[nt][2]), lrelu(acc[nt][3]));
        }
    }

    // num / cat projections (cols 64-127)
    __syncthreads();
    {
        __half* sX0h = (__half*)sX0;
        for (int o = tid; o < 8192; o += 256) {
            int row = o >> 6, c = o & 63;
            int g = node0 + row;
            float vv = 0.f;
            if (g < NN) {
                if (c < 32) {
                    float a = sNC[256 + c];
                    #pragma unroll
                    for (int k = 0; k < 5; k++)
                        a = fmaf(__ldg(numf + (size_t)g * 5 + k), sNC[k * 32 + c], a);
                    vv = lrelu(a);
                } else {
                    int cc = c - 32;
                    float a = sNC[288 + cc];
                    #pragma unroll
                    for (int k = 0; k < 3; k++)
                        a = fmaf(__ldg(catf + (size_t)g * 3 + k), sNC[160 + k * 32 + cc], a);
                    vv = lrelu(a);
                }
            }
            sX0h[row * 136 + 64 + c] = __float2half(vv);
        }
    }
    __syncthreads();

    // W1: out = leaky( x0 @ W1 + b1 ), write fp16 packed
    {
        float acc[16][4];
        #pragma unroll
        for (int nt = 0; nt < 16; nt++) {
            float2 bv = *(const float2*)(b1 + nt * 8 + 2 * v);
            acc[nt][0] = bv.x; acc[nt][1] = bv.y; acc[nt][2] = bv.x; acc[nt][3] = bv.y;
        }
        #pragma unroll
        for (int ks = 0; ks < 8; ks++) {
            uint32_t a0, a1, a2, a3;
            lda16(sX0, 68, r0 + u, ks * 8, v, a0, a1, a2, a3);
            #pragma unroll
            for (int nt = 0; nt < 16; nt++) {
                uint32_t b0, b1;
                ldb16(sW1, 128, ks * 8, nt * 8, u, v, b0, b1);
                mma_f16(acc[nt], a0, a1, a2, a3, b0, b1);
            }
        }
        int gA = node0 + r0 + u, gB = gA + 8;
        #pragma unroll
        for (int nt = 0; nt < 16; nt++) {
            int wofs = nt * 4 + v;
            if (gA < NN)
                outh[(size_t)gA * 64 + wofs] = pk(lrelu(acc[nt][0]), lrelu(acc[nt][1]));
            if (gB < NN)
                outh[(size_t)gB * 64 + wofs] = pk(lrelu(acc[nt][2]), lrelu(acc[nt][3]));
        }
    }
}

// ---------------- pull (fp16 gather, warp/node, optional LN affine, unroll 4) ----------------
__global__ void pull_kernel(const uint32_t* __restrict__ xh,
                            const float* __restrict__ scale,
                            const float* __restrict__ shift,
                            int apply) {
    const int w = (blockIdx.x * blockDim.x + threadIdx.x) >> 5;
    const int lane = threadIdx.x & 31;
    if (w >= NN) return;
    float4 sc = make_float4(1.f, 1.f, 1.f, 1.f);
    float4 sh = make_float4(0.f, 0.f, 0.f, 0.f);
    if (apply) {
        sc = __ldg((const float4*)scale + lane);
        sh = __ldg((const float4*)shift + lane);
    }
    const int beg = g_rowptr[w], end = g_rowptr[w + 1];
    const float NEG = -3.0e38f;
    float4 a0 = make_float4(NEG, NEG, NEG, NEG);
    float4 a1 = a0;

    #define PULL_ONE(VE)                                                             \
    {                                                                                 \
        uint2 d = __ldg((const uint2*)(xh + (size_t)((VE) & 0x3FFFFFFF) * 64) + lane);\
        float2 fx = upk(d.x), fy = upk(d.y);                                          \
        float4 f;                                                                     \
        f.x = fmaf(fx.x, sc.x, sh.x); f.y = fmaf(fx.y, sc.y, sh.y);                   \
        f.z = fmaf(fy.x, sc.z, sh.z); f.w = fmaf(fy.y, sc.w, sh.w);                   \
        if ((VE) >> 30) {                                                             \
            a1.x = fmaxf(a1.x, f.x); a1.y = fmaxf(a1.y, f.y);                         \
            a1.z = fmaxf(a1.z, f.z); a1.w = fmaxf(a1.w, f.w);                         \
        } else {                                                                      \
            a0.x = fmaxf(a0.x, f.x); a0.y = fmaxf(a0.y, f.y);                         \
            a0.z = fmaxf(a0.z, f.z); a0.w = fmaxf(a0.w, f.w);                         \
        }                                                                             \
    }

    int e = beg;
    for (; e + 4 <= end; e += 4) {
        int v0 = g_ebuf[e], v1 = g_ebuf[e + 1], v2 = g_ebuf[e + 2], v3 = g_ebuf[e + 3];
        PULL_ONE(v0); PULL_ONE(v1); PULL_ONE(v2); PULL_ONE(v3);
    }
    for (; e < end; e++) { int v0 = g_ebuf[e]; PULL_ONE(v0); }
    #undef PULL_ONE

    uint2 o0, o1;
    o0.x = pk((a0.x == NEG) ? 0.f : a0.x, (a0.y == NEG) ? 0.f : a0.y);
    o0.y = pk((a0.z == NEG) ? 0.f : a0.z, (a0.w == NEG) ? 0.f : a0.w);
    o1.x = pk((a1.x == NEG) ? 0.f : a1.x, (a1.y == NEG) ? 0.f : a1.y);
    o1.y = pk((a1.z == NEG) ? 0.f : a1.z, (a1.w == NEG) ? 0.f : a1.w);
    ((uint2*)(g_aggh + (size_t)w * 64))[lane] = o0;
    ((uint2*)(g_aggh + (size_t)(NN + w) * 64))[lane] = o1;
}

// ---------------- RGCN GEMM (fp16 mma, persistent, direct-LDG A, no tile barriers) ----------
// smem words: sW 192*128 = 24576
__global__ void __launch_bounds__(256, 1) rgcn_kernel(
    const uint32_t* __restrict__ xh,
    const float* __restrict__ root,
    const float* __restrict__ relw,
    const float* __restrict__ bias,
    const float* __restrict__ scale,
    const float* __restrict__ shift,
    int apply,
    uint32_t* __restrict__ outh,
    double* __restrict__ sums)
{
    extern __shared__ uint32_t S[];
    uint32_t* sW = S;             // kp 0..191, pitch 128, swizzled
    __shared__ double sred[2];
    const int tid = threadIdx.x;
    const int lane = tid & 31, warp = tid >> 5;
    const int u = lane >> 2, v = lane & 3;
    const int r0 = warp * 16;
    if (tid < 2) sred[tid] = 0.0;

    for (int i = tid; i < 2048; i += 256) cvtw(sW, 128, root, 128, i >> 5, (i & 31) * 4);
    for (int i = tid; i < 4096; i += 256)
        cvtw(sW + 64 * 128, 128, relw, 128, i >> 5, (i & 31) * 4);
    __syncthreads();

    for (int tile = blockIdx.x; tile < NTILES; tile += PGRID) {
        const int node0 = tile * 128;
        const int gA = node0 + r0 + u, gB = gA + 8;
        const bool okA = gA < NN, okB = gB < NN;

        float acc[16][4];
        #pragma unroll
        for (int nt = 0; nt < 16; nt++) {
            float2 bv = *(const float2*)(bias + nt * 8 + 2 * v);
            acc[nt][0] = bv.x; acc[nt][1] = bv.y; acc[nt][2] = bv.x; acc[nt][3] = bv.y;
        }

        // fragment loader for step s (0..23)
        #define LOAD_FRAG(S_, F_)                                                      \
        {                                                                               \
            int part = (S_) >> 3;                                                       \
            const uint32_t* base = (part == 0) ? xh : g_aggh;                           \
            size_t ofs = (part == 2) ? (size_t)NN * 64 : 0;                             \
            int w0 = (((S_) & 7) << 3) + v;                                             \
            F_[0] = okA ? __ldg(base + ofs + (size_t)gA * 64 + w0)     : 0u;            \
            F_[2] = okA ? __ldg(base + ofs + (size_t)gA * 64 + w0 + 4) : 0u;            \
            F_[1] = okB ? __ldg(base + ofs + (size_t)gB * 64 + w0)     : 0u;            \
            F_[3] = okB ? __ldg(base + ofs + (size_t)gB * 64 + w0 + 4) : 0u;            \
            if (apply && part == 0) {                                                   \
                float2 s0 = __ldg((const float2*)scale + w0);                           \
                float2 h0 = __ldg((const float2*)shift + w0);                           \
                float2 s1 = __ldg((const float2*)scale + w0 + 4);                       \
                float2 h1 = __ldg((const float2*)shift + w0 + 4);                       \
                F_[0] = aff(F_[0], s0, h0); F_[1] = aff(F_[1], s0, h0);                 \
                F_[2] = aff(F_[2], s1, h1); F_[3] = aff(F_[3], s1, h1);                 \
            }                                                                           \
        }

        uint32_t cf[4];
        LOAD_FRAG(0, cf);
        #pragma unroll
        for (int s = 0; s < 24; s++) {
            uint32_t nf[4];
            if (s < 23) LOAD_FRAG(s + 1, nf);
            #pragma unroll
            for (int nt = 0; nt < 16; nt++) {
                uint32_t b0, b1;
                ldb16(sW, 128, s * 8, nt * 8, u, v, b0, b1);
                mma_f16(acc[nt], cf[0], cf[1], cf[2], cf[3], b0, b1);
            }
            if (s < 23) { cf[0] = nf[0]; cf[1] = nf[1]; cf[2] = nf[2]; cf[3] = nf[3]; }
        }
        #undef LOAD_FRAG

        float ls = 0.f, lq = 0.f;
        #pragma unroll
        for (int nt = 0; nt < 16; nt++) {
            int wofs = nt * 4 + v;
            if (okA) {
                float x0 = acc[nt][0], x1 = acc[nt][1];
                outh[(size_t)gA * 64 + wofs] = pk(x0, x1);
                ls += x0 + x1; lq += x0 * x0 + x1 * x1;
            }
            if (okB) {
                float x0 = acc[nt][2], x1 = acc[nt][3];
                outh[(size_t)gB * 64 + wofs] = pk(x0, x1);
                ls += x0 + x1; lq += x0 * x0 + x1 * x1;
            }
        }
        #pragma unroll
        for (int off = 16; off; off >>= 1) {
            ls += __shfl_down_sync(0xFFFFFFFFu, ls, off);
            lq += __shfl_down_sync(0xFFFFFFFFu, lq, off);
        }
        if (lane == 0) {
            atomicAdd(&sred[0], (double)ls);
            atomicAdd(&sred[1], (double)lq);
        }
    }

    __syncthreads();
    if (tid == 0) {
        atomicAdd(&sums[0], sred[0]);
        atomicAdd(&sums[1], sred[1]);
    }
}

// ---------------- head (direct-LDG A with LN affine) ----------------
// smem words: sW2 8192 | sw3 128 floats
__global__ void __launch_bounds__(256, 1) head_kernel(
    const uint32_t* __restrict__ xh,
    const float* __restrict__ W2,
    const float* __restrict__ b2,
    const float* __restrict__ W3,
    const float* __restrict__ b3,
    const float* __restrict__ scale,
    const float* __restrict__ shift,
    float* __restrict__ out)
{
    extern __shared__ uint32_t S[];
    uint32_t* sW2 = S;
    float*    sw3 = (float*)(S + 8192);
    const int tid = threadIdx.x;
    const int node0 = blockIdx.x * 128;
    const int lane = tid & 31, warp = tid >> 5;
    const int u = lane >> 2, v = lane & 3;
    const int r0 = warp * 16;

    for (int i = tid; i < 2048; i += 256) cvtw(sW2, 128, W2, 128, i >> 5, (i & 31) * 4);
    if (tid < 128) sw3[tid] = W3[tid];
    __syncthreads();

    const int gA = node0 + r0 + u, gB = gA + 8;
    const bool okA = gA < NN, okB = gB < NN;

    float acc[16][4];
    #pragma unroll
    for (int nt = 0; nt < 16; nt++) {
        float2 bv = *(const float2*)(b2 + nt * 8 + 2 * v);
        acc[nt][0] = bv.x; acc[nt][1] = bv.y; acc[nt][2] = bv.x; acc[nt][3] = bv.y;
    }
    #pragma unroll
    for (int s = 0; s < 8; s++) {
        int w0 = s * 8 + v;
        uint32_t f0 = okA ? __ldg(xh + (size_t)gA * 64 + w0)     : 0u;
        uint32_t f2 = okA ? __ldg(xh + (size_t)gA * 64 + w0 + 4) : 0u;
        uint32_t f1 = okB ? __ldg(xh + (size_t)gB * 64 + w0)     : 0u;
        uint32_t f3 = okB ? __ldg(xh + (size_t)gB * 64 + w0 + 4) : 0u;
        float2 s0 = __ldg((const float2*)scale + w0), h0 = __ldg((const float2*)shift + w0);
        float2 s1 = __ldg((const float2*)scale + w0 + 4), h1 = __ldg((const float2*)shift + w0 + 4);
        f0 = aff(f0, s0, h0); f1 = aff(f1, s0, h0);
        f2 = aff(f2, s1, h1); f3 = aff(f3, s1, h1);
        #pragma unroll
        for (int nt = 0; nt < 16; nt++) {
            uint32_t b0, b1;
            ldb16(sW2, 128, s * 8, nt * 8, u, v, b0, b1);
            mma_f16(acc[nt], f0, f1, f2, f3, b0, b1);
        }
    }

    float pA = 0.f, pB = 0.f;
    #pragma unroll
    for (int nt = 0; nt < 16; nt++) {
        int col = nt * 8 + 2 * v;
        float w0 = sw3[col], w1 = sw3[col + 1];
        pA += lrelu(acc[nt][0]) * w0 + lrelu(acc[nt][1]) * w1;
        pB += lrelu(acc[nt][2]) * w0 + lrelu(acc[nt][3]) * w1;
    }
    pA += __shfl_xor_sync(0xFFFFFFFFu, pA, 1);
    pA += __shfl_xor_sync(0xFFFFFFFFu, pA, 2);
    pB += __shfl_xor_sync(0xFFFFFFFFu, pB, 1);
    pB += __shfl_xor_sync(0xFFFFFFFFu, pB, 2);
    if (v == 0) {
        float b3v = __ldg(b3);
        if (okA) out[gA] = 1.f / (1.f + expf(-(pA + b3v)));
        if (okB) out[gB] = 1.f / (1.f + expf(-(pB + b3v)));
    }
}

// ---------------- launch ----------------
extern "C" void kernel_launch(void* const* d_in, const int* in_sizes, int n_in,
                              void* d_out, int out_size)
{
    const float* desc  = (const float*)d_in[0];
    const float* tweet = (const float*)d_in[1];
    const float* numf  = (const float*)d_in[2];
    const float* catf  = (const float*)d_in[3];
    const int*   ei    = (const int*)d_in[4];
    const int*   et    = (const int*)d_in[5];
    const float* Wd = (const float*)d_in[6];  const float* bd = (const float*)d_in[7];
    const float* Wt = (const float*)d_in[8];  const float* bt = (const float*)d_in[9];
    const float* Wn = (const float*)d_in[10]; const float* bn = (const float*)d_in[11];
    const float* Wc = (const float*)d_in[12]; const float* bc = (const float*)d_in[13];
    const float* W1 = (const float*)d_in[14]; const float* b1 = (const float*)d_in[15];
    const float* rg1_w    = (const float*)d_in[16];
    const float* rg1_root = (const float*)d_in[17];
    const float* rg1_bias = (const float*)d_in[18];
    const float* ln1_g = (const float*)d_in[19]; const float* ln1_b = (const float*)d_in[20];
    const float* rg2_w    = (const float*)d_in[21];
    const float* rg2_root = (const float*)d_in[22];
    const float* rg2_bias = (const float*)d_in[23];
    const float* ln2_g = (const float*)d_in[24]; const float* ln2_b = (const float*)d_in[25];
    const float* W2 = (const float*)d_in[26]; const float* b2 = (const float*)d_in[27];
    const float* W3 = (const float*)d_in[28]; const float* b3 = (const float*)d_in[29];

    uint32_t *xah, *xbh;
    float *sc1, *sh1, *sc2, *sh2;
    double* sums;
    cudaGetSymbolAddress((void**)&xah, g_xah);
    cudaGetSymbolAddress((void**)&xbh, g_xbh);
    cudaGetSymbolAddress((void**)&sums, g_sums);
    cudaGetSymbolAddress((void**)&sc1, g_sc1);
    cudaGetSymbolAddress((void**)&sh1, g_sh1);
    cudaGetSymbolAddress((void**)&sc2, g_sc2);
    cudaGetSymbolAddress((void**)&sh2, g_sh2);

    const int SM_ENC  = 46912 * 4;          // 187648
    const int SM_RGCN = 24576 * 4;          // 98304
    const int SM_HEAD = (8192 + 128) * 4;   // 33280
    cudaFuncSetAttribute(encode_kernel, cudaFuncAttributeMaxDynamicSharedMemorySize, SM_ENC);
    cudaFuncSetAttribute(rgcn_kernel,   cudaFuncAttributeMaxDynamicSharedMemorySize, SM_RGCN);
    cudaFuncSetAttribute(head_kernel,   cudaFuncAttributeMaxDynamicSharedMemorySize, SM_HEAD);

    init_kernel<<<(NN + 255) / 256, 256>>>();
    hist_kernel<<<(EE + 255) / 256, 256>>>(ei);
    s1_kernel<<<NSB, 256>>>();
    s2_kernel<<<1, 256>>>();
    s3_kernel<<<NSB, 256>>>();
    fill_kernel<<<(EE + 255) / 256, 256>>>(ei, et);

    encode_kernel<<<NTILES, 256, SM_ENC>>>(desc, tweet, numf, catf,
                                           Wd, bd, Wt, bt, Wn, bn, Wc, bc,
                                           W1, b1, xah);

    pull_kernel<<<(NN + 7) / 8, 256>>>(xah, sc1, sh1, 0);
    rgcn_kernel<<<PGRID, 256, SM_RGCN>>>(xah, rg1_root, rg1_w, rg1_bias,
                                         sc1, sh1, 0, xbh, sums + 0);
    fin_kernel<<<1, 128>>>(sums + 0, ln1_g, ln1_b, sc1, sh1);

    pull_kernel<<<(NN + 7) / 8, 256>>>(xbh, sc1, sh1, 1);
    rgcn_kernel<<<PGRID, 256, SM_RGCN>>>(xbh, rg2_root, rg2_w, rg2_bias,
                                         sc1, sh1, 1, xah, sums + 2);
    fin_kernel<<<1, 128>>>(sums + 2, ln2_g, ln2_b, sc2, sh2);

    head_kernel<<<NTILES, 256, SM_HEAD>>>(xah, W2, b2, W3, b3, sc2, sh2, (float*)d_out);
}

// round 7
// speedup vs baseline: 2.5344x; 1.1505x over previous
#include <cuda_runtime.h>
#include <cuda_fp16.h>
#include <math.h>
#include <stdint.h>

#define NN 50000
#define EE 600000
#define DDIM 128
#define NTILES ((NN + 127) / 128)   // 391
#define PGRID 148
#define NSB ((NN + 255) / 256)      // 196

// ---------------- scratch ----------------
__device__ uint32_t g_xah[(size_t)NN * 64];    // fp16 x (encode out / rgcn2 out)
__device__ uint32_t g_xbh[(size_t)NN * 64];    // fp16 rgcn1 out
__device__ uint32_t g_aggh[(size_t)2 * NN * 64];
__device__ int    g_deg[NN];
__device__ int    g_tmp[NN];
__device__ int    g_bsum[NSB];
__device__ int    g_rowptr[NN + 1];
__device__ int    g_cur[NN];
__device__ int    g_ebuf[EE];
__device__ double g_sums[4];
__device__ float  g_sc1[DDIM], g_sh1[DDIM];
__device__ float  g_sc2[DDIM], g_sh2[DDIM];

__device__ __forceinline__ float lrelu(float x) { return x > 0.f ? x : 0.01f * x; }

__device__ __forceinline__ uint32_t pk(float a, float b) {
    __half2 h = __floats2half2_rn(a, b);
    return *reinterpret_cast<uint32_t*>(&h);
}
__device__ __forceinline__ float2 upk(uint32_t w) {
    __half2 h = *reinterpret_cast<__half2*>(&w);
    return __half22float2(h);
}
__device__ __forceinline__ uint32_t aff(uint32_t w, float2 s, float2 h) {
    float2 f = upk(w);
    return pk(fmaf(f.x, s.x, h.x), fmaf(f.y, s.y, h.y));
}

// fp16 mma m16n8k16, fp32 accum
__device__ __forceinline__ void mma_f16(float c[4], uint32_t a0, uint32_t a1,
                                        uint32_t a2, uint32_t a3,
                                        uint32_t b0, uint32_t b1) {
    asm volatile(
        "mma.sync.aligned.m16n8k16.row.col.f32.f16.f16.f32 "
        "{%0,%1,%2,%3},{%4,%5,%6,%7},{%8,%9},{%0,%1,%2,%3};"
        : "+f"(c[0]), "+f"(c[1]), "+f"(c[2]), "+f"(c[3])
        : "r"(a0), "r"(a1), "r"(a2), "r"(a3), "r"(b0), "r"(b1));
}

// A fragment from half2-word smem [row][kp], pitch P words. kp0 % 8 == 0.
__device__ __forceinline__ void lda16(const uint32_t* sA, int P, int row, int kp0, int v,
                                      uint32_t& a0, uint32_t& a1, uint32_t& a2, uint32_t& a3) {
    const uint32_t* p = sA + row * P + kp0 + v;
    a0 = p[0]; a1 = p[8 * P]; a2 = p[4]; a3 = p[8 * P + 4];
}

// B fragment from half2-word smem [kp][n ^ ((kp&3)<<3)], pitch P words. kp0 % 8 == 0.
__device__ __forceinline__ void ldb16(const uint32_t* sW, int P, int kp0, int n0, int u, int v,
                                      uint32_t& b0, uint32_t& b1) {
    int col = (n0 + u) ^ (v << 3);
    b0 = sW[(kp0 + v) * P + col];
    b1 = sW[(kp0 + v + 4) * P + col];
}

// convert weight rows 2kp,2kp+1 cols n4..n4+3 into 4 half2 words, swizzled store
__device__ __forceinline__ void cvtw(uint32_t* sW, int P, const float* W, int N, int kp, int n4) {
    float4 f0 = __ldg((const float4*)(W + (size_t)(2 * kp) * N + n4));
    float4 f1 = __ldg((const float4*)(W + (size_t)(2 * kp + 1) * N + n4));
    uint4 w;
    w.x = pk(f0.x, f1.x); w.y = pk(f0.y, f1.y);
    w.z = pk(f0.z, f1.z); w.w = pk(f0.w, f1.w);
    *(uint4*)(sW + kp * P + (n4 ^ ((kp & 3) << 3))) = w;
}

// ---------------- setup kernels ----------------
__global__ void init_kernel() {
    int i = blockIdx.x * blockDim.x + threadIdx.x;
    if (i < NN) g_deg[i] = 0;
    if (i < 4) g_sums[i] = 0.0;
}

__global__ void hist_kernel(const int* __restrict__ ei) {
    int e = blockIdx.x * blockDim.x + threadIdx.x;
    if (e < EE) atomicAdd(&g_deg[ei[EE + e]], 1);
}

__global__ void s1_kernel() {
    __shared__ int ws[8];
    const int tid = threadIdx.x, b = blockIdx.x;
    const int lane = tid & 31, wid = tid >> 5;
    int i = b * 256 + tid;
    int v = (i < NN) ? g_deg[i] : 0;
    int x = v;
    #pragma unroll
    for (int o = 1; o < 32; o <<= 1) {
        int y = __shfl_up_sync(0xFFFFFFFFu, x, o);
        if (lane >= o) x += y;
    }
    if (lane == 31) ws[wid] = x;
    __syncthreads();
    if (wid == 0) {
        int s = (lane < 8) ? ws[lane] : 0;
        #pragma unroll
        for (int o = 1; o < 8; o <<= 1) {
            int y = __shfl_up_sync(0xFFFFFFFFu, s, o);
            if (lane >= o) s += y;
        }
        if (lane < 8) ws[lane] = s;
    }
    __syncthreads();
    int incl = x + (wid > 0 ? ws[wid - 1] : 0);
    if (i < NN) g_tmp[i] = incl;
    if (tid == 255) g_bsum[b] = incl;
}

__global__ void s2_kernel() {
    __shared__ int ws[8];
    const int tid = threadIdx.x;
    const int lane = tid & 31, wid = tid >> 5;
    int v = (tid < NSB) ? g_bsum[tid] : 0;
    int x = v;
    #pragma unroll
    for (int o = 1; o < 32; o <<= 1) {
        int y = __shfl_up_sync(0xFFFFFFFFu, x, o);
        if (lane >= o) x += y;
    }
    if (lane == 31) ws[wid] = x;
    __syncthreads();
    if (wid == 0) {
        int s = (lane < 8) ? ws[lane] : 0;
        #pragma unroll
        for (int o = 1; o < 8; o <<= 1) {
            int y = __shfl_up_sync(0xFFFFFFFFu, s, o);
            if (lane >= o) s += y;
        }
        if (lane < 8) ws[lane] = s;
    }
    __syncthreads();
    int incl = x + (wid > 0 ? ws[wid - 1] : 0);
    if (tid < NSB) g_bsum[tid] = incl - v;
}

__global__ void s3_kernel() {
    const int b = blockIdx.x, tid = threadIdx.x;
    int i = b * 256 + tid;
    if (i < NN) {
        int r = g_tmp[i] + g_bsum[b];
        g_rowptr[i + 1] = r;
        g_cur[i] = r - g_deg[i];
    }
    if (i == 0) g_rowptr[0] = 0;
}

__global__ void fill_kernel(const int* __restrict__ ei, const int* __restrict__ et) {
    int e = blockIdx.x * blockDim.x + threadIdx.x;
    if (e >= EE) return;
    int src = ei[e];
    int dst = ei[EE + e];
    int pos = atomicAdd(&g_cur[dst], 1);
    g_ebuf[pos] = src | (et[e] << 30);
}

__global__ void fin_kernel(const double* __restrict__ s,
                           const float* __restrict__ g,
                           const float* __restrict__ b,
                           float* __restrict__ scale,
                           float* __restrict__ shift) {
    int c = threadIdx.x;
    const double cnt = (double)NN * DDIM;
    double mu = s[0] / cnt;
    double var = s[1] / cnt - mu * mu;
    float rstd = (float)(1.0 / sqrt(var + 1e-5));
    float sc = rstd * g[c];
    scale[c] = sc;
    shift[c] = b[c] - (float)mu * sc;
}

// ---------------- encode (2 CTAs/SM: single reloaded weight buffer) ----------------
// smem words: sW 12288 | sX0 8704 | sA0 2560 | sA1 2560 | sNC 320  = 26432 (105728 B)
__global__ void __launch_bounds__(256, 2) encode_kernel(
    const float* __restrict__ desc, const float* __restrict__ tweet,
    const float* __restrict__ numf, const float* __restrict__ catf,
    const float* __restrict__ Wd, const float* __restrict__ bd,
    const float* __restrict__ Wt, const float* __restrict__ bt,
    const float* __restrict__ Wn, const float* __restrict__ bn,
    const float* __restrict__ Wc, const float* __restrict__ bc,
    const float* __restrict__ W1, const float* __restrict__ b1,
    uint32_t* __restrict__ outh)
{
    extern __shared__ uint32_t S[];
    uint32_t* sW  = S;             // phase-reloaded: Wd / Wt (12288), then W1 (8192)
    uint32_t* sX0 = S + 12288;     // pitch 68 words, 128 rows
    uint32_t* sA0 = S + 20992;     // pitch 20 words, 128 rows
    uint32_t* sA1 = S + 23552;
    float*    sNC = (float*)(S + 26112);

    const int tid = threadIdx.x;
    const int node0 = blockIdx.x * 128;
    const int lane = tid & 31, warp = tid >> 5;
    const int u = lane >> 2, v = lane & 3;
    const int r0 = warp * 16;
    const int srow = tid >> 3, sc4 = (tid & 7) * 4;

    if (tid < 160) sNC[tid] = Wn[tid];
    if (tid < 96)  sNC[160 + tid] = Wc[tid];
    if (tid < 32)  { sNC[256 + tid] = bn[tid]; sNC[288 + tid] = bc[tid]; }

    for (int ph = 0; ph < 2; ph++) {
        const float* In = ph ? tweet : desc;
        const float* W  = ph ? Wt : Wd;
        const float* B  = ph ? bt : bd;

        // (prior phase's mma finished at its last ENC_ITER barrier)
        for (int i = tid; i < 3072; i += 256) cvtw(sW, 32, W, 32, i >> 3, (i & 7) * 4);

        float acc[4][4];
        #pragma unroll
        for (int nt = 0; nt < 4; nt++) {
            float2 bv = *(const float2*)(B + nt * 8 + 2 * v);
            acc[nt][0] = bv.x; acc[nt][1] = bv.y; acc[nt][2] = bv.x; acc[nt][3] = bv.y;
        }

        float4 pvA[4], pvB[4];
        #pragma unroll
        for (int j = 0; j < 4; j++) {
            int g = node0 + srow + j * 32;
            pvA[j] = make_float4(0.f, 0.f, 0.f, 0.f);
            pvB[j] = make_float4(0.f, 0.f, 0.f, 0.f);
            if (g < NN) {
                pvA[j] = __ldg((const float4*)(In + (size_t)g * 768 + sc4));
                pvB[j] = __ldg((const float4*)(In + (size_t)g * 768 + 32 + sc4));
            }
        }
        #pragma unroll
        for (int j = 0; j < 4; j++) {
            uint2 w; w.x = pk(pvA[j].x, pvA[j].y); w.y = pk(pvA[j].z, pvA[j].w);
            *(uint2*)(sA0 + (srow + j * 32) * 20 + (sc4 >> 1)) = w;
        }
        __syncthreads();   // weights + chunk0 visible

        #define ENC_ITER(CI, PVL, PVS, SRC, DST)                                        \
        {                                                                                \
            if ((CI) + 2 < 24) {                                                         \
                _Pragma("unroll")                                                        \
                for (int j = 0; j < 4; j++) {                                            \
                    int g = node0 + srow + j * 32;                                       \
                    PVL[j] = make_float4(0.f, 0.f, 0.f, 0.f);                            \
                    if (g < NN)                                                          \
                        PVL[j] = __ldg((const float4*)(In + (size_t)g * 768              \
                                                       + ((CI) + 2) * 32 + sc4));        \
                }                                                                        \
            }                                                                            \
            if ((CI) + 1 < 24) {                                                         \
                _Pragma("unroll")                                                        \
                for (int j = 0; j < 4; j++) {                                            \
                    uint2 w; w.x = pk(PVS[j].x, PVS[j].y); w.y = pk(PVS[j].z, PVS[j].w); \
                    *(uint2*)((DST) + (srow + j * 32) * 20 + (sc4 >> 1)) = w;            \
                }                                                                        \
            }                                                                            \
            _Pragma("unroll")                                                            \
            for (int ks = 0; ks < 2; ks++) {                                             \
                uint32_t a0, a1, a2, a3;                                                 \
                lda16((SRC), 20, r0 + u, ks * 8, v, a0, a1, a2, a3);                     \
                int kp0 = (CI) * 16 + ks * 8;                                            \
                _Pragma("unroll")                                                        \
                for (int nt = 0; nt < 4; nt++) {                                         \
                    uint32_t b0, b1;                                                     \
                    ldb16(sW, 32, kp0, nt * 8, u, v, b0, b1);                            \
                    mma_f16(acc[nt], a0, a1, a2, a3, b0, b1);                            \
                }                                                                        \
            }                                                                            \
            __syncthreads();                                                             \
        }

        for (int cc = 0; cc < 24; cc += 2) {
            ENC_ITER(cc,     pvA, pvB, sA0, sA1);
            ENC_ITER(cc + 1, pvB, pvA, sA1, sA0);
        }
        #undef ENC_ITER

        const int cb2 = ph * 16;
        #pragma unroll
        for (int nt = 0; nt < 4; nt++) {
            int kp = cb2 + nt * 4 + v;
            sX0[(r0 + u) * 68 + kp]     = pk(lrelu(acc[nt][0]), lrelu(acc[nt][1]));
            sX0[(r0 + u + 8) * 68 + kp] = pk(lrelu(acc[nt][2]), lrelu(acc[nt][3]));
        }
    }

    // num / cat projections (cols 64-127)
    __syncthreads();
    {
        __half* sX0h = (__half*)sX0;
        for (int o = tid; o < 8192; o += 256) {
            int row = o >> 6, c = o & 63;
            int g = node0 + row;
            float vv = 0.f;
            if (g < NN) {
                if (c < 32) {
                    float a = sNC[256 + c];
                    #pragma unroll
                    for (int k = 0; k < 5; k++)
                        a = fmaf(__ldg(numf + (size_t)g * 5 + k), sNC[k * 32 + c], a);
                    vv = lrelu(a);
                } else {
                    int cc = c - 32;
                    float a = sNC[288 + cc];
                    #pragma unroll
                    for (int k = 0; k < 3; k++)
                        a = fmaf(__ldg(catf + (size_t)g * 3 + k), sNC[160 + k * 32 + cc], a);
                    vv = lrelu(a);
                }
            }
            sX0h[row * 136 + 64 + c] = __float2half(vv);
        }
    }
    // load W1 into sW (prior consumers of sW done: mma finished before epilogue barriers)
    for (int i = tid; i < 2048; i += 256) cvtw(sW, 128, W1, 128, i >> 5, (i & 31) * 4);
    __syncthreads();

    // W1: out = leaky( x0 @ W1 + b1 ), write fp16 packed
    {
        float acc[16][4];
        #pragma unroll
        for (int nt = 0; nt < 16; nt++) {
            float2 bv = *(const float2*)(b1 + nt * 8 + 2 * v);
            acc[nt][0] = bv.x; acc[nt][1] = bv.y; acc[nt][2] = bv.x; acc[nt][3] = bv.y;
        }
        #pragma unroll
        for (int ks = 0; ks < 8; ks++) {
            uint32_t a0, a1, a2, a3;
            lda16(sX0, 68, r0 + u, ks * 8, v, a0, a1, a2, a3);
            #pragma unroll
            for (int nt = 0; nt < 16; nt++) {
                uint32_t b0, b1;
                ldb16(sW, 128, ks * 8, nt * 8, u, v, b0, b1);
                mma_f16(acc[nt], a0, a1, a2, a3, b0, b1);
            }
        }
        int gA = node0 + r0 + u, gB = gA + 8;
        #pragma unroll
        for (int nt = 0; nt < 16; nt++) {
            int wofs = nt * 4 + v;
            if (gA < NN)
                outh[(size_t)gA * 64 + wofs] = pk(lrelu(acc[nt][0]), lrelu(acc[nt][1]));
            if (gB < NN)
                outh[(size_t)gB * 64 + wofs] = pk(lrelu(acc[nt][2]), lrelu(acc[nt][3]));
        }
    }
}

// ---------------- pull (fp16 gather, warp/node, optional LN affine, unroll 4) ----------------
__global__ void pull_kernel(const uint32_t* __restrict__ xh,
                            const float* __restrict__ scale,
                            const float* __restrict__ shift,
                            int apply) {
    const int w = (blockIdx.x * blockDim.x + threadIdx.x) >> 5;
    const int lane = threadIdx.x & 31;
    if (w >= NN) return;
    float4 sc = make_float4(1.f, 1.f, 1.f, 1.f);
    float4 sh = make_float4(0.f, 0.f, 0.f, 0.f);
    if (apply) {
        sc = __ldg((const float4*)scale + lane);
        sh = __ldg((const float4*)shift + lane);
    }
    const int beg = g_rowptr[w], end = g_rowptr[w + 1];
    const float NEG = -3.0e38f;
    float4 a0 = make_float4(NEG, NEG, NEG, NEG);
    float4 a1 = a0;

    #define PULL_ONE(VE)                                                             \
    {                                                                                 \
        uint2 d = __ldg((const uint2*)(xh + (size_t)((VE) & 0x3FFFFFFF) * 64) + lane);\
        float2 fx = upk(d.x), fy = upk(d.y);                                          \
        float4 f;                                                                     \
        f.x = fmaf(fx.x, sc.x, sh.x); f.y = fmaf(fx.y, sc.y, sh.y);                   \
        f.z = fmaf(fy.x, sc.z, sh.z); f.w = fmaf(fy.y, sc.w, sh.w);                   \
        if ((VE) >> 30) {                                                             \
            a1.x = fmaxf(a1.x, f.x); a1.y = fmaxf(a1.y, f.y);                         \
            a1.z = fmaxf(a1.z, f.z); a1.w = fmaxf(a1.w, f.w);                         \
        } else {                                                                      \
            a0.x = fmaxf(a0.x, f.x); a0.y = fmaxf(a0.y, f.y);                         \
            a0.z = fmaxf(a0.z, f.z); a0.w = fmaxf(a0.w, f.w);                         \
        }                                                                             \
    }

    int e = beg;
    for (; e + 4 <= end; e += 4) {
        int v0 = g_ebuf[e], v1 = g_ebuf[e + 1], v2 = g_ebuf[e + 2], v3 = g_ebuf[e + 3];
        PULL_ONE(v0); PULL_ONE(v1); PULL_ONE(v2); PULL_ONE(v3);
    }
    for (; e < end; e++) { int v0 = g_ebuf[e]; PULL_ONE(v0); }
    #undef PULL_ONE

    uint2 o0, o1;
    o0.x = pk((a0.x == NEG) ? 0.f : a0.x, (a0.y == NEG) ? 0.f : a0.y);
    o0.y = pk((a0.z == NEG) ? 0.f : a0.z, (a0.w == NEG) ? 0.f : a0.w);
    o1.x = pk((a1.x == NEG) ? 0.f : a1.x, (a1.y == NEG) ? 0.f : a1.y);
    o1.y = pk((a1.z == NEG) ? 0.f : a1.z, (a1.w == NEG) ? 0.f : a1.w);
    ((uint2*)(g_aggh + (size_t)w * 64))[lane] = o0;
    ((uint2*)(g_aggh + (size_t)(NN + w) * 64))[lane] = o1;
}

// ---------------- RGCN GEMM (fp16 mma, persistent, direct-LDG A, 2-step prefetch) --------
// smem words: sW 192*128 = 24576
__global__ void __launch_bounds__(256, 1) rgcn_kernel(
    const uint32_t* __restrict__ xh,
    const float* __restrict__ root,
    const float* __restrict__ relw,
    const float* __restrict__ bias,
    const float* __restrict__ scale,
    const float* __restrict__ shift,
    int apply,
    uint32_t* __restrict__ outh,
    double* __restrict__ sums)
{
    extern __shared__ uint32_t S[];
    uint32_t* sW = S;
    __shared__ double sred[2];
    const int tid = threadIdx.x;
    const int lane = tid & 31, warp = tid >> 5;
    const int u = lane >> 2, v = lane & 3;
    const int r0 = warp * 16;
    if (tid < 2) sred[tid] = 0.0;

    for (int i = tid; i < 2048; i += 256) cvtw(sW, 128, root, 128, i >> 5, (i & 31) * 4);
    for (int i = tid; i < 4096; i += 256)
        cvtw(sW + 64 * 128, 128, relw, 128, i >> 5, (i & 31) * 4);
    __syncthreads();

    for (int tile = blockIdx.x; tile < NTILES; tile += PGRID) {
        const int node0 = tile * 128;
        const int gA = node0 + r0 + u, gB = gA + 8;
        const bool okA = gA < NN, okB = gB < NN;

        float acc[16][4];
        #pragma unroll
        for (int nt = 0; nt < 16; nt++) {
            float2 bv = *(const float2*)(bias + nt * 8 + 2 * v);
            acc[nt][0] = bv.x; acc[nt][1] = bv.y; acc[nt][2] = bv.x; acc[nt][3] = bv.y;
        }

        #define LOAD_FRAG(S_, F_)                                                      \
        {                                                                               \
            int part = (S_) >> 3;                                                       \
            const uint32_t* base = (part == 0) ? xh : g_aggh;                           \
            size_t ofs = (part == 2) ? (size_t)NN * 64 : 0;                             \
            int w0 = (((S_) & 7) << 3) + v;                                             \
            F_[0] = okA ? __ldg(base + ofs + (size_t)gA * 64 + w0)     : 0u;            \
            F_[2] = okA ? __ldg(base + ofs + (size_t)gA * 64 + w0 + 4) : 0u;            \
            F_[1] = okB ? __ldg(base + ofs + (size_t)gB * 64 + w0)     : 0u;            \
            F_[3] = okB ? __ldg(base + ofs + (size_t)gB * 64 + w0 + 4) : 0u;            \
            if (apply && part == 0) {                                                   \
                float2 s0 = __ldg((const float2*)scale + w0);                           \
                float2 h0 = __ldg((const float2*)shift + w0);                           \
                float2 s1 = __ldg((const float2*)scale + w0 + 4);                       \
                float2 h1 = __ldg((const float2*)shift + w0 + 4);                       \
                F_[0] = aff(F_[0], s0, h0); F_[1] = aff(F_[1], s0, h0);                 \
                F_[2] = aff(F_[2], s1, h1); F_[3] = aff(F_[3], s1, h1);                 \
            }                                                                           \
        }

        uint32_t f0[4], f1[4];
        LOAD_FRAG(0, f0);
        LOAD_FRAG(1, f1);
        #pragma unroll
        for (int s = 0; s < 24; s++) {
            uint32_t fn[4];
            if (s + 2 < 24) LOAD_FRAG(s + 2, fn);
            #pragma unroll
            for (int nt = 0; nt < 16; nt++) {
                uint32_t b0, b1;
                ldb16(sW, 128, s * 8, nt * 8, u, v, b0, b1);
                mma_f16(acc[nt], f0[0], f0[1], f0[2], f0[3], b0, b1);
            }
            #pragma unroll
            for (int q = 0; q < 4; q++) { f0[q] = f1[q]; f1[q] = fn[q]; }
        }
        #undef LOAD_FRAG

        float ls = 0.f, lq = 0.f;
        #pragma unroll
        for (int nt = 0; nt < 16; nt++) {
            int wofs = nt * 4 + v;
            if (okA) {
                float x0 = acc[nt][0], x1 = acc[nt][1];
                outh[(size_t)gA * 64 + wofs] = pk(x0, x1);
                ls += x0 + x1; lq += x0 * x0 + x1 * x1;
            }
            if (okB) {
                float x0 = acc[nt][2], x1 = acc[nt][3];
                outh[(size_t)gB * 64 + wofs] = pk(x0, x1);
                ls += x0 + x1; lq += x0 * x0 + x1 * x1;
            }
        }
        #pragma unroll
        for (int off = 16; off; off >>= 1) {
            ls += __shfl_down_sync(0xFFFFFFFFu, ls, off);
            lq += __shfl_down_sync(0xFFFFFFFFu, lq, off);
        }
        if (lane == 0) {
            atomicAdd(&sred[0], (double)ls);
            atomicAdd(&sred[1], (double)lq);
        }
    }

    __syncthreads();
    if (tid == 0) {
        atomicAdd(&sums[0], sred[0]);
        atomicAdd(&sums[1], sred[1]);
    }
}

// ---------------- head (direct-LDG A with LN affine) ----------------
__global__ void __launch_bounds__(256, 1) head_kernel(
    const uint32_t* __restrict__ xh,
    const float* __restrict__ W2,
    const float* __restrict__ b2,
    const float* __restrict__ W3,
    const float* __restrict__ b3,
    const float* __restrict__ scale,
    const float* __restrict__ shift,
    float* __restrict__ out)
{
    extern __shared__ uint32_t S[];
    uint32_t* sW2 = S;
    float*    sw3 = (float*)(S + 8192);
    const int tid = threadIdx.x;
    const int node0 = blockIdx.x * 128;
    const int lane = tid & 31, warp = tid >> 5;
    const int u = lane >> 2, v = lane & 3;
    const int r0 = warp * 16;

    for (int i = tid; i < 2048; i += 256) cvtw(sW2, 128, W2, 128, i >> 5, (i & 31) * 4);
    if (tid < 128) sw3[tid] = W3[tid];
    __syncthreads();

    const int gA = node0 + r0 + u, gB = gA + 8;
    const bool okA = gA < NN, okB = gB < NN;

    float acc[16][4];
    #pragma unroll
    for (int nt = 0; nt < 16; nt++) {
        float2 bv = *(const float2*)(b2 + nt * 8 + 2 * v);
        acc[nt][0] = bv.x; acc[nt][1] = bv.y; acc[nt][2] = bv.x; acc[nt][3] = bv.y;
    }
    #pragma unroll
    for (int s = 0; s < 8; s++) {
        int w0 = s * 8 + v;
        uint32_t f0 = okA ? __ldg(xh + (size_t)gA * 64 + w0)     : 0u;
        uint32_t f2 = okA ? __ldg(xh + (size_t)gA * 64 + w0 + 4) : 0u;
        uint32_t f1 = okB ? __ldg(xh + (size_t)gB * 64 + w0)     : 0u;
        uint32_t f3 = okB ? __ldg(xh + (size_t)gB * 64 + w0 + 4) : 0u;
        float2 s0 = __ldg((const float2*)scale + w0), h0 = __ldg((const float2*)shift + w0);
        float2 s1 = __ldg((const float2*)scale + w0 + 4), h1 = __ldg((const float2*)shift + w0 + 4);
        f0 = aff(f0, s0, h0); f1 = aff(f1, s0, h0);
        f2 = aff(f2, s1, h1); f3 = aff(f3, s1, h1);
        #pragma unroll
        for (int nt = 0; nt < 16; nt++) {
            uint32_t b0, b1;
            ldb16(sW2, 128, s * 8, nt * 8, u, v, b0, b1);
            mma_f16(acc[nt], f0, f1, f2, f3, b0, b1);
        }
    }

    float pA = 0.f, pB = 0.f;
    #pragma unroll
    for (int nt = 0; nt < 16; nt++) {
        int col = nt * 8 + 2 * v;
        float w0 = sw3[col], w1 = sw3[col + 1];
        pA += lrelu(acc[nt][0]) * w0 + lrelu(acc[nt][1]) * w1;
        pB += lrelu(acc[nt][2]) * w0 + lrelu(acc[nt][3]) * w1;
    }
    pA += __shfl_xor_sync(0xFFFFFFFFu, pA, 1);
    pA += __shfl_xor_sync(0xFFFFFFFFu, pA, 2);
    pB += __shfl_xor_sync(0xFFFFFFFFu, pB, 1);
    pB += __shfl_xor_sync(0xFFFFFFFFu, pB, 2);
    if (v == 0) {
        float b3v = __ldg(b3);
        if (okA) out[gA] = 1.f / (1.f + expf(-(pA + b3v)));
        if (okB) out[gB] = 1.f / (1.f + expf(-(pB + b3v)));
    }
}

// ---------------- launch ----------------
extern "C" void kernel_launch(void* const* d_in, const int* in_sizes, int n_in,
                              void* d_out, int out_size)
{
    const float* desc  = (const float*)d_in[0];
    const float* tweet = (const float*)d_in[1];
    const float* numf  = (const float*)d_in[2];
    const float* catf  = (const float*)d_in[3];
    const int*   ei    = (const int*)d_in[4];
    const int*   et    = (const int*)d_in[5];
    const float* Wd = (const float*)d_in[6];  const float* bd = (const float*)d_in[7];
    const float* Wt = (const float*)d_in[8];  const float* bt = (const float*)d_in[9];
    const float* Wn = (const float*)d_in[10]; const float* bn = (const float*)d_in[11];
    const float* Wc = (const float*)d_in[12]; const float* bc = (const float*)d_in[13];
    const float* W1 = (const float*)d_in[14]; const float* b1 = (const float*)d_in[15];
    const float* rg1_w    = (const float*)d_in[16];
    const float* rg1_root = (const float*)d_in[17];
    const float* rg1_bias = (const float*)d_in[18];
    const float* ln1_g = (const float*)d_in[19]; const float* ln1_b = (const float*)d_in[20];
    const float* rg2_w    = (const float*)d_in[21];
    const float* rg2_root = (const float*)d_in[22];
    const float* rg2_bias = (const float*)d_in[23];
    const float* ln2_g = (const float*)d_in[24]; const float* ln2_b = (const float*)d_in[25];
    const float* W2 = (const float*)d_in[26]; const float* b2 = (const float*)d_in[27];
    const float* W3 = (const float*)d_in[28]; const float* b3 = (const float*)d_in[29];

    uint32_t *xah, *xbh;
    float *sc1, *sh1, *sc2, *sh2;
    double* sums;
    cudaGetSymbolAddress((void**)&xah, g_xah);
    cudaGetSymbolAddress((void**)&xbh, g_xbh);
    cudaGetSymbolAddress((void**)&sums, g_sums);
    cudaGetSymbolAddress((void**)&sc1, g_sc1);
    cudaGetSymbolAddress((void**)&sh1, g_sh1);
    cudaGetSymbolAddress((void**)&sc2, g_sc2);
    cudaGetSymbolAddress((void**)&sh2, g_sh2);

    const int SM_ENC  = 26432 * 4;          // 105728
    const int SM_RGCN = 24576 * 4;          // 98304
    const int SM_HEAD = (8192 + 128) * 4;   // 33280
    cudaFuncSetAttribute(encode_kernel, cudaFuncAttributeMaxDynamicSharedMemorySize, SM_ENC);
    cudaFuncSetAttribute(rgcn_kernel,   cudaFuncAttributeMaxDynamicSharedMemorySize, SM_RGCN);
    cudaFuncSetAttribute(head_kernel,   cudaFuncAttributeMaxDynamicSharedMemorySize, SM_HEAD);

    init_kernel<<<(NN + 255) / 256, 256>>>();
    hist_kernel<<<(EE + 255) / 256, 256>>>(ei);
    s1_kernel<<<NSB, 256>>>();
    s2_kernel<<<1, 256>>>();
    s3_kernel<<<NSB, 256>>>();
    fill_kernel<<<(EE + 255) / 256, 256>>>(ei, et);

    encode_kernel<<<NTILES, 256, SM_ENC>>>(desc, tweet, numf, catf,
                                           Wd, bd, Wt, bt, Wn, bn, Wc, bc,
                                           W1, b1, xah);

    pull_kernel<<<(NN + 7) / 8, 256>>>(xah, sc1, sh1, 0);
    rgcn_kernel<<<PGRID, 256, SM_RGCN>>>(xah, rg1_root, rg1_w, rg1_bias,
                                         sc1, sh1, 0, xbh, sums + 0);
    fin_kernel<<<1, 128>>>(sums + 0, ln1_g, ln1_b, sc1, sh1);

    pull_kernel<<<(NN + 7) / 8, 256>>>(xbh, sc1, sh1, 1);
    rgcn_kernel<<<PGRID, 256, SM_RGCN>>>(xbh, rg2_root, rg2_w, rg2_bias,
                                         sc1, sh1, 1, xah, sums + 2);
    fin_kernel<<<1, 128>>>(sums + 2, ln2_g, ln2_b, sc2, sh2);

    head_kernel<<<NTILES, 256, SM_HEAD>>>(xah, W2, b2, W3, b3, sc2, sh2, (float*)d_out);
}

// round 9
// speedup vs baseline: 2.6259x; 1.0361x over previous
#include <cuda_runtime.h>
#include <cuda_fp16.h>
#include <math.h>
#include <stdint.h>

#define NN 50000
#define EE 600000
#define DDIM 128
#define NTILES ((NN + 127) / 128)   // 391
#define PGRID 148
#define NSB ((NN + 255) / 256)      // 196

// ---------------- scratch ----------------
__device__ uint32_t g_xah[(size_t)NN * 64];    // fp16 x (encode out / rgcn2 out)
__device__ uint32_t g_xbh[(size_t)NN * 64];    // fp16 rgcn1 out
__device__ uint32_t g_aggh[(size_t)2 * NN * 64];
__device__ int    g_deg[NN];
__device__ int    g_tmp[NN];
__device__ int    g_bsum[NSB];
__device__ int    g_rowptr[NN + 1];
__device__ int    g_cur[NN];
__device__ int    g_ebuf[EE];
__device__ double g_sums[4];

__device__ __forceinline__ float lrelu(float x) { return x > 0.f ? x : 0.01f * x; }

__device__ __forceinline__ uint32_t pk(float a, float b) {
    __half2 h = __floats2half2_rn(a, b);
    return *reinterpret_cast<uint32_t*>(&h);
}
__device__ __forceinline__ float2 upk(uint32_t w) {
    __half2 h = *reinterpret_cast<__half2*>(&w);
    return __half22float2(h);
}
__device__ __forceinline__ uint32_t aff(uint32_t w, float2 s, float2 h) {
    float2 f = upk(w);
    return pk(fmaf(f.x, s.x, h.x), fmaf(f.y, s.y, h.y));
}

// fp16 mma m16n8k16, fp32 accum
__device__ __forceinline__ void mma_f16(float c[4], uint32_t a0, uint32_t a1,
                                        uint32_t a2, uint32_t a3,
                                        uint32_t b0, uint32_t b1) {
    asm volatile(
        "mma.sync.aligned.m16n8k16.row.col.f32.f16.f16.f32 "
        "{%0,%1,%2,%3},{%4,%5,%6,%7},{%8,%9},{%0,%1,%2,%3};"
        : "+f"(c[0]), "+f"(c[1]), "+f"(c[2]), "+f"(c[3])
        : "r"(a0), "r"(a1), "r"(a2), "r"(a3), "r"(b0), "r"(b1));
}

// A fragment from half2-word smem [row][kp], pitch P words. kp0 % 8 == 0.
__device__ __forceinline__ void lda16(const uint32_t* sA, int P, int row, int kp0, int v,
                                      uint32_t& a0, uint32_t& a1, uint32_t& a2, uint32_t& a3) {
    const uint32_t* p = sA + row * P + kp0 + v;
    a0 = p[0]; a1 = p[8 * P]; a2 = p[4]; a3 = p[8 * P + 4];
}

// B fragment from half2-word smem [kp][n ^ ((kp&3)<<3)], pitch P words. kp0 % 8 == 0.
__device__ __forceinline__ void ldb16(const uint32_t* sW, int P, int kp0, int n0, int u, int v,
                                      uint32_t& b0, uint32_t& b1) {
    int col = (n0 + u) ^ (v << 3);
    b0 = sW[(kp0 + v) * P + col];
    b1 = sW[(kp0 + v + 4) * P + col];
}

// convert weight rows 2kp,2kp+1 cols n4..n4+3 into 4 half2 words, swizzled store
__device__ __forceinline__ void cvtw(uint32_t* sW, int P, const float* W, int N, int kp, int n4) {
    float4 f0 = __ldg((const float4*)(W + (size_t)(2 * kp) * N + n4));
    float4 f1 = __ldg((const float4*)(W + (size_t)(2 * kp + 1) * N + n4));
    uint4 w;
    w.x = pk(f0.x, f1.x); w.y = pk(f0.y, f1.y);
    w.z = pk(f0.z, f1.z); w.w = pk(f0.w, f1.w);
    *(uint4*)(sW + kp * P + (n4 ^ ((kp & 3) << 3))) = w;
}

// LN affine from fused stats (float recomputation; ~1e-7 vs double)
__device__ __forceinline__ void ln_affine(const double* s, float g, float b,
                                          float& sc, float& sh) {
    const float cnt = (float)NN * (float)DDIM;
    float mu = (float)s[0] / cnt;
    float var = (float)s[1] / cnt - mu * mu;
    float rstd = rsqrtf(var + 1e-5f);
    sc = rstd * g;
    sh = b - mu * sc;
}

// ---------------- setup kernels ----------------
__global__ void init_kernel() {
    int i = blockIdx.x * blockDim.x + threadIdx.x;
    if (i < NN) g_deg[i] = 0;
    if (i < 4) g_sums[i] = 0.0;
}

__global__ void hist_kernel(const int* __restrict__ ei) {
    int e = blockIdx.x * blockDim.x + threadIdx.x;
    if (e < EE) atomicAdd(&g_deg[ei[EE + e]], 1);
}

__global__ void s1_kernel() {
    __shared__ int ws[8];
    const int tid = threadIdx.x, b = blockIdx.x;
    const int lane = tid & 31, wid = tid >> 5;
    int i = b * 256 + tid;
    int v = (i < NN) ? g_deg[i] : 0;
    int x = v;
    #pragma unroll
    for (int o = 1; o < 32; o <<= 1) {
        int y = __shfl_up_sync(0xFFFFFFFFu, x, o);
        if (lane >= o) x += y;
    }
    if (lane == 31) ws[wid] = x;
    __syncthreads();
    if (wid == 0) {
        int s = (lane < 8) ? ws[lane] : 0;
        #pragma unroll
        for (int o = 1; o < 8; o <<= 1) {
            int y = __shfl_up_sync(0xFFFFFFFFu, s, o);
            if (lane >= o) s += y;
        }
        if (lane < 8) ws[lane] = s;
    }
    __syncthreads();
    int incl = x + (wid > 0 ? ws[wid - 1] : 0);
    if (i < NN) g_tmp[i] = incl;
    if (tid == 255) g_bsum[b] = incl;
}

// merged s2+s3: each block computes its own exclusive block offset, applies it
__global__ void s23_kernel() {
    __shared__ int s_off;
    const int b = blockIdx.x, tid = threadIdx.x;
    if (tid < 32) {
        int acc = 0;
        for (int j = tid; j < b; j += 32) acc += g_bsum[j];
        #pragma unroll
        for (int o = 16; o; o >>= 1) acc += __shfl_down_sync(0xFFFFFFFFu, acc, o);
        if (tid == 0) s_off = acc;
    }
    __syncthreads();
    int i = b * 256 + tid;
    if (i < NN) {
        int r = g_tmp[i] + s_off;
        g_rowptr[i + 1] = r;
        g_cur[i] = r - g_deg[i];
    }
    if (i == 0) g_rowptr[0] = 0;
}

__global__ void fill_kernel(const int* __restrict__ ei, const int* __restrict__ et) {
    int e = blockIdx.x * blockDim.x + threadIdx.x;
    if (e >= EE) return;
    int src = ei[e];
    int dst = ei[EE + e];
    int pos = atomicAdd(&g_cur[dst], 1);
    g_ebuf[pos] = src | (et[e] << 30);
}

// ---------------- encode (2 CTAs/SM: single reloaded weight buffer) ----------------
// smem words: sW 12288 | sX0 8704 | sA0 2560 | sA1 2560 | sNC 320  = 26432 (105728 B)
__global__ void __launch_bounds__(256, 2) encode_kernel(
    const float* __restrict__ desc, const float* __restrict__ tweet,
    const float* __restrict__ numf, const float* __restrict__ catf,
    const float* __restrict__ Wd, const float* __restrict__ bd,
    const float* __restrict__ Wt, const float* __restrict__ bt,
    const float* __restrict__ Wn, const float* __restrict__ bn,
    const float* __restrict__ Wc, const float* __restrict__ bc,
    const float* __restrict__ W1, const float* __restrict__ b1,
    uint32_t* __restrict__ outh)
{
    extern __shared__ uint32_t S[];
    uint32_t* sW  = S;             // phase-reloaded: Wd / Wt (12288), then W1 (8192)
    uint32_t* sX0 = S + 12288;     // pitch 68 words, 128 rows
    uint32_t* sA0 = S + 20992;     // pitch 20 words, 128 rows
    uint32_t* sA1 = S + 23552;
    float*    sNC = (float*)(S + 26112);

    const int tid = threadIdx.x;
    const int node0 = blockIdx.x * 128;
    const int lane = tid & 31, warp = tid >> 5;
    const int u = lane >> 2, v = lane & 3;
    const int r0 = warp * 16;
    const int srow = tid >> 3, sc4 = (tid & 7) * 4;

    if (tid < 160) sNC[tid] = Wn[tid];
    if (tid < 96)  sNC[160 + tid] = Wc[tid];
    if (tid < 32)  { sNC[256 + tid] = bn[tid]; sNC[288 + tid] = bc[tid]; }

    for (int ph = 0; ph < 2; ph++) {
        const float* In = ph ? tweet : desc;
        const float* W  = ph ? Wt : Wd;
        const float* B  = ph ? bt : bd;

        for (int i = tid; i < 3072; i += 256) cvtw(sW, 32, W, 32, i >> 3, (i & 7) * 4);

        float acc[4][4];
        #pragma unroll
        for (int nt = 0; nt < 4; nt++) {
            float2 bv = *(const float2*)(B + nt * 8 + 2 * v);
            acc[nt][0] = bv.x; acc[nt][1] = bv.y; acc[nt][2] = bv.x; acc[nt][3] = bv.y;
        }

        float4 pvA[4], pvB[4];
        #pragma unroll
        for (int j = 0; j < 4; j++) {
            int g = node0 + srow + j * 32;
            pvA[j] = make_float4(0.f, 0.f, 0.f, 0.f);
            pvB[j] = make_float4(0.f, 0.f, 0.f, 0.f);
            if (g < NN) {
                pvA[j] = __ldg((const float4*)(In + (size_t)g * 768 + sc4));
                pvB[j] = __ldg((const float4*)(In + (size_t)g * 768 + 32 + sc4));
            }
        }
        #pragma unroll
        for (int j = 0; j < 4; j++) {
            uint2 w; w.x = pk(pvA[j].x, pvA[j].y); w.y = pk(pvA[j].z, pvA[j].w);
            *(uint2*)(sA0 + (srow + j * 32) * 20 + (sc4 >> 1)) = w;
        }
        __syncthreads();   // weights + chunk0 visible

        #define ENC_ITER(CI, PVL, PVS, SRC, DST)                                        \
        {                                                                                \
            if ((CI) + 2 < 24) {                                                         \
                _Pragma("unroll")                                                        \
                for (int j = 0; j < 4; j++) {                                            \
                    int g = node0 + srow + j * 32;                                       \
                    PVL[j] = make_float4(0.f, 0.f, 0.f, 0.f);                            \
                    if (g < NN)                                                          \
                        PVL[j] = __ldg((const float4*)(In + (size_t)g * 768              \
                                                       + ((CI) + 2) * 32 + sc4));        \
                }                                                                        \
            }                                                                            \
            if ((CI) + 1 < 24) {                                                         \
                _Pragma("unroll")                                                        \
                for (int j = 0; j < 4; j++) {                                            \
                    uint2 w; w.x = pk(PVS[j].x, PVS[j].y); w.y = pk(PVS[j].z, PVS[j].w); \
                    *(uint2*)((DST) + (srow + j * 32) * 20 + (sc4 >> 1)) = w;            \
                }                                                                        \
            }                                                                            \
            _Pragma("unroll")                                                            \
            for (int ks = 0; ks < 2; ks++) {                                             \
                uint32_t a0, a1, a2, a3;                                                 \
                lda16((SRC), 20, r0 + u, ks * 8, v, a0, a1, a2, a3);                     \
                int kp0 = (CI) * 16 + ks * 8;                                            \
                _Pragma("unroll")                                                        \
                for (int nt = 0; nt < 4; nt++) {                                         \
                    uint32_t b0, b1;                                                     \
                    ldb16(sW, 32, kp0, nt * 8, u, v, b0, b1);                            \
                    mma_f16(acc[nt], a0, a1, a2, a3, b0, b1);                            \
                }                                                                        \
            }                                                                            \
            __syncthreads();                                                             \
        }

        for (int cc = 0; cc < 24; cc += 2) {
            ENC_ITER(cc,     pvA, pvB, sA0, sA1);
            ENC_ITER(cc + 1, pvB, pvA, sA1, sA0);
        }
        #undef ENC_ITER

        const int cb2 = ph * 16;
        #pragma unroll
        for (int nt = 0; nt < 4; nt++) {
            int kp = cb2 + nt * 4 + v;
            sX0[(r0 + u) * 68 + kp]     = pk(lrelu(acc[nt][0]), lrelu(acc[nt][1]));
            sX0[(r0 + u + 8) * 68 + kp] = pk(lrelu(acc[nt][2]), lrelu(acc[nt][3]));
        }
    }

    // num / cat projections (cols 64-127)
    __syncthreads();
    {
        __half* sX0h = (__half*)sX0;
        for (int o = tid; o < 8192; o += 256) {
            int row = o >> 6, c = o & 63;
            int g = node0 + row;
            float vv = 0.f;
            if (g < NN) {
                if (c < 32) {
                    float a = sNC[256 + c];
                    #pragma unroll
                    for (int k = 0; k < 5; k++)
                        a = fmaf(__ldg(numf + (size_t)g * 5 + k), sNC[k * 32 + c], a);
                    vv = lrelu(a);
                } else {
                    int cc = c - 32;
                    float a = sNC[288 + cc];
                    #pragma unroll
                    for (int k = 0; k < 3; k++)
                        a = fmaf(__ldg(catf + (size_t)g * 3 + k), sNC[160 + k * 32 + cc], a);
                    vv = lrelu(a);
                }
            }
            sX0h[row * 136 + 64 + c] = __float2half(vv);
        }
    }
    for (int i = tid; i < 2048; i += 256) cvtw(sW, 128, W1, 128, i >> 5, (i & 31) * 4);
    __syncthreads();

    // W1: out = leaky( x0 @ W1 + b1 ), write fp16 packed
    {
        float acc[16][4];
        #pragma unroll
        for (int nt = 0; nt < 16; nt++) {
            float2 bv = *(const float2*)(b1 + nt * 8 + 2 * v);
            acc[nt][0] = bv.x; acc[nt][1] = bv.y; acc[nt][2] = bv.x; acc[nt][3] = bv.y;
        }
        #pragma unroll
        for (int ks = 0; ks < 8; ks++) {
            uint32_t a0, a1, a2, a3;
            lda16(sX0, 68, r0 + u, ks * 8, v, a0, a1, a2, a3);
            #pragma unroll
            for (int nt = 0; nt < 16; nt++) {
                uint32_t b0, b1;
                ldb16(sW, 128, ks * 8, nt * 8, u, v, b0, b1);
                mma_f16(acc[nt], a0, a1, a2, a3, b0, b1);
            }
        }
        int gA = node0 + r0 + u, gB = gA + 8;
        #pragma unroll
        for (int nt = 0; nt < 16; nt++) {
            int wofs = nt * 4 + v;
            if (gA < NN)
                outh[(size_t)gA * 64 + wofs] = pk(lrelu(acc[nt][0]), lrelu(acc[nt][1]));
            if (gB < NN)
                outh[(size_t)gB * 64 + wofs] = pk(lrelu(acc[nt][2]), lrelu(acc[nt][3]));
        }
    }
}

// ---------------- pull (fp16 gather, warp/node, inline LN affine, unroll 4) -------------
__global__ void pull_kernel(const uint32_t* __restrict__ xh,
                            const double* __restrict__ sums_in,
                            const float* __restrict__ lng,
                            const float* __restrict__ lnb,
                            int apply) {
    const int w = (blockIdx.x * blockDim.x + threadIdx.x) >> 5;
    const int lane = threadIdx.x & 31;
    if (w >= NN) return;
    float4 sc = make_float4(1.f, 1.f, 1.f, 1.f);
    float4 sh = make_float4(0.f, 0.f, 0.f, 0.f);
    if (apply) {
        float4 g4 = __ldg((const float4*)lng + lane);
        float4 b4 = __ldg((const float4*)lnb + lane);
        ln_affine(sums_in, g4.x, b4.x, sc.x, sh.x);
        ln_affine(sums_in, g4.y, b4.y, sc.y, sh.y);
        ln_affine(sums_in, g4.z, b4.z, sc.z, sh.z);
        ln_affine(sums_in, g4.w, b4.w, sc.w, sh.w);
    }
    const int beg = g_rowptr[w], end = g_rowptr[w + 1];
    const float NEG = -3.0e38f;
    float4 a0 = make_float4(NEG, NEG, NEG, NEG);
    float4 a1 = a0;

    #define PULL_ONE(VE)                                                             \
    {                                                                                 \
        uint2 d = __ldg((const uint2*)(xh + (size_t)((VE) & 0x3FFFFFFF) * 64) + lane);\
        float2 fx = upk(d.x), fy = upk(d.y);                                          \
        float4 f;                                                                     \
        f.x = fmaf(fx.x, sc.x, sh.x); f.y = fmaf(fx.y, sc.y, sh.y);                   \
        f.z = fmaf(fy.x, sc.z, sh.z); f.w = fmaf(fy.y, sc.w, sh.w);                   \
        if ((VE) >> 30) {                                                             \
            a1.x = fmaxf(a1.x, f.x); a1.y = fmaxf(a1.y, f.y);                         \
            a1.z = fmaxf(a1.z, f.z); a1.w = fmaxf(a1.w, f.w);                         \
        } else {                                                                      \
            a0.x = fmaxf(a0.x, f.x); a0.y = fmaxf(a0.y, f.y);                         \
            a0.z = fmaxf(a0.z, f.z); a0.w = fmaxf(a0.w, f.w);                         \
        }                                                                             \
    }

    int e = beg;
    for (; e + 4 <= end; e += 4) {
        int v0 = g_ebuf[e], v1 = g_ebuf[e + 1], v2 = g_ebuf[e + 2], v3 = g_ebuf[e + 3];
        PULL_ONE(v0); PULL_ONE(v1); PULL_ONE(v2); PULL_ONE(v3);
    }
    for (; e < end; e++) { int v0 = g_ebuf[e]; PULL_ONE(v0); }
    #undef PULL_ONE

    uint2 o0, o1;
    o0.x = pk((a0.x == NEG) ? 0.f : a0.x, (a0.y == NEG) ? 0.f : a0.y);
    o0.y = pk((a0.z == NEG) ? 0.f : a0.z, (a0.w == NEG) ? 0.f : a0.w);
    o1.x = pk((a1.x == NEG) ? 0.f : a1.x, (a1.y == NEG) ? 0.f : a1.y);
    o1.y = pk((a1.z == NEG) ? 0.f : a1.z, (a1.w == NEG) ? 0.f : a1.w);
    ((uint2*)(g_aggh + (size_t)w * 64))[lane] = o0;
    ((uint2*)(g_aggh + (size_t)(NN + w) * 64))[lane] = o1;
}

// ---------------- RGCN GEMM (fp16 mma, persistent, direct-LDG A, 2-step prefetch) --------
// smem words: sW 24576 | sSc 128 | sSh 128  = 24832 (99328 B)
__global__ void __launch_bounds__(256, 1) rgcn_kernel(
    const uint32_t* __restrict__ xh,
    const float* __restrict__ root,
    const float* __restrict__ relw,
    const float* __restrict__ bias,
    const double* __restrict__ sums_in,
    const float* __restrict__ lng,
    const float* __restrict__ lnb,
    int apply,
    uint32_t* __restrict__ outh,
    double* __restrict__ sums_out)
{
    extern __shared__ uint32_t S[];
    uint32_t* sW = S;
    float2* sSc = (float2*)(S + 24576);   // 64 float2 = 128 words
    float2* sSh = sSc + 64;               // 64 float2 = 128 words
    __shared__ double sred[2];
    const int tid = threadIdx.x;
    const int lane = tid & 31, warp = tid >> 5;
    const int u = lane >> 2, v = lane & 3;
    const int r0 = warp * 16;
    if (tid < 2) sred[tid] = 0.0;

    for (int i = tid; i < 2048; i += 256) cvtw(sW, 128, root, 128, i >> 5, (i & 31) * 4);
    for (int i = tid; i < 4096; i += 256)
        cvtw(sW + 64 * 128, 128, relw, 128, i >> 5, (i & 31) * 4);
    if (apply && tid < 64) {
        float2 g2 = __ldg((const float2*)lng + tid);
        float2 b2 = __ldg((const float2*)lnb + tid);
        float2 sc, sh;
        ln_affine(sums_in, g2.x, b2.x, sc.x, sh.x);
        ln_affine(sums_in, g2.y, b2.y, sc.y, sh.y);
        sSc[tid] = sc; sSh[tid] = sh;
    }
    __syncthreads();

    for (int tile = blockIdx.x; tile < NTILES; tile += PGRID) {
        const int node0 = tile * 128;
        const int gA = node0 + r0 + u, gB = gA + 8;
        const bool okA = gA < NN, okB = gB < NN;

        float acc[16][4];
        #pragma unroll
        for (int nt = 0; nt < 16; nt++) {
            float2 bv = *(const float2*)(bias + nt * 8 + 2 * v);
            acc[nt][0] = bv.x; acc[nt][1] = bv.y; acc[nt][2] = bv.x; acc[nt][3] = bv.y;
        }

        #define LOAD_FRAG(S_, F_)                                                      \
        {                                                                               \
            int part = (S_) >> 3;                                                       \
            const uint32_t* base = (part == 0) ? xh : g_aggh;                           \
            size_t ofs = (part == 2) ? (size_t)NN * 64 : 0;                             \
            int w0 = (((S_) & 7) << 3) + v;                                             \
            F_[0] = okA ? __ldg(base + ofs + (size_t)gA * 64 + w0)     : 0u;            \
            F_[2] = okA ? __ldg(base + ofs + (size_t)gA * 64 + w0 + 4) : 0u;            \
            F_[1] = okB ? __ldg(base + ofs + (size_t)gB * 64 + w0)     : 0u;            \
            F_[3] = okB ? __ldg(base + ofs + (size_t)gB * 64 + w0 + 4) : 0u;            \
            if (apply && part == 0) {                                                   \
                float2 s0 = sSc[w0],     h0 = sSh[w0];                                  \
                float2 s1 = sSc[w0 + 4], h1 = sSh[w0 + 4];                              \
                F_[0] = aff(F_[0], s0, h0); F_[1] = aff(F_[1], s0, h0);                 \
                F_[2] = aff(F_[2], s1, h1); F_[3] = aff(F_[3], s1, h1);                 \
            }                                                                           \
        }

        uint32_t f0[4], f1[4];
        LOAD_FRAG(0, f0);
        LOAD_FRAG(1, f1);
        #pragma unroll
        for (int s = 0; s < 24; s++) {
            uint32_t fn[4];
            if (s + 2 < 24) LOAD_FRAG(s + 2, fn);
            #pragma unroll
            for (int nt = 0; nt < 16; nt++) {
                uint32_t b0, b1;
                ldb16(sW, 128, s * 8, nt * 8, u, v, b0, b1);
                mma_f16(acc[nt], f0[0], f0[1], f0[2], f0[3], b0, b1);
            }
            #pragma unroll
            for (int q = 0; q < 4; q++) { f0[q] = f1[q]; f1[q] = fn[q]; }
        }
        #undef LOAD_FRAG

        float ls = 0.f, lq = 0.f;
        #pragma unroll
        for (int nt = 0; nt < 16; nt++) {
            int wofs = nt * 4 + v;
            if (okA) {
                float x0 = acc[nt][0], x1 = acc[nt][1];
                outh[(size_t)gA * 64 + wofs] = pk(x0, x1);
                ls += x0 + x1; lq += x0 * x0 + x1 * x1;
            }
            if (okB) {
                float x0 = acc[nt][2], x1 = acc[nt][3];
                outh[(size_t)gB * 64 + wofs] = pk(x0, x1);
                ls += x0 + x1; lq += x0 * x0 + x1 * x1;
            }
        }
        #pragma unroll
        for (int off = 16; off; off >>= 1) {
            ls += __shfl_down_sync(0xFFFFFFFFu, ls, off);
            lq += __shfl_down_sync(0xFFFFFFFFu, lq, off);
        }
        if (lane == 0) {
            atomicAdd(&sred[0], (double)ls);
            atomicAdd(&sred[1], (double)lq);
        }
    }

    __syncthreads();
    if (tid == 0) {
        atomicAdd(&sums_out[0], sred[0]);
        atomicAdd(&sums_out[1], sred[1]);
    }
}

// ---------------- head (direct-LDG A, inline LN affine) ----------------
// smem words: sW2 8192 | sw3 128 | sSc 128 | sSh 128  = 8576 (34304 B)
__global__ void __launch_bounds__(256, 1) head_kernel(
    const uint32_t* __restrict__ xh,
    const float* __restrict__ W2,
    const float* __restrict__ b2,
    const float* __restrict__ W3,
    const float* __restrict__ b3,
    const double* __restrict__ sums_in,
    const float* __restrict__ lng,
    const float* __restrict__ lnb,
    float* __restrict__ out)
{
    extern __shared__ uint32_t S[];
    uint32_t* sW2 = S;
    float*    sw3 = (float*)(S + 8192);
    float2*   sSc = (float2*)(S + 8320);
    float2*   sSh = sSc + 64;
    const int tid = threadIdx.x;
    const int node0 = blockIdx.x * 128;
    const int lane = tid & 31, warp = tid >> 5;
    const int u = lane >> 2, v = lane & 3;
    const int r0 = warp * 16;

    for (int i = tid; i < 2048; i += 256) cvtw(sW2, 128, W2, 128, i >> 5, (i & 31) * 4);
    if (tid < 128) sw3[tid] = W3[tid];
    if (tid < 64) {
        float2 g2 = __ldg((const float2*)lng + tid);
        float2 b2v = __ldg((const float2*)lnb + tid);
        float2 sc, sh;
        ln_affine(sums_in, g2.x, b2v.x, sc.x, sh.x);
        ln_affine(sums_in, g2.y, b2v.y, sc.y, sh.y);
        sSc[tid] = sc; sSh[tid] = sh;
    }
    __syncthreads();

    const int gA = node0 + r0 + u, gB = gA + 8;
    const bool okA = gA < NN, okB = gB < NN;

    float acc[16][4];
    #pragma unroll
    for (int nt = 0; nt < 16; nt++) {
        float2 bv = *(const float2*)(b2 + nt * 8 + 2 * v);
        acc[nt][0] = bv.x; acc[nt][1] = bv.y; acc[nt][2] = bv.x; acc[nt][3] = bv.y;
    }
    #pragma unroll
    for (int s = 0; s < 8; s++) {
        int w0 = s * 8 + v;
        uint32_t f0 = okA ? __ldg(xh + (size_t)gA * 64 + w0)     : 0u;
        uint32_t f2 = okA ? __ldg(xh + (size_t)gA * 64 + w0 + 4) : 0u;
        uint32_t f1 = okB ? __ldg(xh + (size_t)gB * 64 + w0)     : 0u;
        uint32_t f3 = okB ? __ldg(xh + (size_t)gB * 64 + w0 + 4) : 0u;
        float2 s0 = sSc[w0], h0 = sSh[w0];
        float2 s1 = sSc[w0 + 4], h1 = sSh[w0 + 4];
        f0 = aff(f0, s0, h0); f1 = aff(f1, s0, h0);
        f2 = aff(f2, s1, h1); f3 = aff(f3, s1, h1);
        #pragma unroll
        for (int nt = 0; nt < 16; nt++) {
            uint32_t b0, b1;
            ldb16(sW2, 128, s * 8, nt * 8, u, v, b0, b1);
            mma_f16(acc[nt], f0, f1, f2, f3, b0, b1);
        }
    }

    float pA = 0.f, pB = 0.f;
    #pragma unroll
    for (int nt = 0; nt < 16; nt++) {
        int col = nt * 8 + 2 * v;
        float w0 = sw3[col], w1 = sw3[col + 1];
        pA += lrelu(acc[nt][0]) * w0 + lrelu(acc[nt][1]) * w1;
        pB += lrelu(acc[nt][2]) * w0 + lrelu(acc[nt][3]) * w1;
    }
    pA += __shfl_xor_sync(0xFFFFFFFFu, pA, 1);
    pA += __shfl_xor_sync(0xFFFFFFFFu, pA, 2);
    pB += __shfl_xor_sync(0xFFFFFFFFu, pB, 1);
    pB += __shfl_xor_sync(0xFFFFFFFFu, pB, 2);
    if (v == 0) {
        float b3v = __ldg(b3);
        if (okA) out[gA] = 1.f / (1.f + expf(-(pA + b3v)));
        if (okB) out[gB] = 1.f / (1.f + expf(-(pB + b3v)));
    }
}

// ---------------- launch ----------------
extern "C" void kernel_launch(void* const* d_in, const int* in_sizes, int n_in,
                              void* d_out, int out_size)
{
    const float* desc  = (const float*)d_in[0];
    const float* tweet = (const float*)d_in[1];
    const float* numf  = (const float*)d_in[2];
    const float* catf  = (const float*)d_in[3];
    const int*   ei    = (const int*)d_in[4];
    const int*   et    = (const int*)d_in[5];
    const float* Wd = (const float*)d_in[6];  const float* bd = (const float*)d_in[7];
    const float* Wt = (const float*)d_in[8];  const float* bt = (const float*)d_in[9];
    const float* Wn = (const float*)d_in[10]; const float* bn = (const float*)d_in[11];
    const float* Wc = (const float*)d_in[12]; const float* bc = (const float*)d_in[13];
    const float* W1 = (const float*)d_in[14]; const float* b1 = (const float*)d_in[15];
    const float* rg1_w    = (const float*)d_in[16];
    const float* rg1_root = (const float*)d_in[17];
    const float* rg1_bias = (const float*)d_in[18];
    const float* ln1_g = (const float*)d_in[19]; const float* ln1_b = (const float*)d_in[20];
    const float* rg2_w    = (const float*)d_in[21];
    const float* rg2_root = (const float*)d_in[22];
    const float* rg2_bias = (const float*)d_in[23];
    const float* ln2_g = (const float*)d_in[24]; const float* ln2_b = (const float*)d_in[25];
    const float* W2 = (const float*)d_in[26]; const float* b2 = (const float*)d_in[27];
    const float* W3 = (const float*)d_in[28]; const float* b3 = (const float*)d_in[29];

    uint32_t *xah, *xbh;
    double* sums;
    cudaGetSymbolAddress((void**)&xah, g_xah);
    cudaGetSymbolAddress((void**)&xbh, g_xbh);
    cudaGetSymbolAddress((void**)&sums, g_sums);

    const int SM_ENC  = 26432 * 4;                 // 105728
    const int SM_RGCN = (24576 + 256) * 4;         // 99328  (FIX: was +64)
    const int SM_HEAD = (8192 + 128 + 256) * 4;    // 34304
    cudaFuncSetAttribute(encode_kernel, cudaFuncAttributeMaxDynamicSharedMemorySize, SM_ENC);
    cudaFuncSetAttribute(rgcn_kernel,   cudaFuncAttributeMaxDynamicSharedMemorySize, SM_RGCN);
    cudaFuncSetAttribute(head_kernel,   cudaFuncAttributeMaxDynamicSharedMemorySize, SM_HEAD);

    // side stream for the CSR build, overlapped with encode (capture fork/join)
    static cudaStream_t side = nullptr;
    static cudaEvent_t evFork = nullptr, evJoin = nullptr;
    if (side == nullptr) {
        cudaStreamCreateWithFlags(&side, cudaStreamNonBlocking);
        cudaEventCreateWithFlags(&evFork, cudaEventDisableTiming);
        cudaEventCreateWithFlags(&evJoin, cudaEventDisableTiming);
    }

    cudaEventRecord(evFork, 0);
    cudaStreamWaitEvent(side, evFork, 0);
    init_kernel<<<(NN + 255) / 256, 256, 0, side>>>();
    hist_kernel<<<(EE + 255) / 256, 256, 0, side>>>(ei);
    s1_kernel<<<NSB, 256, 0, side>>>();
    s23_kernel<<<NSB, 256, 0, side>>>();
    fill_kernel<<<(EE + 255) / 256, 256, 0, side>>>(ei, et);
    cudaEventRecord(evJoin, side);

    encode_kernel<<<NTILES, 256, SM_ENC>>>(desc, tweet, numf, catf,
                                           Wd, bd, Wt, bt, Wn, bn, Wc, bc,
                                           W1, b1, xah);
    cudaStreamWaitEvent(0, evJoin, 0);

    pull_kernel<<<(NN + 7) / 8, 256>>>(xah, sums, ln1_g, ln1_b, 0);
    rgcn_kernel<<<PGRID, 256, SM_RGCN>>>(xah, rg1_root, rg1_w, rg1_bias,
                                         sums, ln1_g, ln1_b, 0, xbh, sums + 0);
    pull_kernel<<<(NN + 7) / 8, 256>>>(xbh, sums + 0, ln1_g, ln1_b, 1);
    rgcn_kernel<<<PGRID, 256, SM_RGCN>>>(xbh, rg2_root, rg2_w, rg2_bias,
                                         sums + 0, ln1_g, ln1_b, 1, xah, sums + 2);
    head_kernel<<<NTILES, 256, SM_HEAD>>>(xah, W2, b2, W3, b3,
                                          sums + 2, ln2_g, ln2_b, (float*)d_out);
}